// round 1
// baseline (speedup 1.0000x reference)
#include <cuda_runtime.h>
#include <math.h>

// Problem shape (fixed by the dataset)
#define BB 4
#define NN 4096
#define EE 1024
#define DD 256

#define NEG_FILL (-3.402823466385288598e+38f)   // float32 min, matches jnp.finfo(f32).min

// -------- scratch (static device globals; no allocations allowed) --------
__device__ float g_Q[(size_t)BB * NN * DD];          // 16.8 MB
__device__ float g_K[(size_t)BB * NN * DD];          // 16.8 MB
__device__ float g_V[(size_t)BB * NN * EE];          // 67 MB
__device__ float g_Wv[(size_t)EE * EE];              // 4 MB
__device__ float g_P[(size_t)BB * NN * NN];          // 268 MB (scores -> probs, in place)

// ---------------------------------------------------------------------------
// Generic row-major SGEMM: C[M,N] = alpha * A[M,K] @ B[K,N]
// 64x64 tile, BK=16, 256 threads, 4x4 per-thread microtile.
// All of M,N divisible by 64 and K by 16 (guaranteed by the shapes here).
// CAUSAL_K: limit the k-loop to the row tile's end (valid because softmax'd
// P has exact zeros beyond the diagonal).
// ---------------------------------------------------------------------------
template <bool CAUSAL_K>
__global__ void __launch_bounds__(256)
gemm_nn_64(const float* __restrict__ A, const float* __restrict__ B,
           float* __restrict__ C, int M, int N, int K, float alpha,
           long long strideA, long long strideB, long long strideC)
{
    A += (size_t)blockIdx.z * strideA;
    B += (size_t)blockIdx.z * strideB;
    C += (size_t)blockIdx.z * strideC;

    const int m0 = blockIdx.y * 64;
    const int n0 = blockIdx.x * 64;

    int kEnd = K;
    if (CAUSAL_K) {
        int lim = m0 + 64;
        kEnd = lim < K ? lim : K;
    }

    __shared__ float As[16][64];
    __shared__ float Bs[16][64];

    const int tid = threadIdx.x;
    const int tx = tid & 15;        // n micro index
    const int ty = tid >> 4;        // m micro index

    const int am = tid >> 2;            // 0..63
    const int ak = (tid & 3) * 4;       // 0,4,8,12
    const int bk = tid >> 4;            // 0..15
    const int bn = (tid & 15) * 4;      // 0..60

    float acc[4][4] = {};

    for (int k0 = 0; k0 < kEnd; k0 += 16) {
        float4 av = *(const float4*)(A + (size_t)(m0 + am) * K + k0 + ak);
        float4 bv = *(const float4*)(B + (size_t)(k0 + bk) * N + n0 + bn);
        As[ak + 0][am] = av.x;
        As[ak + 1][am] = av.y;
        As[ak + 2][am] = av.z;
        As[ak + 3][am] = av.w;
        *(float4*)&Bs[bk][bn] = bv;
        __syncthreads();

#pragma unroll
        for (int kk = 0; kk < 16; kk++) {
            const float4 a = *(const float4*)&As[kk][ty * 4];
            const float4 b = *(const float4*)&Bs[kk][tx * 4];
            float ar[4] = {a.x, a.y, a.z, a.w};
            float br[4] = {b.x, b.y, b.z, b.w};
#pragma unroll
            for (int i = 0; i < 4; i++)
#pragma unroll
                for (int j = 0; j < 4; j++)
                    acc[i][j] += ar[i] * br[j];
        }
        __syncthreads();
    }

#pragma unroll
    for (int i = 0; i < 4; i++) {
        float4 v = make_float4(acc[i][0] * alpha, acc[i][1] * alpha,
                               acc[i][2] * alpha, acc[i][3] * alpha);
        *(float4*)(C + (size_t)(m0 + ty * 4 + i) * N + n0 + tx * 4) = v;
    }
}

// ---------------------------------------------------------------------------
// Scores: S[b,q,k] = (Q[b,q,:] . K[b,k,:]) / sqrt(D), GEMM-NT per batch.
// Skips tiles strictly above the diagonal (softmax masks by index, so the
// skipped region may hold garbage).
// ---------------------------------------------------------------------------
__global__ void __launch_bounds__(256)
gemm_nt_scores(const float* __restrict__ Qm, const float* __restrict__ Km,
               float* __restrict__ Pm)
{
    const int m0 = blockIdx.y * 64;   // query tile
    const int n0 = blockIdx.x * 64;   // key tile
    if (n0 > m0 + 63) return;         // fully masked tile

    const float* A = Qm + (size_t)blockIdx.z * NN * DD;
    const float* B = Km + (size_t)blockIdx.z * NN * DD;
    float*       C = Pm + (size_t)blockIdx.z * NN * NN;

    __shared__ float As[16][64];
    __shared__ float Bs[16][64];

    const int tid = threadIdx.x;
    const int tx = tid & 15;
    const int ty = tid >> 4;

    const int am = tid >> 2;
    const int ak = (tid & 3) * 4;

    float acc[4][4] = {};

    for (int k0 = 0; k0 < DD; k0 += 16) {
        float4 av = *(const float4*)(A + (size_t)(m0 + am) * DD + k0 + ak);
        float4 bv = *(const float4*)(B + (size_t)(n0 + am) * DD + k0 + ak);
        As[ak + 0][am] = av.x;
        As[ak + 1][am] = av.y;
        As[ak + 2][am] = av.z;
        As[ak + 3][am] = av.w;
        Bs[ak + 0][am] = bv.x;
        Bs[ak + 1][am] = bv.y;
        Bs[ak + 2][am] = bv.z;
        Bs[ak + 3][am] = bv.w;
        __syncthreads();

#pragma unroll
        for (int kk = 0; kk < 16; kk++) {
            const float4 a = *(const float4*)&As[kk][ty * 4];
            const float4 b = *(const float4*)&Bs[kk][tx * 4];
            float ar[4] = {a.x, a.y, a.z, a.w};
            float br[4] = {b.x, b.y, b.z, b.w};
#pragma unroll
            for (int i = 0; i < 4; i++)
#pragma unroll
                for (int j = 0; j < 4; j++)
                    acc[i][j] += ar[i] * br[j];
        }
        __syncthreads();
    }

    const float scale = 1.0f / 16.0f;   // 1/sqrt(256)
#pragma unroll
    for (int i = 0; i < 4; i++) {
        float4 v = make_float4(acc[i][0] * scale, acc[i][1] * scale,
                               acc[i][2] * scale, acc[i][3] * scale);
        *(float4*)(C + (size_t)(m0 + ty * 4 + i) * NN + n0 + tx * 4) = v;
    }
}

// ---------------------------------------------------------------------------
// Row softmax with the reference quirk:
//   v = (k <= q && s != 0) ? s : NEG_FILL;  p = softmax(v)
// One CTA per row; row (4096 floats) staged in shared memory.
// ---------------------------------------------------------------------------
__global__ void __launch_bounds__(256)
softmax_rows(float* __restrict__ Pm)
{
    const int row = blockIdx.x;          // 0 .. BB*NN-1
    const int q = row & (NN - 1);
    float* S = Pm + (size_t)row * NN;

    __shared__ float buf[NN];
    __shared__ float red[256];
    const int tid = threadIdx.x;

    float lmax = -INFINITY;
    for (int k = tid; k < NN; k += 256) {
        float s = S[k];
        float v = (k <= q && s != 0.0f) ? s : NEG_FILL;
        buf[k] = v;
        lmax = fmaxf(lmax, v);
    }
    red[tid] = lmax;
    __syncthreads();
#pragma unroll
    for (int s = 128; s > 0; s >>= 1) {
        if (tid < s) red[tid] = fmaxf(red[tid], red[tid + s]);
        __syncthreads();
    }
    const float mx = red[0];
    __syncthreads();

    float lsum = 0.0f;
    for (int k = tid; k < NN; k += 256) {
        float e = expf(buf[k] - mx);
        buf[k] = e;
        lsum += e;
    }
    red[tid] = lsum;
    __syncthreads();
#pragma unroll
    for (int s = 128; s > 0; s >>= 1) {
        if (tid < s) red[tid] += red[tid + s];
        __syncthreads();
    }
    const float inv = 1.0f / red[0];
    __syncthreads();

    for (int k = tid; k < NN; k += 256)
        S[k] = buf[k] * inv;
}

// ---------------------------------------------------------------------------
extern "C" void kernel_launch(void* const* d_in, const int* in_sizes, int n_in,
                              void* d_out, int out_size)
{
    (void)in_sizes; (void)n_in; (void)out_size;
    const float* X   = (const float*)d_in[0];   // [B,N,E]
    const float* Wq  = (const float*)d_in[1];   // [E,D]
    const float* Wk  = (const float*)d_in[2];   // [E,D]
    const float* Wvd = (const float*)d_in[3];   // [E,D]
    const float* Wvu = (const float*)d_in[4];   // [D,E]
    float* out = (float*)d_out;                 // [B,N,E]

    float *pQ, *pK, *pV, *pWv, *pP;
    cudaGetSymbolAddress((void**)&pQ,  g_Q);
    cudaGetSymbolAddress((void**)&pK,  g_K);
    cudaGetSymbolAddress((void**)&pV,  g_V);
    cudaGetSymbolAddress((void**)&pWv, g_Wv);
    cudaGetSymbolAddress((void**)&pP,  g_P);

    const dim3 blk(256);

    // 1) Wv = Wvdown @ Wvup   [E,E]
    gemm_nn_64<false><<<dim3(EE / 64, EE / 64, 1), blk>>>(
        Wvd, Wvu, pWv, EE, EE, DD, 1.0f, 0, 0, 0);

    // 2) Q = X @ Wq   [B*N, D]
    gemm_nn_64<false><<<dim3(DD / 64, (BB * NN) / 64, 1), blk>>>(
        X, Wq, pQ, BB * NN, DD, EE, 1.0f, 0, 0, 0);

    // 3) K = X @ Wk
    gemm_nn_64<false><<<dim3(DD / 64, (BB * NN) / 64, 1), blk>>>(
        X, Wk, pK, BB * NN, DD, EE, 1.0f, 0, 0, 0);

    // 4) V = X @ Wv   [B*N, E]
    gemm_nn_64<false><<<dim3(EE / 64, (BB * NN) / 64, 1), blk>>>(
        X, pWv, pV, BB * NN, EE, EE, 1.0f, 0, 0, 0);

    // 5) S = Q @ K^T / 16 (causal tiles only)
    gemm_nt_scores<<<dim3(NN / 64, NN / 64, BB), blk>>>(pQ, pK, pP);

    // 6) softmax rows (mask + zero->NEG_FILL quirk applied here)
    softmax_rows<<<BB * NN, 256>>>(pP);

    // 7) out = P @ V  (causal k-limit)
    gemm_nn_64<true><<<dim3(EE / 64, NN / 64, BB), blk>>>(
        pP, pV, out, NN, EE, NN, 1.0f,
        (long long)NN * NN, (long long)NN * EE, (long long)NN * EE);
}

// round 3
// speedup vs baseline: 3.0380x; 3.0380x over previous
#include <cuda_runtime.h>
#include <cuda_bf16.h>
#include <math.h>
#include <stdint.h>

// Problem shape (fixed)
#define BB 4
#define NN 4096
#define EE 1024
#define DD 256
#define NEG_FILL (-3.402823466385288598e+38f)

// ---------------- scratch (static device globals; no allocs) ----------------
__device__ __nv_bfloat16 g_Xh [(size_t)BB * NN * EE];
__device__ __nv_bfloat16 g_Xl [(size_t)BB * NN * EE];
__device__ __nv_bfloat16 g_Qh [(size_t)BB * NN * DD];
__device__ __nv_bfloat16 g_Ql [(size_t)BB * NN * DD];
__device__ __nv_bfloat16 g_Kh [(size_t)BB * NN * DD];
__device__ __nv_bfloat16 g_Kl [(size_t)BB * NN * DD];
__device__ __nv_bfloat16 g_Vth[(size_t)EE * BB * NN];   // V^T [E, B*N]
__device__ __nv_bfloat16 g_Vtl[(size_t)EE * BB * NN];
__device__ __nv_bfloat16 g_WvTh[(size_t)EE * EE];       // (Wvd@Wvu)^T
__device__ __nv_bfloat16 g_WvTl[(size_t)EE * EE];
__device__ __nv_bfloat16 g_WqTh[(size_t)DD * EE];
__device__ __nv_bfloat16 g_WqTl[(size_t)DD * EE];
__device__ __nv_bfloat16 g_WkTh[(size_t)DD * EE];
__device__ __nv_bfloat16 g_WkTl[(size_t)DD * EE];
__device__ __nv_bfloat16 g_WvuTh[(size_t)EE * DD];
__device__ __nv_bfloat16 g_WvuTl[(size_t)EE * DD];
__device__ __nv_bfloat16 g_Wvdh[(size_t)EE * DD];
__device__ __nv_bfloat16 g_Wvdl[(size_t)EE * DD];
__device__ float         g_S  [(size_t)BB * NN * NN];   // raw scores
__device__ __nv_bfloat16 g_Ph [(size_t)BB * NN * NN];   // softmax probs hi
__device__ __nv_bfloat16 g_Pl [(size_t)BB * NN * NN];   // softmax probs lo

// ---------------- helpers ----------------
__device__ __forceinline__ uint32_t smem_u32(const void* p) {
    uint32_t a;
    asm("{ .reg .u64 t; cvta.to.shared.u64 t, %1; cvt.u32.u64 %0, t; }"
        : "=r"(a) : "l"(p));
    return a;
}
__device__ __forceinline__ void ldsm4(uint32_t* r, uint32_t a) {
    asm volatile("ldmatrix.sync.aligned.m8n8.x4.shared.b16 {%0,%1,%2,%3}, [%4];"
                 : "=r"(r[0]), "=r"(r[1]), "=r"(r[2]), "=r"(r[3]) : "r"(a));
}
__device__ __forceinline__ void ldsm2(uint32_t* r, uint32_t a) {
    asm volatile("ldmatrix.sync.aligned.m8n8.x2.shared.b16 {%0,%1}, [%2];"
                 : "=r"(r[0]), "=r"(r[1]) : "r"(a));
}
__device__ __forceinline__ void mma_bf16(float* d, const uint32_t* a, const uint32_t* b) {
    asm volatile(
        "mma.sync.aligned.m16n8k16.row.col.f32.bf16.bf16.f32 "
        "{%0,%1,%2,%3}, {%4,%5,%6,%7}, {%8,%9}, {%0,%1,%2,%3};"
        : "+f"(d[0]), "+f"(d[1]), "+f"(d[2]), "+f"(d[3])
        : "r"(a[0]), "r"(a[1]), "r"(a[2]), "r"(a[3]), "r"(b[0]), "r"(b[1]));
}
__device__ __forceinline__ void cp16(uint32_t saddr, const void* gaddr) {
    asm volatile("cp.async.cg.shared.global [%0], [%1], 16;"
                 :: "r"(saddr), "l"(gaddr) : "memory");
}
#define CP_COMMIT() asm volatile("cp.async.commit_group;" ::: "memory")
#define CP_WAIT1()  asm volatile("cp.async.wait_group 1;" ::: "memory")

// swizzled offset within a 128x32 bf16 tile (rows of 64B, 4x16B chunks)
__device__ __forceinline__ uint32_t tswz(int row, int chunk) {
    return (uint32_t)(row * 64 + ((chunk ^ ((row >> 1) & 3)) << 4));
}

#define TILE_B   8192           // 128*32 bf16
#define STAGE_B  (4 * TILE_B)   // Ah, Al, Bh, Bl
#define NSTAGE   3
#define SMEM_B   (NSTAGE * STAGE_B)

// ---------------------------------------------------------------------------
// bf16 split-3 GEMM:  C[M,N] = alpha * A @ B_nt^T
//   A  hi/lo: [M,K] row-major, ldA;  B_nt hi/lo: [N,K] row-major, ldB
//   OBF: write hi/lo bf16 output (Ch/Cl), else f32 (Cf)
//   CT : transposed write Ct[n*ldC + m]
//   CSKIP: skip tiles strictly above diagonal;  CKLIM: K limited to m0+128
// 128x128x32 tile, 256 threads (8 warps = 2x4), 3-stage cp.async pipeline.
// ---------------------------------------------------------------------------
template <bool CSKIP, bool CKLIM, bool CT, bool OBF>
__global__ void __launch_bounds__(256, 1)
mma_gemm(const __nv_bfloat16* __restrict__ Ah, const __nv_bfloat16* __restrict__ Al,
         const __nv_bfloat16* __restrict__ Bh, const __nv_bfloat16* __restrict__ Bl,
         float* __restrict__ Cf, __nv_bfloat16* __restrict__ Ch,
         __nv_bfloat16* __restrict__ Cl,
         int K, int ldA, int ldB, int ldC, float alpha,
         long long sA, long long sB, long long sC)
{
    const int m0 = blockIdx.y * 128;
    const int n0 = blockIdx.x * 128;
    if (CSKIP && n0 > m0 + 127) return;

    Ah += (size_t)blockIdx.z * sA;  Al += (size_t)blockIdx.z * sA;
    Bh += (size_t)blockIdx.z * sB;  Bl += (size_t)blockIdx.z * sB;
    if (OBF) { Ch += (size_t)blockIdx.z * sC; Cl += (size_t)blockIdx.z * sC; }
    else     { Cf += (size_t)blockIdx.z * sC; }

    int kEnd = K;
    if (CKLIM) { int l = m0 + 128; kEnd = l < K ? l : K; }
    const int numIt = kEnd >> 5;

    extern __shared__ char sm[];
    const int tid = threadIdx.x;
    const int lane = tid & 31;
    const int wid = tid >> 5;
    const int wm = wid >> 2;        // 0..1
    const int wn = wid & 3;         // 0..3

    // ---- cp.async stage issue ----
    auto issue = [&](int stage, int it) {
        char* st = sm + stage * STAGE_B;
        const int k0 = it << 5;
#pragma unroll
        for (int j = 0; j < 2; j++) {
            int idx = tid + j * 256;        // 0..511
            int row = idx >> 2, c = idx & 3;
            uint32_t off = tswz(row, c);
            uint32_t s0 = smem_u32(st) + off;
            const __nv_bfloat16* ga = Ah + (size_t)(m0 + row) * ldA + k0 + c * 8;
            const __nv_bfloat16* gal = Al + (size_t)(m0 + row) * ldA + k0 + c * 8;
            const __nv_bfloat16* gb = Bh + (size_t)(n0 + row) * ldB + k0 + c * 8;
            const __nv_bfloat16* gbl = Bl + (size_t)(n0 + row) * ldB + k0 + c * 8;
            cp16(s0, ga);
            cp16(s0 + TILE_B, gal);
            cp16(s0 + 2 * TILE_B, gb);
            cp16(s0 + 3 * TILE_B, gbl);
        }
    };

    // prologue: 2 stages in flight
    issue(0, 0); CP_COMMIT();
    if (numIt > 1) issue(1, 1);
    CP_COMMIT();

    float acc[4][4][4] = {};

    for (int it = 0; it < numIt; ++it) {
        CP_WAIT1();
        __syncthreads();
        if (it + 2 < numIt) issue((it + 2) % NSTAGE, it + 2);
        CP_COMMIT();

        char* st = sm + (it % NSTAGE) * STAGE_B;
        const uint32_t bAh = smem_u32(st);
        const uint32_t bAl = bAh + TILE_B;
        const uint32_t bBh = bAh + 2 * TILE_B;
        const uint32_t bBl = bAh + 3 * TILE_B;

#pragma unroll
        for (int ks = 0; ks < 2; ks++) {
            uint32_t ah[4][4], al[4][4], bh[4][2], bl[4][2];
            const int arow = wm * 64 + (lane & 15);
            const int ac = ks * 2 + (lane >> 4);
            const int brow = wn * 32 + (lane & 7);
            const int bc = ks * 2 + ((lane >> 3) & 1);
#pragma unroll
            for (int mf = 0; mf < 4; mf++) {
                uint32_t o = tswz(arow + mf * 16, ac);
                ldsm4(ah[mf], bAh + o);
                ldsm4(al[mf], bAl + o);
            }
#pragma unroll
            for (int nf = 0; nf < 4; nf++) {
                uint32_t o = tswz(brow + nf * 8, bc);
                ldsm2(bh[nf], bBh + o);
                ldsm2(bl[nf], bBl + o);
            }
#pragma unroll
            for (int mf = 0; mf < 4; mf++)
#pragma unroll
                for (int nf = 0; nf < 4; nf++) {
                    mma_bf16(acc[mf][nf], ah[mf], bh[nf]);
                    mma_bf16(acc[mf][nf], ah[mf], bl[nf]);
                    mma_bf16(acc[mf][nf], al[mf], bh[nf]);
                }
        }
    }

    // ---- epilogue ----
    const int g = lane >> 2, t2 = (lane & 3) * 2;
#pragma unroll
    for (int mf = 0; mf < 4; mf++)
#pragma unroll
        for (int nf = 0; nf < 4; nf++) {
            const float* a = acc[mf][nf];
            const int r0 = m0 + wm * 64 + mf * 16 + g;
            const int c0 = n0 + wn * 32 + nf * 8 + t2;
#pragma unroll
            for (int h = 0; h < 2; h++) {       // row r0, r0+8
                const int r = r0 + h * 8;
                float v0 = a[h * 2 + 0] * alpha;
                float v1 = a[h * 2 + 1] * alpha;
                if (OBF) {
                    __nv_bfloat16 h0 = __float2bfloat16(v0);
                    __nv_bfloat16 h1 = __float2bfloat16(v1);
                    __nv_bfloat16 l0 = __float2bfloat16(v0 - __bfloat162float(h0));
                    __nv_bfloat16 l1 = __float2bfloat16(v1 - __bfloat162float(h1));
                    if (CT) {
                        Ch[(size_t)c0 * ldC + r] = h0;
                        Ch[(size_t)(c0 + 1) * ldC + r] = h1;
                        Cl[(size_t)c0 * ldC + r] = l0;
                        Cl[(size_t)(c0 + 1) * ldC + r] = l1;
                    } else {
                        *(__nv_bfloat162*)(Ch + (size_t)r * ldC + c0) =
                            __nv_bfloat162(h0, h1);
                        *(__nv_bfloat162*)(Cl + (size_t)r * ldC + c0) =
                            __nv_bfloat162(l0, l1);
                    }
                } else {
                    *(float2*)(Cf + (size_t)r * ldC + c0) = make_float2(v0, v1);
                }
            }
        }
}

// ---------------------------------------------------------------------------
// f32 -> bf16 hi/lo split (elementwise, float4)
// ---------------------------------------------------------------------------
__global__ void __launch_bounds__(256)
split_f32(const float* __restrict__ s, __nv_bfloat16* __restrict__ hp,
          __nv_bfloat16* __restrict__ lp, int n4)
{
    int i = blockIdx.x * 256 + threadIdx.x;
    if (i >= n4) return;
    float4 v = ((const float4*)s)[i];
    __nv_bfloat16 h0 = __float2bfloat16(v.x), h1 = __float2bfloat16(v.y);
    __nv_bfloat16 h2 = __float2bfloat16(v.z), h3 = __float2bfloat16(v.w);
    __nv_bfloat16 l0 = __float2bfloat16(v.x - __bfloat162float(h0));
    __nv_bfloat16 l1 = __float2bfloat16(v.y - __bfloat162float(h1));
    __nv_bfloat16 l2 = __float2bfloat16(v.z - __bfloat162float(h2));
    __nv_bfloat16 l3 = __float2bfloat16(v.w - __bfloat162float(h3));
    ((__nv_bfloat162*)hp)[i * 2 + 0] = __nv_bfloat162(h0, h1);
    ((__nv_bfloat162*)hp)[i * 2 + 1] = __nv_bfloat162(h2, h3);
    ((__nv_bfloat162*)lp)[i * 2 + 0] = __nv_bfloat162(l0, l1);
    ((__nv_bfloat162*)lp)[i * 2 + 1] = __nv_bfloat162(l2, l3);
}

// ---------------------------------------------------------------------------
// transpose + split: src [M,N] f32 -> dstT hi/lo [N,M] bf16
// ---------------------------------------------------------------------------
__global__ void __launch_bounds__(256)
transpose_split(const float* __restrict__ src, __nv_bfloat16* __restrict__ dh,
                __nv_bfloat16* __restrict__ dl, int M, int N)
{
    __shared__ float t[32][33];
    const int bx = blockIdx.x * 32, by = blockIdx.y * 32;
    const int x = threadIdx.x, y = threadIdx.y;
#pragma unroll
    for (int i = 0; i < 32; i += 8)
        t[y + i][x] = src[(size_t)(by + y + i) * N + bx + x];
    __syncthreads();
#pragma unroll
    for (int i = 0; i < 32; i += 8) {
        float v = t[x][y + i];
        __nv_bfloat16 h = __float2bfloat16(v);
        dh[(size_t)(bx + y + i) * M + by + x] = h;
        dl[(size_t)(bx + y + i) * M + by + x] =
            __float2bfloat16(v - __bfloat162float(h));
    }
}

// ---------------------------------------------------------------------------
// Row softmax (lower triangle), reference quirk, writes hi/lo bf16 probs.
// Zero-fills up to the 128 boundary so the PV GEMM's K-limit is exact.
// ---------------------------------------------------------------------------
__global__ void __launch_bounds__(256)
softmax_rows(const float* __restrict__ Sm, __nv_bfloat16* __restrict__ Ph,
             __nv_bfloat16* __restrict__ Pl)
{
    const int row = blockIdx.x;
    const int q = row & (NN - 1);
    const int kup = ((q >> 7) + 1) << 7;
    const float* S = Sm + (size_t)row * NN;
    __nv_bfloat16* ph = Ph + (size_t)row * NN;
    __nv_bfloat16* pl = Pl + (size_t)row * NN;

    __shared__ float buf[NN];
    __shared__ float red[256];
    const int tid = threadIdx.x;

    float lmax = -INFINITY;
    for (int k = tid; k <= q; k += 256) {
        float s = S[k];
        float v = (s != 0.0f) ? s : NEG_FILL;
        buf[k] = v;
        lmax = fmaxf(lmax, v);
    }
    red[tid] = lmax;
    __syncthreads();
#pragma unroll
    for (int s = 128; s > 0; s >>= 1) {
        if (tid < s) red[tid] = fmaxf(red[tid], red[tid + s]);
        __syncthreads();
    }
    const float mx = red[0];
    __syncthreads();

    float lsum = 0.0f;
    for (int k = tid; k <= q; k += 256) {
        float e = expf(buf[k] - mx);
        buf[k] = e;
        lsum += e;
    }
    red[tid] = lsum;
    __syncthreads();
#pragma unroll
    for (int s = 128; s > 0; s >>= 1) {
        if (tid < s) red[tid] += red[tid + s];
        __syncthreads();
    }
    const float inv = 1.0f / red[0];
    __syncthreads();

    for (int k = tid; k < kup; k += 256) {
        float p = (k <= q) ? buf[k] * inv : 0.0f;
        __nv_bfloat16 h = __float2bfloat16(p);
        ph[k] = h;
        pl[k] = __float2bfloat16(p - __bfloat162float(h));
    }
}

// ---------------------------------------------------------------------------
extern "C" void kernel_launch(void* const* d_in, const int* in_sizes, int n_in,
                              void* d_out, int out_size)
{
    (void)in_sizes; (void)n_in; (void)out_size;
    const float* X   = (const float*)d_in[0];
    const float* Wq  = (const float*)d_in[1];
    const float* Wk  = (const float*)d_in[2];
    const float* Wvd = (const float*)d_in[3];
    const float* Wvu = (const float*)d_in[4];
    float* out = (float*)d_out;

    __nv_bfloat16 *pXh, *pXl, *pQh, *pQl, *pKh, *pKl, *pVth, *pVtl;
    __nv_bfloat16 *pWvTh, *pWvTl, *pWqTh, *pWqTl, *pWkTh, *pWkTl;
    __nv_bfloat16 *pWvuTh, *pWvuTl, *pWvdh, *pWvdl, *pPh, *pPl;
    float* pS;
    cudaGetSymbolAddress((void**)&pXh, g_Xh);   cudaGetSymbolAddress((void**)&pXl, g_Xl);
    cudaGetSymbolAddress((void**)&pQh, g_Qh);   cudaGetSymbolAddress((void**)&pQl, g_Ql);
    cudaGetSymbolAddress((void**)&pKh, g_Kh);   cudaGetSymbolAddress((void**)&pKl, g_Kl);
    cudaGetSymbolAddress((void**)&pVth, g_Vth); cudaGetSymbolAddress((void**)&pVtl, g_Vtl);
    cudaGetSymbolAddress((void**)&pWvTh, g_WvTh); cudaGetSymbolAddress((void**)&pWvTl, g_WvTl);
    cudaGetSymbolAddress((void**)&pWqTh, g_WqTh); cudaGetSymbolAddress((void**)&pWqTl, g_WqTl);
    cudaGetSymbolAddress((void**)&pWkTh, g_WkTh); cudaGetSymbolAddress((void**)&pWkTl, g_WkTl);
    cudaGetSymbolAddress((void**)&pWvuTh, g_WvuTh); cudaGetSymbolAddress((void**)&pWvuTl, g_WvuTl);
    cudaGetSymbolAddress((void**)&pWvdh, g_Wvdh); cudaGetSymbolAddress((void**)&pWvdl, g_Wvdl);
    cudaGetSymbolAddress((void**)&pPh, g_Ph);   cudaGetSymbolAddress((void**)&pPl, g_Pl);
    cudaGetSymbolAddress((void**)&pS, g_S);

    cudaFuncSetAttribute(mma_gemm<false, false, true,  true>,
                         cudaFuncAttributeMaxDynamicSharedMemorySize, SMEM_B);
    cudaFuncSetAttribute(mma_gemm<false, false, false, true>,
                         cudaFuncAttributeMaxDynamicSharedMemorySize, SMEM_B);
    cudaFuncSetAttribute(mma_gemm<true,  false, false, false>,
                         cudaFuncAttributeMaxDynamicSharedMemorySize, SMEM_B);
    cudaFuncSetAttribute(mma_gemm<false, true,  false, false>,
                         cudaFuncAttributeMaxDynamicSharedMemorySize, SMEM_B);

    const dim3 blk(256);
    const dim3 tblk(32, 8);

    // ---- prep: splits & transposed-split weights ----
    split_f32<<<(BB * NN * EE / 4 + 255) / 256, blk>>>(X, pXh, pXl, BB * NN * EE / 4);
    split_f32<<<(EE * DD / 4 + 255) / 256, blk>>>(Wvd, pWvdh, pWvdl, EE * DD / 4);
    transpose_split<<<dim3(DD / 32, EE / 32), tblk>>>(Wq, pWqTh, pWqTl, EE, DD);
    transpose_split<<<dim3(DD / 32, EE / 32), tblk>>>(Wk, pWkTh, pWkTl, EE, DD);
    transpose_split<<<dim3(EE / 32, DD / 32), tblk>>>(Wvu, pWvuTh, pWvuTl, DD, EE);

    // 1) WvT = (Wvd @ Wvu)^T   (CT epilogue, bf16 hi/lo out)  M=1024 N=1024 K=256
    mma_gemm<false, false, true, true><<<dim3(8, 8, 1), blk, SMEM_B>>>(
        pWvdh, pWvdl, pWvuTh, pWvuTl, nullptr, pWvTh, pWvTl,
        DD, DD, DD, EE, 1.0f, 0, 0, 0);

    // 2) Q = X @ Wq  -> Qh/Ql   M=16384 N=256 K=1024
    mma_gemm<false, false, false, true><<<dim3(2, 128, 1), blk, SMEM_B>>>(
        pXh, pXl, pWqTh, pWqTl, nullptr, pQh, pQl,
        EE, EE, EE, DD, 1.0f, 0, 0, 0);

    // 3) K = X @ Wk
    mma_gemm<false, false, false, true><<<dim3(2, 128, 1), blk, SMEM_B>>>(
        pXh, pXl, pWkTh, pWkTl, nullptr, pKh, pKl,
        EE, EE, EE, DD, 1.0f, 0, 0, 0);

    // 4) Vt = WvT @ X^T (A=WvT, B_nt=X)  M=1024 N=16384 K=1024, straight bf16 out
    mma_gemm<false, false, false, true><<<dim3(128, 8, 1), blk, SMEM_B>>>(
        pWvTh, pWvTl, pXh, pXl, nullptr, pVth, pVtl,
        EE, EE, EE, BB * NN, 1.0f, 0, 0, 0);

    // 5) S = Q @ K^T / 16 (causal tile skip), f32 out
    mma_gemm<true, false, false, false><<<dim3(32, 32, BB), blk, SMEM_B>>>(
        pQh, pQl, pKh, pKl, pS, nullptr, nullptr,
        DD, DD, DD, NN, 1.0f / 16.0f,
        (long long)NN * DD, (long long)NN * DD, (long long)NN * NN);

    // 6) softmax -> Ph/Pl
    softmax_rows<<<BB * NN, 256>>>(pS, pPh, pPl);

    // 7) out = P @ V  (A=Ph/Pl, B_nt=Vt slice, causal K-limit), f32 out
    mma_gemm<false, true, false, false><<<dim3(8, 32, BB), blk, SMEM_B>>>(
        pPh, pPl, pVth, pVtl, out, nullptr, nullptr,
        NN, NN, BB * NN, EE, 1.0f,
        (long long)NN * NN, (long long)NN, (long long)NN * EE);
}

// round 5
// speedup vs baseline: 4.9009x; 1.6132x over previous
#include <cuda_runtime.h>
#include <cuda_bf16.h>
#include <math.h>
#include <stdint.h>

// Problem shape (fixed)
#define BB 4
#define NN 4096
#define EE 1024
#define DD 256
#define NEG_FILL (-3.402823466385288598e+38f)

// ---------------- scratch (static device globals; no allocs) ----------------
__device__ __nv_bfloat16 g_Xh  [(size_t)BB * NN * EE];
__device__ __nv_bfloat16 g_Xl  [(size_t)BB * NN * EE];
__device__ __nv_bfloat16 g_Qh  [(size_t)BB * NN * DD];
__device__ __nv_bfloat16 g_Ql  [(size_t)BB * NN * DD];
__device__ __nv_bfloat16 g_Kh  [(size_t)BB * NN * DD];
__device__ __nv_bfloat16 g_Kl  [(size_t)BB * NN * DD];
__device__ __nv_bfloat16 g_VdTh[(size_t)DD * BB * NN];  // (X@Wvd)^T  [256, B*N]
__device__ __nv_bfloat16 g_VdTl[(size_t)DD * BB * NN];
__device__ __nv_bfloat16 g_Th  [(size_t)BB * NN * DD];  // T = P@Vd   [B*N, 256]
__device__ __nv_bfloat16 g_Tl  [(size_t)BB * NN * DD];
__device__ __nv_bfloat16 g_WqTh[(size_t)DD * EE];
__device__ __nv_bfloat16 g_WqTl[(size_t)DD * EE];
__device__ __nv_bfloat16 g_WkTh[(size_t)DD * EE];
__device__ __nv_bfloat16 g_WkTl[(size_t)DD * EE];
__device__ __nv_bfloat16 g_WvdTh[(size_t)DD * EE];
__device__ __nv_bfloat16 g_WvdTl[(size_t)DD * EE];
__device__ __nv_bfloat16 g_WvuTh[(size_t)EE * DD];
__device__ __nv_bfloat16 g_WvuTl[(size_t)EE * DD];
__device__ float         g_S   [(size_t)BB * NN * NN];  // raw scores
__device__ __nv_bfloat16 g_Ph  [(size_t)BB * NN * NN];  // softmax probs hi
__device__ __nv_bfloat16 g_Pl  [(size_t)BB * NN * NN];  // softmax probs lo

// ---------------- helpers ----------------
__device__ __forceinline__ uint32_t smem_u32(const void* p) {
    uint32_t a;
    asm("{ .reg .u64 t; cvta.to.shared.u64 t, %1; cvt.u32.u64 %0, t; }"
        : "=r"(a) : "l"(p));
    return a;
}
__device__ __forceinline__ void ldsm4(uint32_t* r, uint32_t a) {
    asm volatile("ldmatrix.sync.aligned.m8n8.x4.shared.b16 {%0,%1,%2,%3}, [%4];"
                 : "=r"(r[0]), "=r"(r[1]), "=r"(r[2]), "=r"(r[3]) : "r"(a));
}
__device__ __forceinline__ void ldsm2(uint32_t* r, uint32_t a) {
    asm volatile("ldmatrix.sync.aligned.m8n8.x2.shared.b16 {%0,%1}, [%2];"
                 : "=r"(r[0]), "=r"(r[1]) : "r"(a));
}
__device__ __forceinline__ void mma_bf16(float* d, const uint32_t* a, const uint32_t* b) {
    asm volatile(
        "mma.sync.aligned.m16n8k16.row.col.f32.bf16.bf16.f32 "
        "{%0,%1,%2,%3}, {%4,%5,%6,%7}, {%8,%9}, {%0,%1,%2,%3};"
        : "+f"(d[0]), "+f"(d[1]), "+f"(d[2]), "+f"(d[3])
        : "r"(a[0]), "r"(a[1]), "r"(a[2]), "r"(a[3]), "r"(b[0]), "r"(b[1]));
}
__device__ __forceinline__ void cp16(uint32_t saddr, const void* gaddr) {
    asm volatile("cp.async.cg.shared.global [%0], [%1], 16;"
                 :: "r"(saddr), "l"(gaddr) : "memory");
}
#define CP_COMMIT() asm volatile("cp.async.commit_group;" ::: "memory")
#define CP_WAIT1()  asm volatile("cp.async.wait_group 1;" ::: "memory")

// swizzled offset within a 128x32 bf16 tile (rows of 64B, 4x16B chunks)
__device__ __forceinline__ uint32_t tswz(int row, int chunk) {
    return (uint32_t)(row * 64 + ((chunk ^ ((row >> 1) & 3)) << 4));
}

#define TILE_B   8192           // 128*32 bf16
#define STAGE_B  (4 * TILE_B)   // Ah, Al, Bh, Bl
#define NSTAGE   3
#define SMEM_B   (NSTAGE * STAGE_B)

// ---------------------------------------------------------------------------
// bf16 split-3 GEMM:  C[M,N] = alpha * A @ B_nt^T
//   A  hi/lo: [M,K] row-major, ldA;  B_nt hi/lo: [N,K] row-major, ldB
//   OBF: write hi/lo bf16 output (Ch/Cl), else f32 (Cf)
//   CT : transposed write Ct[n*ldC + m]
//   CSKIP: skip tiles strictly above diagonal;  CKLIM: K limited to m0+128
// 128x128x32 tile, 256 threads (8 warps = 2x4), 3-stage cp.async pipeline.
// ---------------------------------------------------------------------------
template <bool CSKIP, bool CKLIM, bool CT, bool OBF>
__global__ void __launch_bounds__(256, 1)
mma_gemm(const __nv_bfloat16* __restrict__ Ah, const __nv_bfloat16* __restrict__ Al,
         const __nv_bfloat16* __restrict__ Bh, const __nv_bfloat16* __restrict__ Bl,
         float* __restrict__ Cf, __nv_bfloat16* __restrict__ Ch,
         __nv_bfloat16* __restrict__ Cl,
         int K, int ldA, int ldB, int ldC, float alpha,
         long long sA, long long sB, long long sC)
{
    const int m0 = blockIdx.y * 128;
    const int n0 = blockIdx.x * 128;
    if (CSKIP && n0 > m0 + 127) return;

    Ah += (size_t)blockIdx.z * sA;  Al += (size_t)blockIdx.z * sA;
    Bh += (size_t)blockIdx.z * sB;  Bl += (size_t)blockIdx.z * sB;
    if (OBF) { Ch += (size_t)blockIdx.z * sC; Cl += (size_t)blockIdx.z * sC; }
    else     { Cf += (size_t)blockIdx.z * sC; }

    int kEnd = K;
    if (CKLIM) { int l = m0 + 128; kEnd = l < K ? l : K; }
    const int numIt = kEnd >> 5;

    extern __shared__ char sm[];
    const int tid = threadIdx.x;
    const int lane = tid & 31;
    const int wid = tid >> 5;
    const int wm = wid >> 2;        // 0..1
    const int wn = wid & 3;         // 0..3

    auto issue = [&](int stage, int it) {
        char* st = sm + stage * STAGE_B;
        const int k0 = it << 5;
#pragma unroll
        for (int j = 0; j < 2; j++) {
            int idx = tid + j * 256;        // 0..511
            int row = idx >> 2, c = idx & 3;
            uint32_t off = tswz(row, c);
            uint32_t s0 = smem_u32(st) + off;
            const __nv_bfloat16* ga  = Ah + (size_t)(m0 + row) * ldA + k0 + c * 8;
            const __nv_bfloat16* gal = Al + (size_t)(m0 + row) * ldA + k0 + c * 8;
            const __nv_bfloat16* gb  = Bh + (size_t)(n0 + row) * ldB + k0 + c * 8;
            const __nv_bfloat16* gbl = Bl + (size_t)(n0 + row) * ldB + k0 + c * 8;
            cp16(s0, ga);
            cp16(s0 + TILE_B, gal);
            cp16(s0 + 2 * TILE_B, gb);
            cp16(s0 + 3 * TILE_B, gbl);
        }
    };

    issue(0, 0); CP_COMMIT();
    if (numIt > 1) issue(1, 1);
    CP_COMMIT();

    float acc[4][4][4] = {};

    for (int it = 0; it < numIt; ++it) {
        CP_WAIT1();
        __syncthreads();
        if (it + 2 < numIt) issue((it + 2) % NSTAGE, it + 2);
        CP_COMMIT();

        char* st = sm + (it % NSTAGE) * STAGE_B;
        const uint32_t bAh = smem_u32(st);
        const uint32_t bAl = bAh + TILE_B;
        const uint32_t bBh = bAh + 2 * TILE_B;
        const uint32_t bBl = bAh + 3 * TILE_B;

#pragma unroll
        for (int ks = 0; ks < 2; ks++) {
            uint32_t ah[4][4], al[4][4], bh[4][2], bl[4][2];
            const int arow = wm * 64 + (lane & 15);
            const int ac = ks * 2 + (lane >> 4);
            const int brow = wn * 32 + (lane & 7);
            const int bc = ks * 2 + ((lane >> 3) & 1);
#pragma unroll
            for (int mf = 0; mf < 4; mf++) {
                uint32_t o = tswz(arow + mf * 16, ac);
                ldsm4(ah[mf], bAh + o);
                ldsm4(al[mf], bAl + o);
            }
#pragma unroll
            for (int nf = 0; nf < 4; nf++) {
                uint32_t o = tswz(brow + nf * 8, bc);
                ldsm2(bh[nf], bBh + o);
                ldsm2(bl[nf], bBl + o);
            }
#pragma unroll
            for (int mf = 0; mf < 4; mf++)
#pragma unroll
                for (int nf = 0; nf < 4; nf++) {
                    mma_bf16(acc[mf][nf], ah[mf], bh[nf]);
                    mma_bf16(acc[mf][nf], ah[mf], bl[nf]);
                    mma_bf16(acc[mf][nf], al[mf], bh[nf]);
                }
        }
    }

    // ---- epilogue ----
    const int g = lane >> 2, t2 = (lane & 3) * 2;
#pragma unroll
    for (int mf = 0; mf < 4; mf++)
#pragma unroll
        for (int nf = 0; nf < 4; nf++) {
            const float* a = acc[mf][nf];
            const int r0 = m0 + wm * 64 + mf * 16 + g;
            const int c0 = n0 + wn * 32 + nf * 8 + t2;
#pragma unroll
            for (int h = 0; h < 2; h++) {
                const int r = r0 + h * 8;
                float v0 = a[h * 2 + 0] * alpha;
                float v1 = a[h * 2 + 1] * alpha;
                if (OBF) {
                    __nv_bfloat16 h0 = __float2bfloat16(v0);
                    __nv_bfloat16 h1 = __float2bfloat16(v1);
                    __nv_bfloat16 l0 = __float2bfloat16(v0 - __bfloat162float(h0));
                    __nv_bfloat16 l1 = __float2bfloat16(v1 - __bfloat162float(h1));
                    if (CT) {
                        Ch[(size_t)c0 * ldC + r] = h0;
                        Ch[(size_t)(c0 + 1) * ldC + r] = h1;
                        Cl[(size_t)c0 * ldC + r] = l0;
                        Cl[(size_t)(c0 + 1) * ldC + r] = l1;
                    } else {
                        *(__nv_bfloat162*)(Ch + (size_t)r * ldC + c0) =
                            __nv_bfloat162(h0, h1);
                        *(__nv_bfloat162*)(Cl + (size_t)r * ldC + c0) =
                            __nv_bfloat162(l0, l1);
                    }
                } else {
                    *(float2*)(Cf + (size_t)r * ldC + c0) = make_float2(v0, v1);
                }
            }
        }
}

// ---------------------------------------------------------------------------
// f32 -> bf16 hi/lo split (elementwise, float4)
// ---------------------------------------------------------------------------
__global__ void __launch_bounds__(256)
split_f32(const float* __restrict__ s, __nv_bfloat16* __restrict__ hp,
          __nv_bfloat16* __restrict__ lp, int n4)
{
    int i = blockIdx.x * 256 + threadIdx.x;
    if (i >= n4) return;
    float4 v = ((const float4*)s)[i];
    __nv_bfloat16 h0 = __float2bfloat16(v.x), h1 = __float2bfloat16(v.y);
    __nv_bfloat16 h2 = __float2bfloat16(v.z), h3 = __float2bfloat16(v.w);
    __nv_bfloat16 l0 = __float2bfloat16(v.x - __bfloat162float(h0));
    __nv_bfloat16 l1 = __float2bfloat16(v.y - __bfloat162float(h1));
    __nv_bfloat16 l2 = __float2bfloat16(v.z - __bfloat162float(h2));
    __nv_bfloat16 l3 = __float2bfloat16(v.w - __bfloat162float(h3));
    ((__nv_bfloat162*)hp)[i * 2 + 0] = __nv_bfloat162(h0, h1);
    ((__nv_bfloat162*)hp)[i * 2 + 1] = __nv_bfloat162(h2, h3);
    ((__nv_bfloat162*)lp)[i * 2 + 0] = __nv_bfloat162(l0, l1);
    ((__nv_bfloat162*)lp)[i * 2 + 1] = __nv_bfloat162(l2, l3);
}

// ---------------------------------------------------------------------------
// transpose + split: src [M,N] f32 -> dstT hi/lo [N,M] bf16
// ---------------------------------------------------------------------------
__global__ void __launch_bounds__(256)
transpose_split(const float* __restrict__ src, __nv_bfloat16* __restrict__ dh,
                __nv_bfloat16* __restrict__ dl, int M, int N)
{
    __shared__ float t[32][33];
    const int bx = blockIdx.x * 32, by = blockIdx.y * 32;
    const int x = threadIdx.x, y = threadIdx.y;
#pragma unroll
    for (int i = 0; i < 32; i += 8)
        t[y + i][x] = src[(size_t)(by + y + i) * N + bx + x];
    __syncthreads();
#pragma unroll
    for (int i = 0; i < 32; i += 8) {
        float v = t[x][y + i];
        __nv_bfloat16 h = __float2bfloat16(v);
        dh[(size_t)(bx + y + i) * M + by + x] = h;
        dl[(size_t)(bx + y + i) * M + by + x] =
            __float2bfloat16(v - __bfloat162float(h));
    }
}

// ---------------------------------------------------------------------------
// Row softmax (lower triangle), reference quirk, writes hi/lo bf16 probs.
// Zero-fills up to the 128 boundary so the T GEMM's K-limit is exact.
// ---------------------------------------------------------------------------
__global__ void __launch_bounds__(256)
softmax_rows(const float* __restrict__ Sm, __nv_bfloat16* __restrict__ Ph,
             __nv_bfloat16* __restrict__ Pl)
{
    const int row = blockIdx.x;
    const int q = row & (NN - 1);
    const int kup = ((q >> 7) + 1) << 7;
    const float* S = Sm + (size_t)row * NN;
    __nv_bfloat16* ph = Ph + (size_t)row * NN;
    __nv_bfloat16* pl = Pl + (size_t)row * NN;

    __shared__ float buf[NN];
    __shared__ float red[256];
    const int tid = threadIdx.x;

    float lmax = -INFINITY;
    for (int k = tid; k <= q; k += 256) {
        float s = S[k];
        float v = (s != 0.0f) ? s : NEG_FILL;
        buf[k] = v;
        lmax = fmaxf(lmax, v);
    }
    red[tid] = lmax;
    __syncthreads();
#pragma unroll
    for (int s = 128; s > 0; s >>= 1) {
        if (tid < s) red[tid] = fmaxf(red[tid], red[tid + s]);
        __syncthreads();
    }
    const float mx = red[0];
    __syncthreads();

    float lsum = 0.0f;
    for (int k = tid; k <= q; k += 256) {
        float e = expf(buf[k] - mx);
        buf[k] = e;
        lsum += e;
    }
    red[tid] = lsum;
    __syncthreads();
#pragma unroll
    for (int s = 128; s > 0; s >>= 1) {
        if (tid < s) red[tid] += red[tid + s];
        __syncthreads();
    }
    const float inv = 1.0f / red[0];
    __syncthreads();

    for (int k = tid; k < kup; k += 256) {
        float p = (k <= q) ? buf[k] * inv : 0.0f;
        __nv_bfloat16 h = __float2bfloat16(p);
        ph[k] = h;
        pl[k] = __float2bfloat16(p - __bfloat162float(h));
    }
}

// ---------------------------------------------------------------------------
extern "C" void kernel_launch(void* const* d_in, const int* in_sizes, int n_in,
                              void* d_out, int out_size)
{
    (void)in_sizes; (void)n_in; (void)out_size;
    const float* X   = (const float*)d_in[0];
    const float* Wq  = (const float*)d_in[1];
    const float* Wk  = (const float*)d_in[2];
    const float* Wvd = (const float*)d_in[3];
    const float* Wvu = (const float*)d_in[4];
    float* out = (float*)d_out;

    __nv_bfloat16 *pXh, *pXl, *pQh, *pQl, *pKh, *pKl, *pVdTh, *pVdTl, *pTh, *pTl;
    __nv_bfloat16 *pWqTh, *pWqTl, *pWkTh, *pWkTl, *pWvdTh, *pWvdTl, *pWvuTh, *pWvuTl;
    __nv_bfloat16 *pPh, *pPl;
    float* pS;
    cudaGetSymbolAddress((void**)&pXh, g_Xh);     cudaGetSymbolAddress((void**)&pXl, g_Xl);
    cudaGetSymbolAddress((void**)&pQh, g_Qh);     cudaGetSymbolAddress((void**)&pQl, g_Ql);
    cudaGetSymbolAddress((void**)&pKh, g_Kh);     cudaGetSymbolAddress((void**)&pKl, g_Kl);
    cudaGetSymbolAddress((void**)&pVdTh, g_VdTh); cudaGetSymbolAddress((void**)&pVdTl, g_VdTl);
    cudaGetSymbolAddress((void**)&pTh, g_Th);     cudaGetSymbolAddress((void**)&pTl, g_Tl);
    cudaGetSymbolAddress((void**)&pWqTh, g_WqTh); cudaGetSymbolAddress((void**)&pWqTl, g_WqTl);
    cudaGetSymbolAddress((void**)&pWkTh, g_WkTh); cudaGetSymbolAddress((void**)&pWkTl, g_WkTl);
    cudaGetSymbolAddress((void**)&pWvdTh, g_WvdTh); cudaGetSymbolAddress((void**)&pWvdTl, g_WvdTl);
    cudaGetSymbolAddress((void**)&pWvuTh, g_WvuTh); cudaGetSymbolAddress((void**)&pWvuTl, g_WvuTl);
    cudaGetSymbolAddress((void**)&pPh, g_Ph);     cudaGetSymbolAddress((void**)&pPl, g_Pl);
    cudaGetSymbolAddress((void**)&pS, g_S);

    cudaFuncSetAttribute(mma_gemm<false, false, false, true>,
                         cudaFuncAttributeMaxDynamicSharedMemorySize, SMEM_B);
    cudaFuncSetAttribute(mma_gemm<false, false, true,  true>,
                         cudaFuncAttributeMaxDynamicSharedMemorySize, SMEM_B);
    cudaFuncSetAttribute(mma_gemm<true,  false, false, false>,
                         cudaFuncAttributeMaxDynamicSharedMemorySize, SMEM_B);
    cudaFuncSetAttribute(mma_gemm<false, true,  false, true>,
                         cudaFuncAttributeMaxDynamicSharedMemorySize, SMEM_B);
    cudaFuncSetAttribute(mma_gemm<false, false, false, false>,
                         cudaFuncAttributeMaxDynamicSharedMemorySize, SMEM_B);

    const dim3 blk(256);
    const dim3 tblk(32, 8);

    // ---- prep: split X; transpose+split all weights ----
    split_f32<<<(BB * NN * EE / 4 + 255) / 256, blk>>>(X, pXh, pXl, BB * NN * EE / 4);
    transpose_split<<<dim3(DD / 32, EE / 32), tblk>>>(Wq,  pWqTh,  pWqTl,  EE, DD);
    transpose_split<<<dim3(DD / 32, EE / 32), tblk>>>(Wk,  pWkTh,  pWkTl,  EE, DD);
    transpose_split<<<dim3(DD / 32, EE / 32), tblk>>>(Wvd, pWvdTh, pWvdTl, EE, DD);
    transpose_split<<<dim3(EE / 32, DD / 32), tblk>>>(Wvu, pWvuTh, pWvuTl, DD, EE);

    // 1) Q = X @ Wq   M=16384 N=256 K=1024
    mma_gemm<false, false, false, true><<<dim3(2, 128, 1), blk, SMEM_B>>>(
        pXh, pXl, pWqTh, pWqTl, nullptr, pQh, pQl,
        EE, EE, EE, DD, 1.0f, 0, 0, 0);

    // 2) K = X @ Wk
    mma_gemm<false, false, false, true><<<dim3(2, 128, 1), blk, SMEM_B>>>(
        pXh, pXl, pWkTh, pWkTl, nullptr, pKh, pKl,
        EE, EE, EE, DD, 1.0f, 0, 0, 0);

    // 3) VdT = (X @ Wvd)^T   (CT epilogue) -> [256, 16384]
    mma_gemm<false, false, true, true><<<dim3(2, 128, 1), blk, SMEM_B>>>(
        pXh, pXl, pWvdTh, pWvdTl, nullptr, pVdTh, pVdTl,
        EE, EE, EE, BB * NN, 1.0f, 0, 0, 0);

    // 4) S = Q @ K^T / 16 (causal tile skip), f32 out, per batch
    mma_gemm<true, false, false, false><<<dim3(32, 32, BB), blk, SMEM_B>>>(
        pQh, pQl, pKh, pKl, pS, nullptr, nullptr,
        DD, DD, DD, NN, 1.0f / 16.0f,
        (long long)NN * DD, (long long)NN * DD, (long long)NN * NN);

    // 5) softmax -> Ph/Pl
    softmax_rows<<<BB * NN, 256>>>(pS, pPh, pPl);

    // 6) T = P @ Vd (causal K-limit), bf16 hi/lo out, per batch   [N, 256]
    mma_gemm<false, true, false, true><<<dim3(2, 32, BB), blk, SMEM_B>>>(
        pPh, pPl, pVdTh, pVdTl, nullptr, pTh, pTl,
        NN, NN, BB * NN, DD, 1.0f,
        (long long)NN * NN, (long long)NN, (long long)NN * DD);

    // 7) out = T @ Wvu   M=16384 N=1024 K=256, f32 out
    mma_gemm<false, false, false, false><<<dim3(8, 128, 1), blk, SMEM_B>>>(
        pTh, pTl, pWvuTh, pWvuTl, out, nullptr, nullptr,
        DD, DD, DD, EE, 1.0f, 0, 0, 0);
}

// round 6
// speedup vs baseline: 5.0114x; 1.0226x over previous
#include <cuda_runtime.h>
#include <cuda_bf16.h>
#include <math.h>
#include <stdint.h>

// Problem shape (fixed)
#define BB 4
#define NN 4096
#define EE 1024
#define DD 256
#define NEG_FILL (-3.402823466385288598e+38f)

// ---------------- scratch (static device globals; no allocs) ----------------
__device__ __nv_bfloat16 g_Xh  [(size_t)BB * NN * EE];
__device__ __nv_bfloat16 g_Xl  [(size_t)BB * NN * EE];
__device__ __nv_bfloat16 g_Qh  [(size_t)BB * NN * DD];
__device__ __nv_bfloat16 g_Ql  [(size_t)BB * NN * DD];
__device__ __nv_bfloat16 g_Kh  [(size_t)BB * NN * DD];
__device__ __nv_bfloat16 g_Kl  [(size_t)BB * NN * DD];
__device__ __nv_bfloat16 g_VdTh[(size_t)DD * BB * NN];  // (X@Wvd)^T  [256, B*N]
__device__ __nv_bfloat16 g_VdTl[(size_t)DD * BB * NN];
__device__ __nv_bfloat16 g_Th  [(size_t)BB * NN * DD];  // T = P@Vd   [B*N, 256]
__device__ __nv_bfloat16 g_Tl  [(size_t)BB * NN * DD];
__device__ __nv_bfloat16 g_WqTh[(size_t)DD * EE];
__device__ __nv_bfloat16 g_WqTl[(size_t)DD * EE];
__device__ __nv_bfloat16 g_WkTh[(size_t)DD * EE];
__device__ __nv_bfloat16 g_WkTl[(size_t)DD * EE];
__device__ __nv_bfloat16 g_WvdTh[(size_t)DD * EE];
__device__ __nv_bfloat16 g_WvdTl[(size_t)DD * EE];
__device__ __nv_bfloat16 g_WvuTh[(size_t)EE * DD];
__device__ __nv_bfloat16 g_WvuTl[(size_t)EE * DD];
__device__ float         g_S   [(size_t)BB * NN * NN];  // raw scores
__device__ __nv_bfloat16 g_Ph  [(size_t)BB * NN * NN];  // softmax probs hi
__device__ __nv_bfloat16 g_Pl  [(size_t)BB * NN * NN];  // softmax probs lo

// ---------------- helpers ----------------
__device__ __forceinline__ uint32_t smem_u32(const void* p) {
    uint32_t a;
    asm("{ .reg .u64 t; cvta.to.shared.u64 t, %1; cvt.u32.u64 %0, t; }"
        : "=r"(a) : "l"(p));
    return a;
}
__device__ __forceinline__ void ldsm4(uint32_t* r, uint32_t a) {
    asm volatile("ldmatrix.sync.aligned.m8n8.x4.shared.b16 {%0,%1,%2,%3}, [%4];"
                 : "=r"(r[0]), "=r"(r[1]), "=r"(r[2]), "=r"(r[3]) : "r"(a));
}
__device__ __forceinline__ void ldsm2(uint32_t* r, uint32_t a) {
    asm volatile("ldmatrix.sync.aligned.m8n8.x2.shared.b16 {%0,%1}, [%2];"
                 : "=r"(r[0]), "=r"(r[1]) : "r"(a));
}
__device__ __forceinline__ void mma_bf16(float* d, const uint32_t* a, const uint32_t* b) {
    asm volatile(
        "mma.sync.aligned.m16n8k16.row.col.f32.bf16.bf16.f32 "
        "{%0,%1,%2,%3}, {%4,%5,%6,%7}, {%8,%9}, {%0,%1,%2,%3};"
        : "+f"(d[0]), "+f"(d[1]), "+f"(d[2]), "+f"(d[3])
        : "r"(a[0]), "r"(a[1]), "r"(a[2]), "r"(a[3]), "r"(b[0]), "r"(b[1]));
}
__device__ __forceinline__ void cp16(uint32_t saddr, const void* gaddr) {
    asm volatile("cp.async.cg.shared.global [%0], [%1], 16;"
                 :: "r"(saddr), "l"(gaddr) : "memory");
}
#define CP_COMMIT() asm volatile("cp.async.commit_group;" ::: "memory")
#define CP_WAIT2()  asm volatile("cp.async.wait_group 2;" ::: "memory")

// swizzled offset within a 128x32 bf16 tile (rows of 64B, 4x16B chunks)
__device__ __forceinline__ uint32_t tswz(int row, int chunk) {
    return (uint32_t)(row * 64 + ((chunk ^ ((row >> 1) & 3)) << 4));
}

#define TILE_B   8192           // 128*32 bf16
#define STAGE_B  (4 * TILE_B)   // Ah, Al, Bh, Bl
#define NSTAGE   4
#define SMEM_B   (NSTAGE * STAGE_B)

// ---------------------------------------------------------------------------
// Mainloop core: 128x128x(32*numIt) split-3 bf16 MMA, 4-stage cp.async.
// Leaves result in acc[4][4][4].
// ---------------------------------------------------------------------------
__device__ __forceinline__ void gemm_core(
    const __nv_bfloat16* __restrict__ Ah, const __nv_bfloat16* __restrict__ Al,
    const __nv_bfloat16* __restrict__ Bh, const __nv_bfloat16* __restrict__ Bl,
    int m0, int n0, int ldA, int ldB, int numIt, char* sm,
    float acc[4][4][4])
{
    const int tid = threadIdx.x;
    const int lane = tid & 31;
    const int wid = tid >> 5;
    const int wm = wid >> 2;        // 0..1
    const int wn = wid & 3;         // 0..3

    auto issue = [&](int stage, int it) {
        char* st = sm + stage * STAGE_B;
        const int k0 = it << 5;
#pragma unroll
        for (int j = 0; j < 2; j++) {
            int idx = tid + j * 256;        // 0..511
            int row = idx >> 2, c = idx & 3;
            uint32_t off = tswz(row, c);
            uint32_t s0 = smem_u32(st) + off;
            const __nv_bfloat16* ga  = Ah + (size_t)(m0 + row) * ldA + k0 + c * 8;
            const __nv_bfloat16* gal = Al + (size_t)(m0 + row) * ldA + k0 + c * 8;
            const __nv_bfloat16* gb  = Bh + (size_t)(n0 + row) * ldB + k0 + c * 8;
            const __nv_bfloat16* gbl = Bl + (size_t)(n0 + row) * ldB + k0 + c * 8;
            cp16(s0, ga);
            cp16(s0 + TILE_B, gal);
            cp16(s0 + 2 * TILE_B, gb);
            cp16(s0 + 3 * TILE_B, gbl);
        }
    };

    // prologue: 3 stages in flight (commit count fixed at 3)
    issue(0, 0); CP_COMMIT();
    if (numIt > 1) issue(1, 1);
    CP_COMMIT();
    if (numIt > 2) issue(2, 2);
    CP_COMMIT();

    for (int it = 0; it < numIt; ++it) {
        CP_WAIT2();
        __syncthreads();
        if (it + 3 < numIt) issue((it + 3) & 3, it + 3);
        CP_COMMIT();

        char* st = sm + (it & 3) * STAGE_B;
        const uint32_t bAh = smem_u32(st);
        const uint32_t bAl = bAh + TILE_B;
        const uint32_t bBh = bAh + 2 * TILE_B;
        const uint32_t bBl = bAh + 3 * TILE_B;

#pragma unroll
        for (int ks = 0; ks < 2; ks++) {
            uint32_t ah[4][4], al[4][4], bh[4][2], bl[4][2];
            const int arow = wm * 64 + (lane & 15);
            const int ac = ks * 2 + (lane >> 4);
            const int brow = wn * 32 + (lane & 7);
            const int bc = ks * 2 + ((lane >> 3) & 1);
#pragma unroll
            for (int mf = 0; mf < 4; mf++) {
                uint32_t o = tswz(arow + mf * 16, ac);
                ldsm4(ah[mf], bAh + o);
                ldsm4(al[mf], bAl + o);
            }
#pragma unroll
            for (int nf = 0; nf < 4; nf++) {
                uint32_t o = tswz(brow + nf * 8, bc);
                ldsm2(bh[nf], bBh + o);
                ldsm2(bl[nf], bBl + o);
            }
#pragma unroll
            for (int mf = 0; mf < 4; mf++)
#pragma unroll
                for (int nf = 0; nf < 4; nf++) {
                    mma_bf16(acc[mf][nf], ah[mf], bh[nf]);
                    mma_bf16(acc[mf][nf], ah[mf], bl[nf]);
                    mma_bf16(acc[mf][nf], al[mf], bh[nf]);
                }
        }
        __syncthreads();
    }
}

// ---- epilogue helpers ----
__device__ __forceinline__ void store_bf(
    float acc[4][4][4], __nv_bfloat16* Ch, __nv_bfloat16* Cl,
    int m0, int n0, int ldC, float alpha, bool ct)
{
    const int lane = threadIdx.x & 31;
    const int wid = threadIdx.x >> 5;
    const int wm = wid >> 2, wn = wid & 3;
    const int g = lane >> 2, t2 = (lane & 3) * 2;
#pragma unroll
    for (int mf = 0; mf < 4; mf++)
#pragma unroll
        for (int nf = 0; nf < 4; nf++) {
            const float* a = acc[mf][nf];
            const int r0 = m0 + wm * 64 + mf * 16 + g;
            const int c0 = n0 + wn * 32 + nf * 8 + t2;
#pragma unroll
            for (int h = 0; h < 2; h++) {
                const int r = r0 + h * 8;
                float v0 = a[h * 2 + 0] * alpha;
                float v1 = a[h * 2 + 1] * alpha;
                __nv_bfloat16 h0 = __float2bfloat16(v0);
                __nv_bfloat16 h1 = __float2bfloat16(v1);
                __nv_bfloat16 l0 = __float2bfloat16(v0 - __bfloat162float(h0));
                __nv_bfloat16 l1 = __float2bfloat16(v1 - __bfloat162float(h1));
                if (ct) {
                    Ch[(size_t)c0 * ldC + r] = h0;
                    Ch[(size_t)(c0 + 1) * ldC + r] = h1;
                    Cl[(size_t)c0 * ldC + r] = l0;
                    Cl[(size_t)(c0 + 1) * ldC + r] = l1;
                } else {
                    *(__nv_bfloat162*)(Ch + (size_t)r * ldC + c0) = __nv_bfloat162(h0, h1);
                    *(__nv_bfloat162*)(Cl + (size_t)r * ldC + c0) = __nv_bfloat162(l0, l1);
                }
            }
        }
}
__device__ __forceinline__ void store_f32(
    float acc[4][4][4], float* Cf, int m0, int n0, int ldC, float alpha)
{
    const int lane = threadIdx.x & 31;
    const int wid = threadIdx.x >> 5;
    const int wm = wid >> 2, wn = wid & 3;
    const int g = lane >> 2, t2 = (lane & 3) * 2;
#pragma unroll
    for (int mf = 0; mf < 4; mf++)
#pragma unroll
        for (int nf = 0; nf < 4; nf++) {
            const float* a = acc[mf][nf];
            const int r0 = m0 + wm * 64 + mf * 16 + g;
            const int c0 = n0 + wn * 32 + nf * 8 + t2;
#pragma unroll
            for (int h = 0; h < 2; h++) {
                const int r = r0 + h * 8;
                *(float2*)(Cf + (size_t)r * ldC + c0) =
                    make_float2(a[h * 2] * alpha, a[h * 2 + 1] * alpha);
            }
        }
}

// ---------------------------------------------------------------------------
// Generic GEMM kernel (S / T / out paths).
//   CSKIP: skip tiles strictly above diagonal;  CKLIM: K limited to m0+128
//   OBF: bf16 hi/lo out, else f32;  REVY: reverse y (big-K CTAs first)
// ---------------------------------------------------------------------------
template <bool CSKIP, bool CKLIM, bool OBF, bool REVY>
__global__ void __launch_bounds__(256, 1)
mma_gemm(const __nv_bfloat16* __restrict__ Ah, const __nv_bfloat16* __restrict__ Al,
         const __nv_bfloat16* __restrict__ Bh, const __nv_bfloat16* __restrict__ Bl,
         float* __restrict__ Cf, __nv_bfloat16* __restrict__ Ch,
         __nv_bfloat16* __restrict__ Cl,
         int K, int ldA, int ldB, int ldC, float alpha,
         long long sA, long long sB, long long sC)
{
    const int by = REVY ? (gridDim.y - 1 - blockIdx.y) : blockIdx.y;
    const int m0 = by * 128;
    const int n0 = blockIdx.x * 128;
    if (CSKIP && n0 > m0 + 127) return;

    Ah += (size_t)blockIdx.z * sA;  Al += (size_t)blockIdx.z * sA;
    Bh += (size_t)blockIdx.z * sB;  Bl += (size_t)blockIdx.z * sB;
    if (OBF) { Ch += (size_t)blockIdx.z * sC; Cl += (size_t)blockIdx.z * sC; }
    else     { Cf += (size_t)blockIdx.z * sC; }

    int kEnd = K;
    if (CKLIM) { int l = m0 + 128; kEnd = l < K ? l : K; }

    extern __shared__ char sm[];
    float acc[4][4][4] = {};
    gemm_core(Ah, Al, Bh, Bl, m0, n0, ldA, ldB, kEnd >> 5, sm, acc);

    if (OBF) store_bf(acc, Ch, Cl, m0, n0, ldC, alpha, false);
    else     store_f32(acc, Cf, m0, n0, ldC, alpha);
}

// ---------------------------------------------------------------------------
// Merged Q/K/Vd projection: A = X for all, z selects B and destination.
//   z=0: Q = X@Wq -> [B*N, 256];  z=1: K;  z=2: VdT = (X@Wvd)^T (transposed)
// ---------------------------------------------------------------------------
__global__ void __launch_bounds__(256, 1)
mma_gemm_qkv(const __nv_bfloat16* __restrict__ Xh, const __nv_bfloat16* __restrict__ Xl,
             const __nv_bfloat16* __restrict__ Bqh, const __nv_bfloat16* __restrict__ Bql,
             const __nv_bfloat16* __restrict__ Bkh, const __nv_bfloat16* __restrict__ Bkl,
             const __nv_bfloat16* __restrict__ Bvh, const __nv_bfloat16* __restrict__ Bvl,
             __nv_bfloat16* __restrict__ Qh, __nv_bfloat16* __restrict__ Ql,
             __nv_bfloat16* __restrict__ Kh, __nv_bfloat16* __restrict__ Kl,
             __nv_bfloat16* __restrict__ Vh, __nv_bfloat16* __restrict__ Vl)
{
    const int m0 = blockIdx.y * 128;
    const int n0 = blockIdx.x * 128;
    const int z = blockIdx.z;

    const __nv_bfloat16* Bh = (z == 0) ? Bqh : (z == 1) ? Bkh : Bvh;
    const __nv_bfloat16* Bl = (z == 0) ? Bql : (z == 1) ? Bkl : Bvl;

    extern __shared__ char sm[];
    float acc[4][4][4] = {};
    gemm_core(Xh, Xl, Bh, Bl, m0, n0, EE, EE, EE >> 5, sm, acc);

    if (z == 0)      store_bf(acc, Qh, Ql, m0, n0, DD, 1.0f, false);
    else if (z == 1) store_bf(acc, Kh, Kl, m0, n0, DD, 1.0f, false);
    else             store_bf(acc, Vh, Vl, m0, n0, BB * NN, 1.0f, true);
}

// ---------------------------------------------------------------------------
// f32 -> bf16 hi/lo split (elementwise, float4)
// ---------------------------------------------------------------------------
__global__ void __launch_bounds__(256)
split_f32(const float* __restrict__ s, __nv_bfloat16* __restrict__ hp,
          __nv_bfloat16* __restrict__ lp, int n4)
{
    int i = blockIdx.x * 256 + threadIdx.x;
    if (i >= n4) return;
    float4 v = ((const float4*)s)[i];
    __nv_bfloat16 h0 = __float2bfloat16(v.x), h1 = __float2bfloat16(v.y);
    __nv_bfloat16 h2 = __float2bfloat16(v.z), h3 = __float2bfloat16(v.w);
    __nv_bfloat16 l0 = __float2bfloat16(v.x - __bfloat162float(h0));
    __nv_bfloat16 l1 = __float2bfloat16(v.y - __bfloat162float(h1));
    __nv_bfloat16 l2 = __float2bfloat16(v.z - __bfloat162float(h2));
    __nv_bfloat16 l3 = __float2bfloat16(v.w - __bfloat162float(h3));
    ((__nv_bfloat162*)hp)[i * 2 + 0] = __nv_bfloat162(h0, h1);
    ((__nv_bfloat162*)hp)[i * 2 + 1] = __nv_bfloat162(h2, h3);
    ((__nv_bfloat162*)lp)[i * 2 + 0] = __nv_bfloat162(l0, l1);
    ((__nv_bfloat162*)lp)[i * 2 + 1] = __nv_bfloat162(l2, l3);
}

// ---------------------------------------------------------------------------
// transpose + split: src [M,N] f32 -> dstT hi/lo [N,M] bf16
// ---------------------------------------------------------------------------
__global__ void __launch_bounds__(256)
transpose_split(const float* __restrict__ src, __nv_bfloat16* __restrict__ dh,
                __nv_bfloat16* __restrict__ dl, int M, int N)
{
    __shared__ float t[32][33];
    const int bx = blockIdx.x * 32, by = blockIdx.y * 32;
    const int x = threadIdx.x, y = threadIdx.y;
#pragma unroll
    for (int i = 0; i < 32; i += 8)
        t[y + i][x] = src[(size_t)(by + y + i) * N + bx + x];
    __syncthreads();
#pragma unroll
    for (int i = 0; i < 32; i += 8) {
        float v = t[x][y + i];
        __nv_bfloat16 h = __float2bfloat16(v);
        dh[(size_t)(bx + y + i) * M + by + x] = h;
        dl[(size_t)(bx + y + i) * M + by + x] =
            __float2bfloat16(v - __bfloat162float(h));
    }
}

// ---------------------------------------------------------------------------
// Row softmax (lower triangle), reference quirk, writes hi/lo bf16 probs.
// Zero-fills up to the 128 boundary so the T GEMM's K-limit is exact.
// ---------------------------------------------------------------------------
__global__ void __launch_bounds__(256)
softmax_rows(const float* __restrict__ Sm, __nv_bfloat16* __restrict__ Ph,
             __nv_bfloat16* __restrict__ Pl)
{
    const int row = blockIdx.x;
    const int q = row & (NN - 1);
    const int kup = ((q >> 7) + 1) << 7;
    const float* S = Sm + (size_t)row * NN;
    __nv_bfloat16* ph = Ph + (size_t)row * NN;
    __nv_bfloat16* pl = Pl + (size_t)row * NN;

    __shared__ float buf[NN];
    __shared__ float red[256];
    const int tid = threadIdx.x;

    float lmax = -INFINITY;
    for (int k = tid; k <= q; k += 256) {
        float s = S[k];
        float v = (s != 0.0f) ? s : NEG_FILL;
        buf[k] = v;
        lmax = fmaxf(lmax, v);
    }
    red[tid] = lmax;
    __syncthreads();
#pragma unroll
    for (int s = 128; s > 0; s >>= 1) {
        if (tid < s) red[tid] = fmaxf(red[tid], red[tid + s]);
        __syncthreads();
    }
    const float mx = red[0];
    __syncthreads();

    float lsum = 0.0f;
    for (int k = tid; k <= q; k += 256) {
        float e = expf(buf[k] - mx);
        buf[k] = e;
        lsum += e;
    }
    red[tid] = lsum;
    __syncthreads();
#pragma unroll
    for (int s = 128; s > 0; s >>= 1) {
        if (tid < s) red[tid] += red[tid + s];
        __syncthreads();
    }
    const float inv = 1.0f / red[0];
    __syncthreads();

    for (int k = tid; k < kup; k += 256) {
        float p = (k <= q) ? buf[k] * inv : 0.0f;
        __nv_bfloat16 h = __float2bfloat16(p);
        ph[k] = h;
        pl[k] = __float2bfloat16(p - __bfloat162float(h));
    }
}

// ---------------------------------------------------------------------------
extern "C" void kernel_launch(void* const* d_in, const int* in_sizes, int n_in,
                              void* d_out, int out_size)
{
    (void)in_sizes; (void)n_in; (void)out_size;
    const float* X   = (const float*)d_in[0];
    const float* Wq  = (const float*)d_in[1];
    const float* Wk  = (const float*)d_in[2];
    const float* Wvd = (const float*)d_in[3];
    const float* Wvu = (const float*)d_in[4];
    float* out = (float*)d_out;

    __nv_bfloat16 *pXh, *pXl, *pQh, *pQl, *pKh, *pKl, *pVdTh, *pVdTl, *pTh, *pTl;
    __nv_bfloat16 *pWqTh, *pWqTl, *pWkTh, *pWkTl, *pWvdTh, *pWvdTl, *pWvuTh, *pWvuTl;
    __nv_bfloat16 *pPh, *pPl;
    float* pS;
    cudaGetSymbolAddress((void**)&pXh, g_Xh);     cudaGetSymbolAddress((void**)&pXl, g_Xl);
    cudaGetSymbolAddress((void**)&pQh, g_Qh);     cudaGetSymbolAddress((void**)&pQl, g_Ql);
    cudaGetSymbolAddress((void**)&pKh, g_Kh);     cudaGetSymbolAddress((void**)&pKl, g_Kl);
    cudaGetSymbolAddress((void**)&pVdTh, g_VdTh); cudaGetSymbolAddress((void**)&pVdTl, g_VdTl);
    cudaGetSymbolAddress((void**)&pTh, g_Th);     cudaGetSymbolAddress((void**)&pTl, g_Tl);
    cudaGetSymbolAddress((void**)&pWqTh, g_WqTh); cudaGetSymbolAddress((void**)&pWqTl, g_WqTl);
    cudaGetSymbolAddress((void**)&pWkTh, g_WkTh); cudaGetSymbolAddress((void**)&pWkTl, g_WkTl);
    cudaGetSymbolAddress((void**)&pWvdTh, g_WvdTh); cudaGetSymbolAddress((void**)&pWvdTl, g_WvdTl);
    cudaGetSymbolAddress((void**)&pWvuTh, g_WvuTh); cudaGetSymbolAddress((void**)&pWvuTl, g_WvuTl);
    cudaGetSymbolAddress((void**)&pPh, g_Ph);     cudaGetSymbolAddress((void**)&pPl, g_Pl);
    cudaGetSymbolAddress((void**)&pS, g_S);

    cudaFuncSetAttribute(mma_gemm_qkv,
                         cudaFuncAttributeMaxDynamicSharedMemorySize, SMEM_B);
    cudaFuncSetAttribute(mma_gemm<true,  false, false, false>,
                         cudaFuncAttributeMaxDynamicSharedMemorySize, SMEM_B);
    cudaFuncSetAttribute(mma_gemm<false, true,  true,  true>,
                         cudaFuncAttributeMaxDynamicSharedMemorySize, SMEM_B);
    cudaFuncSetAttribute(mma_gemm<false, false, false, false>,
                         cudaFuncAttributeMaxDynamicSharedMemorySize, SMEM_B);

    const dim3 blk(256);
    const dim3 tblk(32, 8);

    // ---- prep: split X; transpose+split all weights ----
    split_f32<<<(BB * NN * EE / 4 + 255) / 256, blk>>>(X, pXh, pXl, BB * NN * EE / 4);
    transpose_split<<<dim3(DD / 32, EE / 32), tblk>>>(Wq,  pWqTh,  pWqTl,  EE, DD);
    transpose_split<<<dim3(DD / 32, EE / 32), tblk>>>(Wk,  pWkTh,  pWkTl,  EE, DD);
    transpose_split<<<dim3(DD / 32, EE / 32), tblk>>>(Wvd, pWvdTh, pWvdTl, EE, DD);
    transpose_split<<<dim3(EE / 32, DD / 32), tblk>>>(Wvu, pWvuTh, pWvuTl, DD, EE);

    // 1) merged Q/K/VdT projection: one launch, z selects target
    mma_gemm_qkv<<<dim3(2, 128, 3), blk, SMEM_B>>>(
        pXh, pXl, pWqTh, pWqTl, pWkTh, pWkTl, pWvdTh, pWvdTl,
        pQh, pQl, pKh, pKl, pVdTh, pVdTl);

    // 2) S = Q @ K^T / 16 (causal tile skip), f32 out, per batch
    mma_gemm<true, false, false, false><<<dim3(32, 32, BB), blk, SMEM_B>>>(
        pQh, pQl, pKh, pKl, pS, nullptr, nullptr,
        DD, DD, DD, NN, 1.0f / 16.0f,
        (long long)NN * DD, (long long)NN * DD, (long long)NN * NN);

    // 3) softmax -> Ph/Pl
    softmax_rows<<<BB * NN, 256>>>(pS, pPh, pPl);

    // 4) T = P @ Vd (causal K-limit, big-K CTAs first), bf16 hi/lo out
    mma_gemm<false, true, true, true><<<dim3(2, 32, BB), blk, SMEM_B>>>(
        pPh, pPl, pVdTh, pVdTl, nullptr, pTh, pTl,
        NN, NN, BB * NN, DD, 1.0f,
        (long long)NN * NN, (long long)NN, (long long)NN * DD);

    // 5) out = T @ Wvu   M=16384 N=1024 K=256, f32 out
    mma_gemm<false, false, false, false><<<dim3(8, 128, 1), blk, SMEM_B>>>(
        pTh, pTl, pWvuTh, pWvuTl, out, nullptr, nullptr,
        DD, DD, DD, EE, 1.0f, 0, 0, 0);
}

// round 8
// speedup vs baseline: 5.4495x; 1.0874x over previous
#include <cuda_runtime.h>
#include <cuda_bf16.h>
#include <math.h>
#include <stdint.h>

// Problem shape (fixed)
#define BB 4
#define NN 4096
#define EE 1024
#define DD 256
#define NEG_FILL (-3.402823466385288598e+38f)

// ---------------- scratch (static device globals; no allocs) ----------------
__device__ __nv_bfloat16 g_Xh  [(size_t)BB * NN * EE];
__device__ __nv_bfloat16 g_Xl  [(size_t)BB * NN * EE];
__device__ __nv_bfloat16 g_Qh  [(size_t)BB * NN * DD];
__device__ __nv_bfloat16 g_Ql  [(size_t)BB * NN * DD];
__device__ __nv_bfloat16 g_Kh  [(size_t)BB * NN * DD];
__device__ __nv_bfloat16 g_Kl  [(size_t)BB * NN * DD];
__device__ __nv_bfloat16 g_VdTh[(size_t)DD * BB * NN];  // (X@Wvd)^T  [256, B*N]
__device__ __nv_bfloat16 g_VdTl[(size_t)DD * BB * NN];
__device__ __nv_bfloat16 g_Th  [(size_t)BB * NN * DD];  // T = softmax(S)@Vd
__device__ __nv_bfloat16 g_Tl  [(size_t)BB * NN * DD];
__device__ float         g_Tp0 [(size_t)BB * NN * DD];  // T split-K partials (f32)
__device__ float         g_Tp1 [(size_t)BB * NN * DD];
__device__ float         g_rsum[(size_t)BB * NN];       // unnormalized row sums
__device__ __nv_bfloat16 g_WqTh[(size_t)DD * EE];
__device__ __nv_bfloat16 g_WqTl[(size_t)DD * EE];
__device__ __nv_bfloat16 g_WkTh[(size_t)DD * EE];
__device__ __nv_bfloat16 g_WkTl[(size_t)DD * EE];
__device__ __nv_bfloat16 g_WvdTh[(size_t)DD * EE];
__device__ __nv_bfloat16 g_WvdTl[(size_t)DD * EE];
__device__ __nv_bfloat16 g_WvuTh[(size_t)EE * DD];
__device__ __nv_bfloat16 g_WvuTl[(size_t)EE * DD];
__device__ __nv_bfloat16 g_Ph  [(size_t)BB * NN * NN];  // unnormalized exp(S) hi
__device__ __nv_bfloat16 g_Pl  [(size_t)BB * NN * NN];  // unnormalized exp(S) lo

// ---------------- helpers ----------------
__device__ __forceinline__ uint32_t smem_u32(const void* p) {
    uint32_t a;
    asm("{ .reg .u64 t; cvta.to.shared.u64 t, %1; cvt.u32.u64 %0, t; }"
        : "=r"(a) : "l"(p));
    return a;
}
__device__ __forceinline__ void ldsm4(uint32_t* r, uint32_t a) {
    asm volatile("ldmatrix.sync.aligned.m8n8.x4.shared.b16 {%0,%1,%2,%3}, [%4];"
                 : "=r"(r[0]), "=r"(r[1]), "=r"(r[2]), "=r"(r[3]) : "r"(a));
}
__device__ __forceinline__ void ldsm2(uint32_t* r, uint32_t a) {
    asm volatile("ldmatrix.sync.aligned.m8n8.x2.shared.b16 {%0,%1}, [%2];"
                 : "=r"(r[0]), "=r"(r[1]) : "r"(a));
}
__device__ __forceinline__ void mma_bf16(float* d, const uint32_t* a, const uint32_t* b) {
    asm volatile(
        "mma.sync.aligned.m16n8k16.row.col.f32.bf16.bf16.f32 "
        "{%0,%1,%2,%3}, {%4,%5,%6,%7}, {%8,%9}, {%0,%1,%2,%3};"
        : "+f"(d[0]), "+f"(d[1]), "+f"(d[2]), "+f"(d[3])
        : "r"(a[0]), "r"(a[1]), "r"(a[2]), "r"(a[3]), "r"(b[0]), "r"(b[1]));
}
__device__ __forceinline__ void cp16(uint32_t saddr, const void* gaddr) {
    asm volatile("cp.async.cg.shared.global [%0], [%1], 16;"
                 :: "r"(saddr), "l"(gaddr) : "memory");
}
#define CP_COMMIT() asm volatile("cp.async.commit_group;" ::: "memory")
#define CP_WAIT2()  asm volatile("cp.async.wait_group 2;" ::: "memory")

// swizzled offset within a 128x32 bf16 tile (rows of 64B, 4x16B chunks)
__device__ __forceinline__ uint32_t tswz(int row, int chunk) {
    return (uint32_t)(row * 64 + ((chunk ^ ((row >> 1) & 3)) << 4));
}

#define TILE_B   8192           // 128*32 bf16
#define STAGE_B  (4 * TILE_B)   // Ah, Al, Bh, Bl
#define NSTAGE   4
#define SMEM_B   (NSTAGE * STAGE_B)

// ---------------------------------------------------------------------------
// Mainloop core: 128x128x(32*numIt) split-3 bf16 MMA, 4-stage cp.async.
// ---------------------------------------------------------------------------
__device__ __forceinline__ void gemm_core(
    const __nv_bfloat16* __restrict__ Ah, const __nv_bfloat16* __restrict__ Al,
    const __nv_bfloat16* __restrict__ Bh, const __nv_bfloat16* __restrict__ Bl,
    int m0, int n0, int ldA, int ldB, int numIt, char* sm,
    float acc[4][4][4])
{
    const int tid = threadIdx.x;
    const int lane = tid & 31;
    const int wid = tid >> 5;
    const int wm = wid >> 2;        // 0..1
    const int wn = wid & 3;         // 0..3

    auto issue = [&](int stage, int it) {
        char* st = sm + stage * STAGE_B;
        const int k0 = it << 5;
#pragma unroll
        for (int j = 0; j < 2; j++) {
            int idx = tid + j * 256;        // 0..511
            int row = idx >> 2, c = idx & 3;
            uint32_t off = tswz(row, c);
            uint32_t s0 = smem_u32(st) + off;
            const __nv_bfloat16* ga  = Ah + (size_t)(m0 + row) * ldA + k0 + c * 8;
            const __nv_bfloat16* gal = Al + (size_t)(m0 + row) * ldA + k0 + c * 8;
            const __nv_bfloat16* gb  = Bh + (size_t)(n0 + row) * ldB + k0 + c * 8;
            const __nv_bfloat16* gbl = Bl + (size_t)(n0 + row) * ldB + k0 + c * 8;
            cp16(s0, ga);
            cp16(s0 + TILE_B, gal);
            cp16(s0 + 2 * TILE_B, gb);
            cp16(s0 + 3 * TILE_B, gbl);
        }
    };

    issue(0, 0); CP_COMMIT();
    if (numIt > 1) issue(1, 1);
    CP_COMMIT();
    if (numIt > 2) issue(2, 2);
    CP_COMMIT();

    for (int it = 0; it < numIt; ++it) {
        CP_WAIT2();
        __syncthreads();
        if (it + 3 < numIt) issue((it + 3) & 3, it + 3);
        CP_COMMIT();

        char* st = sm + (it & 3) * STAGE_B;
        const uint32_t bAh = smem_u32(st);
        const uint32_t bAl = bAh + TILE_B;
        const uint32_t bBh = bAh + 2 * TILE_B;
        const uint32_t bBl = bAh + 3 * TILE_B;

#pragma unroll
        for (int ks = 0; ks < 2; ks++) {
            uint32_t ah[4][4], al[4][4], bh[4][2], bl[4][2];
            const int arow = wm * 64 + (lane & 15);
            const int ac = ks * 2 + (lane >> 4);
            const int brow = wn * 32 + (lane & 7);
            const int bc = ks * 2 + ((lane >> 3) & 1);
#pragma unroll
            for (int mf = 0; mf < 4; mf++) {
                uint32_t o = tswz(arow + mf * 16, ac);
                ldsm4(ah[mf], bAh + o);
                ldsm4(al[mf], bAl + o);
            }
#pragma unroll
            for (int nf = 0; nf < 4; nf++) {
                uint32_t o = tswz(brow + nf * 8, bc);
                ldsm2(bh[nf], bBh + o);
                ldsm2(bl[nf], bBl + o);
            }
#pragma unroll
            for (int mf = 0; mf < 4; mf++)
#pragma unroll
                for (int nf = 0; nf < 4; nf++) {
                    mma_bf16(acc[mf][nf], ah[mf], bh[nf]);
                    mma_bf16(acc[mf][nf], ah[mf], bl[nf]);
                    mma_bf16(acc[mf][nf], al[mf], bh[nf]);
                }
        }
        __syncthreads();
    }
}

// ---- epilogue helpers ----
__device__ __forceinline__ void store_bf(
    float acc[4][4][4], __nv_bfloat16* Ch, __nv_bfloat16* Cl,
    int m0, int n0, int ldC, bool ct)
{
    const int lane = threadIdx.x & 31;
    const int wid = threadIdx.x >> 5;
    const int wm = wid >> 2, wn = wid & 3;
    const int g = lane >> 2, t2 = (lane & 3) * 2;
#pragma unroll
    for (int mf = 0; mf < 4; mf++)
#pragma unroll
        for (int nf = 0; nf < 4; nf++) {
            const float* a = acc[mf][nf];
            const int r0 = m0 + wm * 64 + mf * 16 + g;
            const int c0 = n0 + wn * 32 + nf * 8 + t2;
#pragma unroll
            for (int h = 0; h < 2; h++) {
                const int r = r0 + h * 8;
                float v0 = a[h * 2 + 0];
                float v1 = a[h * 2 + 1];
                __nv_bfloat16 h0 = __float2bfloat16(v0);
                __nv_bfloat16 h1 = __float2bfloat16(v1);
                __nv_bfloat16 l0 = __float2bfloat16(v0 - __bfloat162float(h0));
                __nv_bfloat16 l1 = __float2bfloat16(v1 - __bfloat162float(h1));
                if (ct) {
                    Ch[(size_t)c0 * ldC + r] = h0;
                    Ch[(size_t)(c0 + 1) * ldC + r] = h1;
                    Cl[(size_t)c0 * ldC + r] = l0;
                    Cl[(size_t)(c0 + 1) * ldC + r] = l1;
                } else {
                    *(__nv_bfloat162*)(Ch + (size_t)r * ldC + c0) = __nv_bfloat162(h0, h1);
                    *(__nv_bfloat162*)(Cl + (size_t)r * ldC + c0) = __nv_bfloat162(l0, l1);
                }
            }
        }
}
__device__ __forceinline__ void store_f32(
    float acc[4][4][4], float* Cf, int m0, int n0, int ldC)
{
    const int lane = threadIdx.x & 31;
    const int wid = threadIdx.x >> 5;
    const int wm = wid >> 2, wn = wid & 3;
    const int g = lane >> 2, t2 = (lane & 3) * 2;
#pragma unroll
    for (int mf = 0; mf < 4; mf++)
#pragma unroll
        for (int nf = 0; nf < 4; nf++) {
            const float* a = acc[mf][nf];
            const int r0 = m0 + wm * 64 + mf * 16 + g;
            const int c0 = n0 + wn * 32 + nf * 8 + t2;
#pragma unroll
            for (int h = 0; h < 2; h++) {
                const int r = r0 + h * 8;
                *(float2*)(Cf + (size_t)r * ldC + c0) =
                    make_float2(a[h * 2], a[h * 2 + 1]);
            }
        }
}

// ---------------------------------------------------------------------------
// Merged Q/K/Vd projection: A = X for all, z selects B and destination.
// ---------------------------------------------------------------------------
__global__ void __launch_bounds__(256, 1)
mma_gemm_qkv(const __nv_bfloat16* __restrict__ Xh, const __nv_bfloat16* __restrict__ Xl,
             const __nv_bfloat16* __restrict__ Bqh, const __nv_bfloat16* __restrict__ Bql,
             const __nv_bfloat16* __restrict__ Bkh, const __nv_bfloat16* __restrict__ Bkl,
             const __nv_bfloat16* __restrict__ Bvh, const __nv_bfloat16* __restrict__ Bvl,
             __nv_bfloat16* __restrict__ Qh, __nv_bfloat16* __restrict__ Ql,
             __nv_bfloat16* __restrict__ Kh, __nv_bfloat16* __restrict__ Kl,
             __nv_bfloat16* __restrict__ Vh, __nv_bfloat16* __restrict__ Vl)
{
    const int m0 = blockIdx.y * 128;
    const int n0 = blockIdx.x * 128;
    const int z = blockIdx.z;

    const __nv_bfloat16* Bh = (z == 0) ? Bqh : (z == 1) ? Bkh : Bvh;
    const __nv_bfloat16* Bl = (z == 0) ? Bql : (z == 1) ? Bkl : Bvl;

    extern __shared__ char sm[];
    float acc[4][4][4] = {};
    gemm_core(Xh, Xl, Bh, Bl, m0, n0, EE, EE, EE >> 5, sm, acc);

    if (z == 0)      store_bf(acc, Qh, Ql, m0, n0, DD, false);
    else if (z == 1) store_bf(acc, Kh, Kl, m0, n0, DD, false);
    else             store_bf(acc, Vh, Vl, m0, n0, BB * NN, true);
}

// ---------------------------------------------------------------------------
// S GEMM with fused quirk + exp + row-sum epilogue.
//   s = (Q.K)/16;  e = (masked) ? 0 : expf(s!=0 ? s : NEG_FILL)
//   Writes unnormalized probs as bf16 hi/lo; rowsum += e via atomics.
// Max-subtraction omitted: |s| <~ 16 so exp and row sums sit far inside f32.
// ---------------------------------------------------------------------------
__global__ void __launch_bounds__(256, 1)
mma_gemm_sexp(const __nv_bfloat16* __restrict__ Qh, const __nv_bfloat16* __restrict__ Ql,
              const __nv_bfloat16* __restrict__ Kh, const __nv_bfloat16* __restrict__ Kl,
              __nv_bfloat16* __restrict__ Ph, __nv_bfloat16* __restrict__ Pl,
              float* __restrict__ rsum)
{
    const int m0 = blockIdx.y * 128;
    const int n0 = blockIdx.x * 128;
    if (n0 > m0 + 127) return;          // fully masked tile
    const int z = blockIdx.z;

    const __nv_bfloat16* Ah = Qh + (size_t)z * NN * DD;
    const __nv_bfloat16* Al = Ql + (size_t)z * NN * DD;
    const __nv_bfloat16* Bh = Kh + (size_t)z * NN * DD;
    const __nv_bfloat16* Bl = Kl + (size_t)z * NN * DD;
    Ph += (size_t)z * NN * NN;
    Pl += (size_t)z * NN * NN;
    rsum += (size_t)z * NN;

    extern __shared__ char sm[];
    float acc[4][4][4] = {};
    gemm_core(Ah, Al, Bh, Bl, m0, n0, DD, DD, DD >> 5, sm, acc);

    const bool diag = (m0 == n0);
    const int lane = threadIdx.x & 31;
    const int wid = threadIdx.x >> 5;
    const int wm = wid >> 2, wn = wid & 3;
    const int g = lane >> 2, t2 = (lane & 3) * 2;
    const float alpha = 1.0f / 16.0f;

#pragma unroll
    for (int mf = 0; mf < 4; mf++) {
#pragma unroll
        for (int h = 0; h < 2; h++) {
            const int rl = wm * 64 + mf * 16 + g + h * 8;   // row within tile
            const int row = m0 + rl;
            float rs = 0.0f;
#pragma unroll
            for (int nf = 0; nf < 4; nf++) {
                const int cl = wn * 32 + nf * 8 + t2;       // col within tile
                float s0 = acc[mf][nf][h * 2 + 0] * alpha;
                float s1 = acc[mf][nf][h * 2 + 1] * alpha;
                float e0 = (diag && cl > rl) ? 0.0f
                           : expf((s0 != 0.0f) ? s0 : NEG_FILL);
                float e1 = (diag && cl + 1 > rl) ? 0.0f
                           : expf((s1 != 0.0f) ? s1 : NEG_FILL);
                rs += e0 + e1;
                __nv_bfloat16 h0 = __float2bfloat16(e0);
                __nv_bfloat16 h1 = __float2bfloat16(e1);
                __nv_bfloat16 l0 = __float2bfloat16(e0 - __bfloat162float(h0));
                __nv_bfloat16 l1 = __float2bfloat16(e1 - __bfloat162float(h1));
                *(__nv_bfloat162*)(Ph + (size_t)row * NN + n0 + cl) = __nv_bfloat162(h0, h1);
                *(__nv_bfloat162*)(Pl + (size_t)row * NN + n0 + cl) = __nv_bfloat162(l0, l1);
            }
            rs += __shfl_xor_sync(0xffffffff, rs, 1);
            rs += __shfl_xor_sync(0xffffffff, rs, 2);
            if ((lane & 3) == 0) atomicAdd(&rsum[row], rs);
        }
    }
}

// ---------------------------------------------------------------------------
// T GEMM, split-K in two halves -> f32 partials. Reverse-y: big-K CTAs first.
// ---------------------------------------------------------------------------
__global__ void __launch_bounds__(256, 1)
mma_gemm_tsplit(const __nv_bfloat16* __restrict__ Ph, const __nv_bfloat16* __restrict__ Pl,
                const __nv_bfloat16* __restrict__ Vh, const __nv_bfloat16* __restrict__ Vl,
                float* __restrict__ Tp0, float* __restrict__ Tp1)
{
    const int by = gridDim.y - 1 - blockIdx.y;
    const int m0 = by * 128;
    const int n0 = blockIdx.x * 128;
    const int batch = blockIdx.z >> 1;
    const int half = blockIdx.z & 1;

    const int kEnd = m0 + 128;          // causal K limit (multiple of 128)
    const int kh = kEnd >> 1;           // multiple of 64 (so multiple of 32)
    const int ks = half ? kh : 0;
    const int ke = half ? kEnd : kh;

    const __nv_bfloat16* Ah = Ph + (size_t)batch * NN * NN + ks;
    const __nv_bfloat16* Al = Pl + (size_t)batch * NN * NN + ks;
    const __nv_bfloat16* Bh = Vh + (size_t)batch * NN + ks;
    const __nv_bfloat16* Bl = Vl + (size_t)batch * NN + ks;
    float* Tp = (half ? Tp1 : Tp0) + (size_t)batch * NN * DD;

    extern __shared__ char sm[];
    float acc[4][4][4] = {};
    gemm_core(Ah, Al, Bh, Bl, m0, n0, NN, BB * NN, (ke - ks) >> 5, sm, acc);
    store_f32(acc, Tp, m0, n0, DD);
}

// ---------------------------------------------------------------------------
// Combine T partials, normalize by row sums, emit bf16 hi/lo.
// ---------------------------------------------------------------------------
__global__ void __launch_bounds__(256)
combine_T(const float* __restrict__ p0, const float* __restrict__ p1,
          const float* __restrict__ rsum,
          __nv_bfloat16* __restrict__ Th, __nv_bfloat16* __restrict__ Tl)
{
    int i = blockIdx.x * 256 + threadIdx.x;          // over (BB*NN*DD)/4
    float4 a = ((const float4*)p0)[i];
    float4 b = ((const float4*)p1)[i];
    const float inv = 1.0f / rsum[i >> 6];           // row = (i*4)/DD
    float v0 = (a.x + b.x) * inv, v1 = (a.y + b.y) * inv;
    float v2 = (a.z + b.z) * inv, v3 = (a.w + b.w) * inv;
    __nv_bfloat16 h0 = __float2bfloat16(v0), h1 = __float2bfloat16(v1);
    __nv_bfloat16 h2 = __float2bfloat16(v2), h3 = __float2bfloat16(v3);
    __nv_bfloat16 l0 = __float2bfloat16(v0 - __bfloat162float(h0));
    __nv_bfloat16 l1 = __float2bfloat16(v1 - __bfloat162float(h1));
    __nv_bfloat16 l2 = __float2bfloat16(v2 - __bfloat162float(h2));
    __nv_bfloat16 l3 = __float2bfloat16(v3 - __bfloat162float(h3));
    ((__nv_bfloat162*)Th)[i * 2 + 0] = __nv_bfloat162(h0, h1);
    ((__nv_bfloat162*)Th)[i * 2 + 1] = __nv_bfloat162(h2, h3);
    ((__nv_bfloat162*)Tl)[i * 2 + 0] = __nv_bfloat162(l0, l1);
    ((__nv_bfloat162*)Tl)[i * 2 + 1] = __nv_bfloat162(l2, l3);
}

// ---------------------------------------------------------------------------
// out = T @ Wvu, f32 out
// ---------------------------------------------------------------------------
__global__ void __launch_bounds__(256, 1)
mma_gemm_out(const __nv_bfloat16* __restrict__ Ah, const __nv_bfloat16* __restrict__ Al,
             const __nv_bfloat16* __restrict__ Bh, const __nv_bfloat16* __restrict__ Bl,
             float* __restrict__ Cf)
{
    const int m0 = blockIdx.y * 128;
    const int n0 = blockIdx.x * 128;
    extern __shared__ char sm[];
    float acc[4][4][4] = {};
    gemm_core(Ah, Al, Bh, Bl, m0, n0, DD, DD, DD >> 5, sm, acc);
    store_f32(acc, Cf, m0, n0, EE);
}

// ---------------------------------------------------------------------------
// f32 -> bf16 hi/lo split (elementwise, float4)
// ---------------------------------------------------------------------------
__global__ void __launch_bounds__(256)
split_f32(const float* __restrict__ s, __nv_bfloat16* __restrict__ hp,
          __nv_bfloat16* __restrict__ lp, int n4)
{
    int i = blockIdx.x * 256 + threadIdx.x;
    if (i >= n4) return;
    float4 v = ((const float4*)s)[i];
    __nv_bfloat16 h0 = __float2bfloat16(v.x), h1 = __float2bfloat16(v.y);
    __nv_bfloat16 h2 = __float2bfloat16(v.z), h3 = __float2bfloat16(v.w);
    __nv_bfloat16 l0 = __float2bfloat16(v.x - __bfloat162float(h0));
    __nv_bfloat16 l1 = __float2bfloat16(v.y - __bfloat162float(h1));
    __nv_bfloat16 l2 = __float2bfloat16(v.z - __bfloat162float(h2));
    __nv_bfloat16 l3 = __float2bfloat16(v.w - __bfloat162float(h3));
    ((__nv_bfloat162*)hp)[i * 2 + 0] = __nv_bfloat162(h0, h1);
    ((__nv_bfloat162*)hp)[i * 2 + 1] = __nv_bfloat162(h2, h3);
    ((__nv_bfloat162*)lp)[i * 2 + 0] = __nv_bfloat162(l0, l1);
    ((__nv_bfloat162*)lp)[i * 2 + 1] = __nv_bfloat162(l2, l3);
}

// ---------------------------------------------------------------------------
// transpose + split: src [M,N] f32 -> dstT hi/lo [N,M] bf16
// ---------------------------------------------------------------------------
__global__ void __launch_bounds__(256)
transpose_split(const float* __restrict__ src, __nv_bfloat16* __restrict__ dh,
                __nv_bfloat16* __restrict__ dl, int M, int N)
{
    __shared__ float t[32][33];
    const int bx = blockIdx.x * 32, by = blockIdx.y * 32;
    const int x = threadIdx.x, y = threadIdx.y;
#pragma unroll
    for (int i = 0; i < 32; i += 8)
        t[y + i][x] = src[(size_t)(by + y + i) * N + bx + x];
    __syncthreads();
#pragma unroll
    for (int i = 0; i < 32; i += 8) {
        float v = t[x][y + i];
        __nv_bfloat16 h = __float2bfloat16(v);
        dh[(size_t)(bx + y + i) * M + by + x] = h;
        dl[(size_t)(bx + y + i) * M + by + x] =
            __float2bfloat16(v - __bfloat162float(h));
    }
}

// ---------------------------------------------------------------------------
extern "C" void kernel_launch(void* const* d_in, const int* in_sizes, int n_in,
                              void* d_out, int out_size)
{
    (void)in_sizes; (void)n_in; (void)out_size;
    const float* X   = (const float*)d_in[0];
    const float* Wq  = (const float*)d_in[1];
    const float* Wk  = (const float*)d_in[2];
    const float* Wvd = (const float*)d_in[3];
    const float* Wvu = (const float*)d_in[4];
    float* out = (float*)d_out;

    __nv_bfloat16 *pXh, *pXl, *pQh, *pQl, *pKh, *pKl, *pVdTh, *pVdTl, *pTh, *pTl;
    __nv_bfloat16 *pWqTh, *pWqTl, *pWkTh, *pWkTl, *pWvdTh, *pWvdTl, *pWvuTh, *pWvuTl;
    __nv_bfloat16 *pPh, *pPl;
    float *pTp0, *pTp1, *pRs;
    cudaGetSymbolAddress((void**)&pXh, g_Xh);     cudaGetSymbolAddress((void**)&pXl, g_Xl);
    cudaGetSymbolAddress((void**)&pQh, g_Qh);     cudaGetSymbolAddress((void**)&pQl, g_Ql);
    cudaGetSymbolAddress((void**)&pKh, g_Kh);     cudaGetSymbolAddress((void**)&pKl, g_Kl);
    cudaGetSymbolAddress((void**)&pVdTh, g_VdTh); cudaGetSymbolAddress((void**)&pVdTl, g_VdTl);
    cudaGetSymbolAddress((void**)&pTh, g_Th);     cudaGetSymbolAddress((void**)&pTl, g_Tl);
    cudaGetSymbolAddress((void**)&pTp0, g_Tp0);   cudaGetSymbolAddress((void**)&pTp1, g_Tp1);
    cudaGetSymbolAddress((void**)&pRs, g_rsum);
    cudaGetSymbolAddress((void**)&pWqTh, g_WqTh); cudaGetSymbolAddress((void**)&pWqTl, g_WqTl);
    cudaGetSymbolAddress((void**)&pWkTh, g_WkTh); cudaGetSymbolAddress((void**)&pWkTl, g_WkTl);
    cudaGetSymbolAddress((void**)&pWvdTh, g_WvdTh); cudaGetSymbolAddress((void**)&pWvdTl, g_WvdTl);
    cudaGetSymbolAddress((void**)&pWvuTh, g_WvuTh); cudaGetSymbolAddress((void**)&pWvuTl, g_WvuTl);
    cudaGetSymbolAddress((void**)&pPh, g_Ph);     cudaGetSymbolAddress((void**)&pPl, g_Pl);

    cudaFuncSetAttribute(mma_gemm_qkv,
                         cudaFuncAttributeMaxDynamicSharedMemorySize, SMEM_B);
    cudaFuncSetAttribute(mma_gemm_sexp,
                         cudaFuncAttributeMaxDynamicSharedMemorySize, SMEM_B);
    cudaFuncSetAttribute(mma_gemm_tsplit,
                         cudaFuncAttributeMaxDynamicSharedMemorySize, SMEM_B);
    cudaFuncSetAttribute(mma_gemm_out,
                         cudaFuncAttributeMaxDynamicSharedMemorySize, SMEM_B);

    const dim3 blk(256);
    const dim3 tblk(32, 8);

    // ---- prep: zero row sums; split X; transpose+split weights ----
    cudaMemsetAsync(pRs, 0, (size_t)BB * NN * sizeof(float));
    split_f32<<<(BB * NN * EE / 4 + 255) / 256, blk>>>(X, pXh, pXl, BB * NN * EE / 4);
    transpose_split<<<dim3(DD / 32, EE / 32), tblk>>>(Wq,  pWqTh,  pWqTl,  EE, DD);
    transpose_split<<<dim3(DD / 32, EE / 32), tblk>>>(Wk,  pWkTh,  pWkTl,  EE, DD);
    transpose_split<<<dim3(DD / 32, EE / 32), tblk>>>(Wvd, pWvdTh, pWvdTl, EE, DD);
    transpose_split<<<dim3(EE / 32, DD / 32), tblk>>>(Wvu, pWvuTh, pWvuTl, DD, EE);

    // 1) merged Q/K/VdT projection
    mma_gemm_qkv<<<dim3(2, 128, 3), blk, SMEM_B>>>(
        pXh, pXl, pWqTh, pWqTl, pWkTh, pWkTl, pWvdTh, pWvdTl,
        pQh, pQl, pKh, pKl, pVdTh, pVdTl);

    // 2) S = Q@K^T/16 with fused quirk+exp+rowsum epilogue (softmax deleted)
    mma_gemm_sexp<<<dim3(32, 32, BB), blk, SMEM_B>>>(
        pQh, pQl, pKh, pKl, pPh, pPl, pRs);

    // 3) T partials = exp(S) @ Vd, split-K halves, big-K CTAs first
    mma_gemm_tsplit<<<dim3(2, 32, BB * 2), blk, SMEM_B>>>(
        pPh, pPl, pVdTh, pVdTl, pTp0, pTp1);

    // 4) combine + normalize -> Th/Tl
    combine_T<<<(BB * NN * DD / 4) / 256, blk>>>(pTp0, pTp1, pRs, pTh, pTl);

    // 5) out = T @ Wvu
    mma_gemm_out<<<dim3(8, 128, 1), blk, SMEM_B>>>(
        pTh, pTl, pWvuTh, pWvuTl, out);
}

// round 9
// speedup vs baseline: 6.3430x; 1.1640x over previous
#include <cuda_runtime.h>
#include <cuda_bf16.h>
#include <math.h>
#include <stdint.h>

// Problem shape (fixed)
#define BB 4
#define NN 4096
#define EE 1024
#define DD 256
#define NEG_FILL (-3.402823466385288598e+38f)

// ---------------- scratch (static device globals; no allocs) ----------------
__device__ __nv_bfloat16 g_Xh  [(size_t)BB * NN * EE];
__device__ __nv_bfloat16 g_Xl  [(size_t)BB * NN * EE];
__device__ __nv_bfloat16 g_Qh  [(size_t)BB * NN * DD];
__device__ __nv_bfloat16 g_Ql  [(size_t)BB * NN * DD];
__device__ __nv_bfloat16 g_Kh  [(size_t)BB * NN * DD];
__device__ __nv_bfloat16 g_Kl  [(size_t)BB * NN * DD];
__device__ __nv_bfloat16 g_VdTh[(size_t)DD * BB * NN];  // (X@Wvd)^T  [256, B*N]
__device__ __nv_bfloat16 g_VdTl[(size_t)DD * BB * NN];
__device__ __nv_bfloat16 g_Th  [(size_t)BB * NN * DD];  // T = softmax(S)@Vd
__device__ __nv_bfloat16 g_Tl  [(size_t)BB * NN * DD];
__device__ float         g_Tp0 [(size_t)BB * NN * DD];  // T split-K partials (f32)
__device__ float         g_Tp1 [(size_t)BB * NN * DD];
__device__ float         g_rsum[(size_t)BB * NN];       // unnormalized row sums
__device__ __nv_bfloat16 g_WqTh[(size_t)DD * EE];
__device__ __nv_bfloat16 g_WqTl[(size_t)DD * EE];
__device__ __nv_bfloat16 g_WkTh[(size_t)DD * EE];
__device__ __nv_bfloat16 g_WkTl[(size_t)DD * EE];
__device__ __nv_bfloat16 g_WvdTh[(size_t)DD * EE];
__device__ __nv_bfloat16 g_WvdTl[(size_t)DD * EE];
__device__ __nv_bfloat16 g_WvuTh[(size_t)EE * DD];
__device__ __nv_bfloat16 g_WvuTl[(size_t)EE * DD];
__device__ __nv_bfloat16 g_Ph  [(size_t)BB * NN * NN];  // unnormalized exp(S) hi
__device__ __nv_bfloat16 g_Pl  [(size_t)BB * NN * NN];  // unnormalized exp(S) lo

// ---------------- helpers ----------------
__device__ __forceinline__ uint32_t smem_u32(const void* p) {
    uint32_t a;
    asm("{ .reg .u64 t; cvta.to.shared.u64 t, %1; cvt.u32.u64 %0, t; }"
        : "=r"(a) : "l"(p));
    return a;
}
__device__ __forceinline__ void ldsm4(uint32_t* r, uint32_t a) {
    asm volatile("ldmatrix.sync.aligned.m8n8.x4.shared.b16 {%0,%1,%2,%3}, [%4];"
                 : "=r"(r[0]), "=r"(r[1]), "=r"(r[2]), "=r"(r[3]) : "r"(a));
}
__device__ __forceinline__ void ldsm2(uint32_t* r, uint32_t a) {
    asm volatile("ldmatrix.sync.aligned.m8n8.x2.shared.b16 {%0,%1}, [%2];"
                 : "=r"(r[0]), "=r"(r[1]) : "r"(a));
}
__device__ __forceinline__ void mma_bf16(float* d, const uint32_t* a, const uint32_t* b) {
    asm volatile(
        "mma.sync.aligned.m16n8k16.row.col.f32.bf16.bf16.f32 "
        "{%0,%1,%2,%3}, {%4,%5,%6,%7}, {%8,%9}, {%0,%1,%2,%3};"
        : "+f"(d[0]), "+f"(d[1]), "+f"(d[2]), "+f"(d[3])
        : "r"(a[0]), "r"(a[1]), "r"(a[2]), "r"(a[3]), "r"(b[0]), "r"(b[1]));
}
__device__ __forceinline__ void cp16(uint32_t saddr, const void* gaddr) {
    asm volatile("cp.async.cg.shared.global [%0], [%1], 16;"
                 :: "r"(saddr), "l"(gaddr) : "memory");
}
#define CP_COMMIT() asm volatile("cp.async.commit_group;" ::: "memory")
#define CP_WAIT1()  asm volatile("cp.async.wait_group 1;" ::: "memory")

// swizzled offset within a 128x32 bf16 tile (rows of 64B, 4x16B chunks)
__device__ __forceinline__ uint32_t tswz(int row, int chunk) {
    return (uint32_t)(row * 64 + ((chunk ^ ((row >> 1) & 3)) << 4));
}

#define TILE_B   8192           // 128*32 bf16
#define STAGE_B  (4 * TILE_B)   // Ah, Al, Bh, Bl
#define NSTAGE   2              // double buffer -> 64 KB -> occupancy 2
#define SMEM_B   (NSTAGE * STAGE_B)

// ---------------------------------------------------------------------------
// Mainloop core: 128x128x(32*numIt) split-3 bf16 MMA, 2-stage double buffer.
// Designed for __launch_bounds__(256, 2): two CTAs per SM so one CTA's
// mainloop overlaps the other's prologue/epilogue.
// ---------------------------------------------------------------------------
__device__ __forceinline__ void gemm_core(
    const __nv_bfloat16* __restrict__ Ah, const __nv_bfloat16* __restrict__ Al,
    const __nv_bfloat16* __restrict__ Bh, const __nv_bfloat16* __restrict__ Bl,
    int m0, int n0, int ldA, int ldB, int numIt, char* sm,
    float acc[4][4][4])
{
    const int tid = threadIdx.x;
    const int lane = tid & 31;
    const int wid = tid >> 5;
    const int wm = wid >> 2;        // 0..1
    const int wn = wid & 3;         // 0..3

    auto issue = [&](int stage, int it) {
        char* st = sm + stage * STAGE_B;
        const int k0 = it << 5;
#pragma unroll
        for (int j = 0; j < 2; j++) {
            int idx = tid + j * 256;        // 0..511
            int row = idx >> 2, c = idx & 3;
            uint32_t off = tswz(row, c);
            uint32_t s0 = smem_u32(st) + off;
            const __nv_bfloat16* ga  = Ah + (size_t)(m0 + row) * ldA + k0 + c * 8;
            const __nv_bfloat16* gal = Al + (size_t)(m0 + row) * ldA + k0 + c * 8;
            const __nv_bfloat16* gb  = Bh + (size_t)(n0 + row) * ldB + k0 + c * 8;
            const __nv_bfloat16* gbl = Bl + (size_t)(n0 + row) * ldB + k0 + c * 8;
            cp16(s0, ga);
            cp16(s0 + TILE_B, gal);
            cp16(s0 + 2 * TILE_B, gb);
            cp16(s0 + 3 * TILE_B, gbl);
        }
    };

    issue(0, 0); CP_COMMIT();
    if (numIt > 1) issue(1, 1);
    CP_COMMIT();

    for (int it = 0; it < numIt; ++it) {
        CP_WAIT1();                 // stage (it&1) landed
        __syncthreads();

        char* st = sm + (it & 1) * STAGE_B;
        const uint32_t bAh = smem_u32(st);
        const uint32_t bAl = bAh + TILE_B;
        const uint32_t bBh = bAh + 2 * TILE_B;
        const uint32_t bBl = bAh + 3 * TILE_B;

#pragma unroll
        for (int ks = 0; ks < 2; ks++) {
            uint32_t ah[4][4], al[4][4], bh[4][2], bl[4][2];
            const int arow = wm * 64 + (lane & 15);
            const int ac = ks * 2 + (lane >> 4);
            const int brow = wn * 32 + (lane & 7);
            const int bc = ks * 2 + ((lane >> 3) & 1);
#pragma unroll
            for (int mf = 0; mf < 4; mf++) {
                uint32_t o = tswz(arow + mf * 16, ac);
                ldsm4(ah[mf], bAh + o);
                ldsm4(al[mf], bAl + o);
            }
#pragma unroll
            for (int nf = 0; nf < 4; nf++) {
                uint32_t o = tswz(brow + nf * 8, bc);
                ldsm2(bh[nf], bBh + o);
                ldsm2(bl[nf], bBl + o);
            }
#pragma unroll
            for (int mf = 0; mf < 4; mf++)
#pragma unroll
                for (int nf = 0; nf < 4; nf++) {
                    mma_bf16(acc[mf][nf], ah[mf], bh[nf]);
                    mma_bf16(acc[mf][nf], ah[mf], bl[nf]);
                    mma_bf16(acc[mf][nf], al[mf], bh[nf]);
                }
        }
        __syncthreads();            // compute done before stage reuse
        if (it + 2 < numIt) issue(it & 1, it + 2);
        CP_COMMIT();
    }
}

// ---- epilogue helpers ----
__device__ __forceinline__ void store_bf(
    float acc[4][4][4], __nv_bfloat16* Ch, __nv_bfloat16* Cl,
    int m0, int n0, int ldC, bool ct)
{
    const int lane = threadIdx.x & 31;
    const int wid = threadIdx.x >> 5;
    const int wm = wid >> 2, wn = wid & 3;
    const int g = lane >> 2, t2 = (lane & 3) * 2;
#pragma unroll
    for (int mf = 0; mf < 4; mf++)
#pragma unroll
        for (int nf = 0; nf < 4; nf++) {
            const float* a = acc[mf][nf];
            const int r0 = m0 + wm * 64 + mf * 16 + g;
            const int c0 = n0 + wn * 32 + nf * 8 + t2;
#pragma unroll
            for (int h = 0; h < 2; h++) {
                const int r = r0 + h * 8;
                float v0 = a[h * 2 + 0];
                float v1 = a[h * 2 + 1];
                __nv_bfloat16 h0 = __float2bfloat16(v0);
                __nv_bfloat16 h1 = __float2bfloat16(v1);
                __nv_bfloat16 l0 = __float2bfloat16(v0 - __bfloat162float(h0));
                __nv_bfloat16 l1 = __float2bfloat16(v1 - __bfloat162float(h1));
                if (ct) {
                    Ch[(size_t)c0 * ldC + r] = h0;
                    Ch[(size_t)(c0 + 1) * ldC + r] = h1;
                    Cl[(size_t)c0 * ldC + r] = l0;
                    Cl[(size_t)(c0 + 1) * ldC + r] = l1;
                } else {
                    *(__nv_bfloat162*)(Ch + (size_t)r * ldC + c0) = __nv_bfloat162(h0, h1);
                    *(__nv_bfloat162*)(Cl + (size_t)r * ldC + c0) = __nv_bfloat162(l0, l1);
                }
            }
        }
}
__device__ __forceinline__ void store_f32(
    float acc[4][4][4], float* Cf, int m0, int n0, int ldC)
{
    const int lane = threadIdx.x & 31;
    const int wid = threadIdx.x >> 5;
    const int wm = wid >> 2, wn = wid & 3;
    const int g = lane >> 2, t2 = (lane & 3) * 2;
#pragma unroll
    for (int mf = 0; mf < 4; mf++)
#pragma unroll
        for (int nf = 0; nf < 4; nf++) {
            const float* a = acc[mf][nf];
            const int r0 = m0 + wm * 64 + mf * 16 + g;
            const int c0 = n0 + wn * 32 + nf * 8 + t2;
#pragma unroll
            for (int h = 0; h < 2; h++) {
                const int r = r0 + h * 8;
                *(float2*)(Cf + (size_t)r * ldC + c0) =
                    make_float2(a[h * 2], a[h * 2 + 1]);
            }
        }
}

// ---------------------------------------------------------------------------
// Merged Q/K/Vd projection: A = X for all, z selects B and destination.
// ---------------------------------------------------------------------------
__global__ void __launch_bounds__(256, 2)
mma_gemm_qkv(const __nv_bfloat16* __restrict__ Xh, const __nv_bfloat16* __restrict__ Xl,
             const __nv_bfloat16* __restrict__ Bqh, const __nv_bfloat16* __restrict__ Bql,
             const __nv_bfloat16* __restrict__ Bkh, const __nv_bfloat16* __restrict__ Bkl,
             const __nv_bfloat16* __restrict__ Bvh, const __nv_bfloat16* __restrict__ Bvl,
             __nv_bfloat16* __restrict__ Qh, __nv_bfloat16* __restrict__ Ql,
             __nv_bfloat16* __restrict__ Kh, __nv_bfloat16* __restrict__ Kl,
             __nv_bfloat16* __restrict__ Vh, __nv_bfloat16* __restrict__ Vl)
{
    const int m0 = blockIdx.y * 128;
    const int n0 = blockIdx.x * 128;
    const int z = blockIdx.z;

    const __nv_bfloat16* Bh = (z == 0) ? Bqh : (z == 1) ? Bkh : Bvh;
    const __nv_bfloat16* Bl = (z == 0) ? Bql : (z == 1) ? Bkl : Bvl;

    extern __shared__ char sm[];
    float acc[4][4][4] = {};
    gemm_core(Xh, Xl, Bh, Bl, m0, n0, EE, EE, EE >> 5, sm, acc);

    if (z == 0)      store_bf(acc, Qh, Ql, m0, n0, DD, false);
    else if (z == 1) store_bf(acc, Kh, Kl, m0, n0, DD, false);
    else             store_bf(acc, Vh, Vl, m0, n0, BB * NN, true);
}

// ---------------------------------------------------------------------------
// S GEMM with fused quirk + exp + row-sum epilogue.
//   s = (Q.K)/16;  e = (masked) ? 0 : expf(s!=0 ? s : NEG_FILL)
//   Writes unnormalized probs as bf16 hi/lo; rowsum += e via atomics.
// Max-subtraction omitted: |s| <~ 16 so exp and row sums sit far inside f32.
// ---------------------------------------------------------------------------
__global__ void __launch_bounds__(256, 2)
mma_gemm_sexp(const __nv_bfloat16* __restrict__ Qh, const __nv_bfloat16* __restrict__ Ql,
              const __nv_bfloat16* __restrict__ Kh, const __nv_bfloat16* __restrict__ Kl,
              __nv_bfloat16* __restrict__ Ph, __nv_bfloat16* __restrict__ Pl,
              float* __restrict__ rsum)
{
    const int m0 = blockIdx.y * 128;
    const int n0 = blockIdx.x * 128;
    if (n0 > m0 + 127) return;          // fully masked tile
    const int z = blockIdx.z;

    const __nv_bfloat16* Ah = Qh + (size_t)z * NN * DD;
    const __nv_bfloat16* Al = Ql + (size_t)z * NN * DD;
    const __nv_bfloat16* Bh = Kh + (size_t)z * NN * DD;
    const __nv_bfloat16* Bl = Kl + (size_t)z * NN * DD;
    Ph += (size_t)z * NN * NN;
    Pl += (size_t)z * NN * NN;
    rsum += (size_t)z * NN;

    extern __shared__ char sm[];
    float acc[4][4][4] = {};
    gemm_core(Ah, Al, Bh, Bl, m0, n0, DD, DD, DD >> 5, sm, acc);

    const bool diag = (m0 == n0);
    const int lane = threadIdx.x & 31;
    const int wid = threadIdx.x >> 5;
    const int wm = wid >> 2, wn = wid & 3;
    const int g = lane >> 2, t2 = (lane & 3) * 2;
    const float alpha = 1.0f / 16.0f;

#pragma unroll
    for (int mf = 0; mf < 4; mf++) {
#pragma unroll
        for (int h = 0; h < 2; h++) {
            const int rl = wm * 64 + mf * 16 + g + h * 8;   // row within tile
            const int row = m0 + rl;
            float rs = 0.0f;
#pragma unroll
            for (int nf = 0; nf < 4; nf++) {
                const int cl = wn * 32 + nf * 8 + t2;       // col within tile
                float s0 = acc[mf][nf][h * 2 + 0] * alpha;
                float s1 = acc[mf][nf][h * 2 + 1] * alpha;
                float e0 = (diag && cl > rl) ? 0.0f
                           : expf((s0 != 0.0f) ? s0 : NEG_FILL);
                float e1 = (diag && cl + 1 > rl) ? 0.0f
                           : expf((s1 != 0.0f) ? s1 : NEG_FILL);
                rs += e0 + e1;
                __nv_bfloat16 h0 = __float2bfloat16(e0);
                __nv_bfloat16 h1 = __float2bfloat16(e1);
                __nv_bfloat16 l0 = __float2bfloat16(e0 - __bfloat162float(h0));
                __nv_bfloat16 l1 = __float2bfloat16(e1 - __bfloat162float(h1));
                *(__nv_bfloat162*)(Ph + (size_t)row * NN + n0 + cl) = __nv_bfloat162(h0, h1);
                *(__nv_bfloat162*)(Pl + (size_t)row * NN + n0 + cl) = __nv_bfloat162(l0, l1);
            }
            rs += __shfl_xor_sync(0xffffffff, rs, 1);
            rs += __shfl_xor_sync(0xffffffff, rs, 2);
            if ((lane & 3) == 0) atomicAdd(&rsum[row], rs);
        }
    }
}

// ---------------------------------------------------------------------------
// T GEMM, split-K in two halves -> f32 partials. Reverse-y: big-K CTAs first.
// ---------------------------------------------------------------------------
__global__ void __launch_bounds__(256, 2)
mma_gemm_tsplit(const __nv_bfloat16* __restrict__ Ph, const __nv_bfloat16* __restrict__ Pl,
                const __nv_bfloat16* __restrict__ Vh, const __nv_bfloat16* __restrict__ Vl,
                float* __restrict__ Tp0, float* __restrict__ Tp1)
{
    const int by = gridDim.y - 1 - blockIdx.y;
    const int m0 = by * 128;
    const int n0 = blockIdx.x * 128;
    const int batch = blockIdx.z >> 1;
    const int half = blockIdx.z & 1;

    const int kEnd = m0 + 128;          // causal K limit (multiple of 128)
    const int kh = kEnd >> 1;           // multiple of 64 (so multiple of 32)
    const int ks = half ? kh : 0;
    const int ke = half ? kEnd : kh;

    const __nv_bfloat16* Ah = Ph + (size_t)batch * NN * NN + ks;
    const __nv_bfloat16* Al = Pl + (size_t)batch * NN * NN + ks;
    const __nv_bfloat16* Bh = Vh + (size_t)batch * NN + ks;
    const __nv_bfloat16* Bl = Vl + (size_t)batch * NN + ks;
    float* Tp = (half ? Tp1 : Tp0) + (size_t)batch * NN * DD;

    extern __shared__ char sm[];
    float acc[4][4][4] = {};
    gemm_core(Ah, Al, Bh, Bl, m0, n0, NN, BB * NN, (ke - ks) >> 5, sm, acc);
    store_f32(acc, Tp, m0, n0, DD);
}

// ---------------------------------------------------------------------------
// Combine T partials, normalize by row sums, emit bf16 hi/lo.
// ---------------------------------------------------------------------------
__global__ void __launch_bounds__(256)
combine_T(const float* __restrict__ p0, const float* __restrict__ p1,
          const float* __restrict__ rsum,
          __nv_bfloat16* __restrict__ Th, __nv_bfloat16* __restrict__ Tl)
{
    int i = blockIdx.x * 256 + threadIdx.x;          // over (BB*NN*DD)/4
    float4 a = ((const float4*)p0)[i];
    float4 b = ((const float4*)p1)[i];
    const float inv = 1.0f / rsum[i >> 6];           // row = (i*4)/DD
    float v0 = (a.x + b.x) * inv, v1 = (a.y + b.y) * inv;
    float v2 = (a.z + b.z) * inv, v3 = (a.w + b.w) * inv;
    __nv_bfloat16 h0 = __float2bfloat16(v0), h1 = __float2bfloat16(v1);
    __nv_bfloat16 h2 = __float2bfloat16(v2), h3 = __float2bfloat16(v3);
    __nv_bfloat16 l0 = __float2bfloat16(v0 - __bfloat162float(h0));
    __nv_bfloat16 l1 = __float2bfloat16(v1 - __bfloat162float(h1));
    __nv_bfloat16 l2 = __float2bfloat16(v2 - __bfloat162float(h2));
    __nv_bfloat16 l3 = __float2bfloat16(v3 - __bfloat162float(h3));
    ((__nv_bfloat162*)Th)[i * 2 + 0] = __nv_bfloat162(h0, h1);
    ((__nv_bfloat162*)Th)[i * 2 + 1] = __nv_bfloat162(h2, h3);
    ((__nv_bfloat162*)Tl)[i * 2 + 0] = __nv_bfloat162(l0, l1);
    ((__nv_bfloat162*)Tl)[i * 2 + 1] = __nv_bfloat162(l2, l3);
}

// ---------------------------------------------------------------------------
// out = T @ Wvu, f32 out
// ---------------------------------------------------------------------------
__global__ void __launch_bounds__(256, 2)
mma_gemm_out(const __nv_bfloat16* __restrict__ Ah, const __nv_bfloat16* __restrict__ Al,
             const __nv_bfloat16* __restrict__ Bh, const __nv_bfloat16* __restrict__ Bl,
             float* __restrict__ Cf)
{
    const int m0 = blockIdx.y * 128;
    const int n0 = blockIdx.x * 128;
    extern __shared__ char sm[];
    float acc[4][4][4] = {};
    gemm_core(Ah, Al, Bh, Bl, m0, n0, DD, DD, DD >> 5, sm, acc);
    store_f32(acc, Cf, m0, n0, EE);
}

// ---------------------------------------------------------------------------
// Merged prep kernel (one launch replaces 5 kernels + memset):
//   blocks [0, 16384):          X f32 -> bf16 hi/lo split
//   blocks [16384, 16384+1024): 4 weight transpose+splits (256 blocks each)
//   blocks [+1024, +1040):      zero rsum
// ---------------------------------------------------------------------------
__global__ void __launch_bounds__(256)
prep_all(const float* __restrict__ X,
         const float* __restrict__ Wq, const float* __restrict__ Wk,
         const float* __restrict__ Wvd, const float* __restrict__ Wvu,
         __nv_bfloat16* __restrict__ Xh, __nv_bfloat16* __restrict__ Xl,
         __nv_bfloat16* __restrict__ WqTh, __nv_bfloat16* __restrict__ WqTl,
         __nv_bfloat16* __restrict__ WkTh, __nv_bfloat16* __restrict__ WkTl,
         __nv_bfloat16* __restrict__ WvdTh, __nv_bfloat16* __restrict__ WvdTl,
         __nv_bfloat16* __restrict__ WvuTh, __nv_bfloat16* __restrict__ WvuTl,
         float* __restrict__ rsum)
{
    const int b = blockIdx.x;
    const int tid = threadIdx.x;

    if (b < 16384) {                       // ---- X split (exact: 16384*256 = n4)
        int i = b * 256 + tid;
        float4 v = ((const float4*)X)[i];
        __nv_bfloat16 h0 = __float2bfloat16(v.x), h1 = __float2bfloat16(v.y);
        __nv_bfloat16 h2 = __float2bfloat16(v.z), h3 = __float2bfloat16(v.w);
        __nv_bfloat16 l0 = __float2bfloat16(v.x - __bfloat162float(h0));
        __nv_bfloat16 l1 = __float2bfloat16(v.y - __bfloat162float(h1));
        __nv_bfloat16 l2 = __float2bfloat16(v.z - __bfloat162float(h2));
        __nv_bfloat16 l3 = __float2bfloat16(v.w - __bfloat162float(h3));
        ((__nv_bfloat162*)Xh)[i * 2 + 0] = __nv_bfloat162(h0, h1);
        ((__nv_bfloat162*)Xh)[i * 2 + 1] = __nv_bfloat162(h2, h3);
        ((__nv_bfloat162*)Xl)[i * 2 + 0] = __nv_bfloat162(l0, l1);
        ((__nv_bfloat162*)Xl)[i * 2 + 1] = __nv_bfloat162(l2, l3);
        return;
    }
    if (b < 16384 + 1024) {                // ---- weight transpose+split
        const int t = b - 16384;
        const int w = t >> 8;              // 0=Wq 1=Wk 2=Wvd 3=Wvu
        const int s = t & 255;
        const float* src; __nv_bfloat16 *dh, *dl;
        int M, N, gx, gy;
        if (w < 3) {                       // [EE, DD] -> [DD, EE]
            M = EE; N = DD; gx = s & 7; gy = s >> 3;
            src = (w == 0) ? Wq : (w == 1) ? Wk : Wvd;
            dh = (w == 0) ? WqTh : (w == 1) ? WkTh : WvdTh;
            dl = (w == 0) ? WqTl : (w == 1) ? WkTl : WvdTl;
        } else {                           // [DD, EE] -> [EE, DD]
            M = DD; N = EE; gx = s & 31; gy = s >> 5;
            src = Wvu; dh = WvuTh; dl = WvuTl;
        }
        __shared__ float tb[32][33];
        const int bx = gx * 32, by = gy * 32;
        const int x = tid & 31, y = tid >> 5;     // 32x8
#pragma unroll
        for (int i = 0; i < 32; i += 8)
            tb[y + i][x] = src[(size_t)(by + y + i) * N + bx + x];
        __syncthreads();
#pragma unroll
        for (int i = 0; i < 32; i += 8) {
            float v = tb[x][y + i];
            __nv_bfloat16 h = __float2bfloat16(v);
            dh[(size_t)(bx + y + i) * M + by + x] = h;
            dl[(size_t)(bx + y + i) * M + by + x] =
                __float2bfloat16(v - __bfloat162float(h));
        }
        return;
    }
    {                                      // ---- zero rsum (16 blocks x 256 float4)
        const int t = b - (16384 + 1024);
        int i = t * 256 + tid;             // over BB*NN/4 = 4096 float4
        ((float4*)rsum)[i] = make_float4(0.f, 0.f, 0.f, 0.f);
    }
}

// ---------------------------------------------------------------------------
extern "C" void kernel_launch(void* const* d_in, const int* in_sizes, int n_in,
                              void* d_out, int out_size)
{
    (void)in_sizes; (void)n_in; (void)out_size;
    const float* X   = (const float*)d_in[0];
    const float* Wq  = (const float*)d_in[1];
    const float* Wk  = (const float*)d_in[2];
    const float* Wvd = (const float*)d_in[3];
    const float* Wvu = (const float*)d_in[4];
    float* out = (float*)d_out;

    __nv_bfloat16 *pXh, *pXl, *pQh, *pQl, *pKh, *pKl, *pVdTh, *pVdTl, *pTh, *pTl;
    __nv_bfloat16 *pWqTh, *pWqTl, *pWkTh, *pWkTl, *pWvdTh, *pWvdTl, *pWvuTh, *pWvuTl;
    __nv_bfloat16 *pPh, *pPl;
    float *pTp0, *pTp1, *pRs;
    cudaGetSymbolAddress((void**)&pXh, g_Xh);     cudaGetSymbolAddress((void**)&pXl, g_Xl);
    cudaGetSymbolAddress((void**)&pQh, g_Qh);     cudaGetSymbolAddress((void**)&pQl, g_Ql);
    cudaGetSymbolAddress((void**)&pKh, g_Kh);     cudaGetSymbolAddress((void**)&pKl, g_Kl);
    cudaGetSymbolAddress((void**)&pVdTh, g_VdTh); cudaGetSymbolAddress((void**)&pVdTl, g_VdTl);
    cudaGetSymbolAddress((void**)&pTh, g_Th);     cudaGetSymbolAddress((void**)&pTl, g_Tl);
    cudaGetSymbolAddress((void**)&pTp0, g_Tp0);   cudaGetSymbolAddress((void**)&pTp1, g_Tp1);
    cudaGetSymbolAddress((void**)&pRs, g_rsum);
    cudaGetSymbolAddress((void**)&pWqTh, g_WqTh); cudaGetSymbolAddress((void**)&pWqTl, g_WqTl);
    cudaGetSymbolAddress((void**)&pWkTh, g_WkTh); cudaGetSymbolAddress((void**)&pWkTl, g_WkTl);
    cudaGetSymbolAddress((void**)&pWvdTh, g_WvdTh); cudaGetSymbolAddress((void**)&pWvdTl, g_WvdTl);
    cudaGetSymbolAddress((void**)&pWvuTh, g_WvuTh); cudaGetSymbolAddress((void**)&pWvuTl, g_WvuTl);
    cudaGetSymbolAddress((void**)&pPh, g_Ph);     cudaGetSymbolAddress((void**)&pPl, g_Pl);

    cudaFuncSetAttribute(mma_gemm_qkv,
                         cudaFuncAttributeMaxDynamicSharedMemorySize, SMEM_B);
    cudaFuncSetAttribute(mma_gemm_sexp,
                         cudaFuncAttributeMaxDynamicSharedMemorySize, SMEM_B);
    cudaFuncSetAttribute(mma_gemm_tsplit,
                         cudaFuncAttributeMaxDynamicSharedMemorySize, SMEM_B);
    cudaFuncSetAttribute(mma_gemm_out,
                         cudaFuncAttributeMaxDynamicSharedMemorySize, SMEM_B);

    const dim3 blk(256);

    // 0) merged prep: X split + 4 weight transposes + rsum zero, one launch
    prep_all<<<16384 + 1024 + 16, blk>>>(
        X, Wq, Wk, Wvd, Wvu, pXh, pXl,
        pWqTh, pWqTl, pWkTh, pWkTl, pWvdTh, pWvdTl, pWvuTh, pWvuTl, pRs);

    // 1) merged Q/K/VdT projection (occupancy 2)
    mma_gemm_qkv<<<dim3(2, 128, 3), blk, SMEM_B>>>(
        pXh, pXl, pWqTh, pWqTl, pWkTh, pWkTl, pWvdTh, pWvdTl,
        pQh, pQl, pKh, pKl, pVdTh, pVdTl);

    // 2) S = Q@K^T/16 with fused quirk+exp+rowsum epilogue
    mma_gemm_sexp<<<dim3(32, 32, BB), blk, SMEM_B>>>(
        pQh, pQl, pKh, pKl, pPh, pPl, pRs);

    // 3) T partials = exp(S) @ Vd, split-K halves, big-K CTAs first
    mma_gemm_tsplit<<<dim3(2, 32, BB * 2), blk, SMEM_B>>>(
        pPh, pPl, pVdTh, pVdTl, pTp0, pTp1);

    // 4) combine + normalize -> Th/Tl
    combine_T<<<(BB * NN * DD / 4) / 256, blk>>>(pTp0, pTp1, pRs, pTh, pTl);

    // 5) out = T @ Wvu
    mma_gemm_out<<<dim3(8, 128, 1), blk, SMEM_B>>>(
        pTh, pTl, pWvuTh, pWvuTl, out);
}

// round 10
// speedup vs baseline: 6.4088x; 1.0104x over previous
#include <cuda_runtime.h>
#include <cuda_bf16.h>
#include <math.h>
#include <stdint.h>

// Problem shape (fixed)
#define BB 4
#define NN 4096
#define EE 1024
#define DD 256
#define NEG_FILL (-3.402823466385288598e+38f)

// ---------------- scratch (static device globals; no allocs) ----------------
__device__ __nv_bfloat16 g_Xh  [(size_t)BB * NN * EE];
__device__ __nv_bfloat16 g_Xl  [(size_t)BB * NN * EE];
__device__ __nv_bfloat16 g_Qh  [(size_t)BB * NN * DD];
__device__ __nv_bfloat16 g_Ql  [(size_t)BB * NN * DD];
__device__ __nv_bfloat16 g_Kh  [(size_t)BB * NN * DD];
__device__ __nv_bfloat16 g_Kl  [(size_t)BB * NN * DD];
__device__ __nv_bfloat16 g_VdTh[(size_t)DD * BB * NN];  // (X@Wvd)^T  [256, B*N]
__device__ __nv_bfloat16 g_VdTl[(size_t)DD * BB * NN];
__device__ __nv_bfloat16 g_Th  [(size_t)BB * NN * DD];  // T = softmax(S)@Vd
__device__ __nv_bfloat16 g_Tl  [(size_t)BB * NN * DD];
__device__ float         g_Tp0 [(size_t)BB * NN * DD];  // T split-K partials (f32)
__device__ float         g_Tp1 [(size_t)BB * NN * DD];
__device__ float         g_rsum[(size_t)BB * NN];       // unnormalized row sums
__device__ __nv_bfloat16 g_WqTh[(size_t)DD * EE];
__device__ __nv_bfloat16 g_WqTl[(size_t)DD * EE];
__device__ __nv_bfloat16 g_WkTh[(size_t)DD * EE];
__device__ __nv_bfloat16 g_WkTl[(size_t)DD * EE];
__device__ __nv_bfloat16 g_WvdTh[(size_t)DD * EE];
__device__ __nv_bfloat16 g_WvdTl[(size_t)DD * EE];
__device__ __nv_bfloat16 g_WvuTh[(size_t)EE * DD];
__device__ __nv_bfloat16 g_WvuTl[(size_t)EE * DD];
__device__ __nv_bfloat16 g_Ph  [(size_t)BB * NN * NN];  // unnormalized exp(S) hi
__device__ __nv_bfloat16 g_Pl  [(size_t)BB * NN * NN];  // unnormalized exp(S) lo

// ---------------- helpers ----------------
__device__ __forceinline__ uint32_t smem_u32(const void* p) {
    uint32_t a;
    asm("{ .reg .u64 t; cvta.to.shared.u64 t, %1; cvt.u32.u64 %0, t; }"
        : "=r"(a) : "l"(p));
    return a;
}
__device__ __forceinline__ void ldsm4(uint32_t* r, uint32_t a) {
    asm volatile("ldmatrix.sync.aligned.m8n8.x4.shared.b16 {%0,%1,%2,%3}, [%4];"
                 : "=r"(r[0]), "=r"(r[1]), "=r"(r[2]), "=r"(r[3]) : "r"(a));
}
__device__ __forceinline__ void mma_bf16(float* d, const uint32_t* a, const uint32_t* b) {
    asm volatile(
        "mma.sync.aligned.m16n8k16.row.col.f32.bf16.bf16.f32 "
        "{%0,%1,%2,%3}, {%4,%5,%6,%7}, {%8,%9}, {%0,%1,%2,%3};"
        : "+f"(d[0]), "+f"(d[1]), "+f"(d[2]), "+f"(d[3])
        : "r"(a[0]), "r"(a[1]), "r"(a[2]), "r"(a[3]), "r"(b[0]), "r"(b[1]));
}
__device__ __forceinline__ void cp16(uint32_t saddr, const void* gaddr) {
    asm volatile("cp.async.cg.shared.global [%0], [%1], 16;"
                 :: "r"(saddr), "l"(gaddr) : "memory");
}
#define CP_COMMIT() asm volatile("cp.async.commit_group;" ::: "memory")
#define CP_WAIT1()  asm volatile("cp.async.wait_group 1;" ::: "memory")

// swizzled offset within a 128x32 bf16 tile (rows of 64B, 4x16B chunks)
__device__ __forceinline__ uint32_t tswz(int row, int chunk) {
    return (uint32_t)(row * 64 + ((chunk ^ ((row >> 1) & 3)) << 4));
}

#define TILE_B   8192           // 128*32 bf16
#define STAGE_B  (4 * TILE_B)   // Ah, Al, Bh, Bl
#define NSTAGE   3              // 96 KB/CTA -> occupancy 2 (192 KB/SM)
#define SMEM_B   (NSTAGE * STAGE_B)

// ---------------------------------------------------------------------------
// Mainloop core: 128x128x(32*numIt) split-3 bf16 MMA.
// 128 threads, 4 warps (2x2), 64x64 warp tile -> 85 B smem per MMA
// (vs 128 B at 64x32), lifting the crossbar-imposed tensor ceiling 50%->75%.
// 3-stage cp.async ring with ONE barrier per iteration.
// acc layout: acc[mf 0..3][nf 0..7][4]
// ---------------------------------------------------------------------------
__device__ __forceinline__ void gemm_core(
    const __nv_bfloat16* __restrict__ Ah, const __nv_bfloat16* __restrict__ Al,
    const __nv_bfloat16* __restrict__ Bh, const __nv_bfloat16* __restrict__ Bl,
    int m0, int n0, int ldA, int ldB, int numIt, char* sm,
    float acc[4][8][4])
{
    const int tid = threadIdx.x;
    const int lane = tid & 31;
    const int wid = tid >> 5;
    const int wm = wid >> 1;        // 0..1
    const int wn = wid & 1;         // 0..1

    auto issue = [&](int stage, int it) {
        char* st = sm + stage * STAGE_B;
        const int k0 = it << 5;
#pragma unroll
        for (int j = 0; j < 4; j++) {
            int idx = tid + j * 128;        // 0..511
            int row = idx >> 2, c = idx & 3;
            uint32_t off = tswz(row, c);
            uint32_t s0 = smem_u32(st) + off;
            const __nv_bfloat16* ga  = Ah + (size_t)(m0 + row) * ldA + k0 + c * 8;
            const __nv_bfloat16* gal = Al + (size_t)(m0 + row) * ldA + k0 + c * 8;
            const __nv_bfloat16* gb  = Bh + (size_t)(n0 + row) * ldB + k0 + c * 8;
            const __nv_bfloat16* gbl = Bl + (size_t)(n0 + row) * ldB + k0 + c * 8;
            cp16(s0, ga);
            cp16(s0 + TILE_B, gal);
            cp16(s0 + 2 * TILE_B, gb);
            cp16(s0 + 3 * TILE_B, gbl);
        }
    };

    issue(0, 0); CP_COMMIT();
    if (numIt > 1) issue(1, 1);
    CP_COMMIT();

    for (int it = 0; it < numIt; ++it) {
        CP_WAIT1();                 // stage it%3 landed
        __syncthreads();            // all warps done reading stage (it+2)%3 (iter it-1)
        if (it + 2 < numIt) issue((it + 2) % 3, it + 2);
        CP_COMMIT();

        char* st = sm + (it % 3) * STAGE_B;
        const uint32_t bAh = smem_u32(st);
        const uint32_t bAl = bAh + TILE_B;
        const uint32_t bBh = bAh + 2 * TILE_B;
        const uint32_t bBl = bAh + 3 * TILE_B;

#pragma unroll
        for (int ks = 0; ks < 2; ks++) {
            uint32_t ah[4][4], al[4][4], bh[8][2], bl[8][2];
            const int arow = wm * 64 + (lane & 15);
            const int ac = ks * 2 + (lane >> 4);
#pragma unroll
            for (int mf = 0; mf < 4; mf++) {
                uint32_t o = tswz(arow + mf * 16, ac);
                ldsm4(ah[mf], bAh + o);
                ldsm4(al[mf], bAl + o);
            }
            // B: paired ldsm4 covers two n-fragments per instruction.
            // lanes 0-7: rows+0/k-lo, 8-15: rows+0/k-hi, 16-23: rows+8/k-lo,
            // 24-31: rows+8/k-hi  ->  {r0,r1}=nf even, {r2,r3}=nf odd.
            const int brow = wn * 64 + ((lane >> 4) & 1) * 8 + (lane & 7);
            const int bc = ks * 2 + ((lane >> 3) & 1);
#pragma unroll
            for (int nfp = 0; nfp < 4; nfp++) {
                uint32_t o = tswz(brow + nfp * 16, bc);
                uint32_t t4[4];
                ldsm4(t4, bBh + o);
                bh[2 * nfp][0] = t4[0]; bh[2 * nfp][1] = t4[1];
                bh[2 * nfp + 1][0] = t4[2]; bh[2 * nfp + 1][1] = t4[3];
                ldsm4(t4, bBl + o);
                bl[2 * nfp][0] = t4[0]; bl[2 * nfp][1] = t4[1];
                bl[2 * nfp + 1][0] = t4[2]; bl[2 * nfp + 1][1] = t4[3];
            }
#pragma unroll
            for (int mf = 0; mf < 4; mf++)
#pragma unroll
                for (int nf = 0; nf < 8; nf++) {
                    mma_bf16(acc[mf][nf], ah[mf], bh[nf]);
                    mma_bf16(acc[mf][nf], ah[mf], bl[nf]);
                    mma_bf16(acc[mf][nf], al[mf], bh[nf]);
                }
        }
    }
}

// ---- epilogue helpers (64x64 warp tile mapping) ----
__device__ __forceinline__ void store_bf(
    float acc[4][8][4], __nv_bfloat16* Ch, __nv_bfloat16* Cl,
    int m0, int n0, int ldC, bool ct)
{
    const int lane = threadIdx.x & 31;
    const int wid = threadIdx.x >> 5;
    const int wm = wid >> 1, wn = wid & 1;
    const int g = lane >> 2, t2 = (lane & 3) * 2;
#pragma unroll
    for (int mf = 0; mf < 4; mf++)
#pragma unroll
        for (int nf = 0; nf < 8; nf++) {
            const float* a = acc[mf][nf];
            const int r0 = m0 + wm * 64 + mf * 16 + g;
            const int c0 = n0 + wn * 64 + nf * 8 + t2;
#pragma unroll
            for (int h = 0; h < 2; h++) {
                const int r = r0 + h * 8;
                float v0 = a[h * 2 + 0];
                float v1 = a[h * 2 + 1];
                __nv_bfloat16 h0 = __float2bfloat16(v0);
                __nv_bfloat16 h1 = __float2bfloat16(v1);
                __nv_bfloat16 l0 = __float2bfloat16(v0 - __bfloat162float(h0));
                __nv_bfloat16 l1 = __float2bfloat16(v1 - __bfloat162float(h1));
                if (ct) {
                    Ch[(size_t)c0 * ldC + r] = h0;
                    Ch[(size_t)(c0 + 1) * ldC + r] = h1;
                    Cl[(size_t)c0 * ldC + r] = l0;
                    Cl[(size_t)(c0 + 1) * ldC + r] = l1;
                } else {
                    *(__nv_bfloat162*)(Ch + (size_t)r * ldC + c0) = __nv_bfloat162(h0, h1);
                    *(__nv_bfloat162*)(Cl + (size_t)r * ldC + c0) = __nv_bfloat162(l0, l1);
                }
            }
        }
}
__device__ __forceinline__ void store_f32(
    float acc[4][8][4], float* Cf, int m0, int n0, int ldC)
{
    const int lane = threadIdx.x & 31;
    const int wid = threadIdx.x >> 5;
    const int wm = wid >> 1, wn = wid & 1;
    const int g = lane >> 2, t2 = (lane & 3) * 2;
#pragma unroll
    for (int mf = 0; mf < 4; mf++)
#pragma unroll
        for (int nf = 0; nf < 8; nf++) {
            const float* a = acc[mf][nf];
            const int r0 = m0 + wm * 64 + mf * 16 + g;
            const int c0 = n0 + wn * 64 + nf * 8 + t2;
#pragma unroll
            for (int h = 0; h < 2; h++) {
                const int r = r0 + h * 8;
                *(float2*)(Cf + (size_t)r * ldC + c0) =
                    make_float2(a[h * 2], a[h * 2 + 1]);
            }
        }
}

// ---------------------------------------------------------------------------
// Merged Q/K/Vd projection: A = X for all, z selects B and destination.
// ---------------------------------------------------------------------------
__global__ void __launch_bounds__(128, 2)
mma_gemm_qkv(const __nv_bfloat16* __restrict__ Xh, const __nv_bfloat16* __restrict__ Xl,
             const __nv_bfloat16* __restrict__ Bqh, const __nv_bfloat16* __restrict__ Bql,
             const __nv_bfloat16* __restrict__ Bkh, const __nv_bfloat16* __restrict__ Bkl,
             const __nv_bfloat16* __restrict__ Bvh, const __nv_bfloat16* __restrict__ Bvl,
             __nv_bfloat16* __restrict__ Qh, __nv_bfloat16* __restrict__ Ql,
             __nv_bfloat16* __restrict__ Kh, __nv_bfloat16* __restrict__ Kl,
             __nv_bfloat16* __restrict__ Vh, __nv_bfloat16* __restrict__ Vl)
{
    const int m0 = blockIdx.y * 128;
    const int n0 = blockIdx.x * 128;
    const int z = blockIdx.z;

    const __nv_bfloat16* Bh = (z == 0) ? Bqh : (z == 1) ? Bkh : Bvh;
    const __nv_bfloat16* Bl = (z == 0) ? Bql : (z == 1) ? Bkl : Bvl;

    extern __shared__ char sm[];
    float acc[4][8][4] = {};
    gemm_core(Xh, Xl, Bh, Bl, m0, n0, EE, EE, EE >> 5, sm, acc);

    if (z == 0)      store_bf(acc, Qh, Ql, m0, n0, DD, false);
    else if (z == 1) store_bf(acc, Kh, Kl, m0, n0, DD, false);
    else             store_bf(acc, Vh, Vl, m0, n0, BB * NN, true);
}

// ---------------------------------------------------------------------------
// S GEMM with fused quirk + exp + row-sum epilogue.
// ---------------------------------------------------------------------------
__global__ void __launch_bounds__(128, 2)
mma_gemm_sexp(const __nv_bfloat16* __restrict__ Qh, const __nv_bfloat16* __restrict__ Ql,
              const __nv_bfloat16* __restrict__ Kh, const __nv_bfloat16* __restrict__ Kl,
              __nv_bfloat16* __restrict__ Ph, __nv_bfloat16* __restrict__ Pl,
              float* __restrict__ rsum)
{
    const int m0 = blockIdx.y * 128;
    const int n0 = blockIdx.x * 128;
    if (n0 > m0 + 127) return;          // fully masked tile
    const int z = blockIdx.z;

    const __nv_bfloat16* Ah = Qh + (size_t)z * NN * DD;
    const __nv_bfloat16* Al = Ql + (size_t)z * NN * DD;
    const __nv_bfloat16* Bh = Kh + (size_t)z * NN * DD;
    const __nv_bfloat16* Bl = Kl + (size_t)z * NN * DD;
    Ph += (size_t)z * NN * NN;
    Pl += (size_t)z * NN * NN;
    rsum += (size_t)z * NN;

    extern __shared__ char sm[];
    float acc[4][8][4] = {};
    gemm_core(Ah, Al, Bh, Bl, m0, n0, DD, DD, DD >> 5, sm, acc);

    const bool diag = (m0 == n0);
    const int lane = threadIdx.x & 31;
    const int wid = threadIdx.x >> 5;
    const int wm = wid >> 1, wn = wid & 1;
    const int g = lane >> 2, t2 = (lane & 3) * 2;
    const float alpha = 1.0f / 16.0f;

#pragma unroll
    for (int mf = 0; mf < 4; mf++) {
#pragma unroll
        for (int h = 0; h < 2; h++) {
            const int rl = wm * 64 + mf * 16 + g + h * 8;   // row within tile
            const int row = m0 + rl;
            float rs = 0.0f;
#pragma unroll
            for (int nf = 0; nf < 8; nf++) {
                const int cl = wn * 64 + nf * 8 + t2;       // col within tile
                float s0 = acc[mf][nf][h * 2 + 0] * alpha;
                float s1 = acc[mf][nf][h * 2 + 1] * alpha;
                float e0 = (diag && cl > rl) ? 0.0f
                           : expf((s0 != 0.0f) ? s0 : NEG_FILL);
                float e1 = (diag && cl + 1 > rl) ? 0.0f
                           : expf((s1 != 0.0f) ? s1 : NEG_FILL);
                rs += e0 + e1;
                __nv_bfloat16 h0 = __float2bfloat16(e0);
                __nv_bfloat16 h1 = __float2bfloat16(e1);
                __nv_bfloat16 l0 = __float2bfloat16(e0 - __bfloat162float(h0));
                __nv_bfloat16 l1 = __float2bfloat16(e1 - __bfloat162float(h1));
                *(__nv_bfloat162*)(Ph + (size_t)row * NN + n0 + cl) = __nv_bfloat162(h0, h1);
                *(__nv_bfloat162*)(Pl + (size_t)row * NN + n0 + cl) = __nv_bfloat162(l0, l1);
            }
            rs += __shfl_xor_sync(0xffffffff, rs, 1);
            rs += __shfl_xor_sync(0xffffffff, rs, 2);
            if ((lane & 3) == 0) atomicAdd(&rsum[row], rs);
        }
    }
}

// ---------------------------------------------------------------------------
// T GEMM, split-K in two halves -> f32 partials. Reverse-y: big-K CTAs first.
// ---------------------------------------------------------------------------
__global__ void __launch_bounds__(128, 2)
mma_gemm_tsplit(const __nv_bfloat16* __restrict__ Ph, const __nv_bfloat16* __restrict__ Pl,
                const __nv_bfloat16* __restrict__ Vh, const __nv_bfloat16* __restrict__ Vl,
                float* __restrict__ Tp0, float* __restrict__ Tp1)
{
    const int by = gridDim.y - 1 - blockIdx.y;
    const int m0 = by * 128;
    const int n0 = blockIdx.x * 128;
    const int batch = blockIdx.z >> 1;
    const int half = blockIdx.z & 1;

    const int kEnd = m0 + 128;          // causal K limit (multiple of 128)
    const int kh = kEnd >> 1;           // multiple of 64 (so multiple of 32)
    const int ks = half ? kh : 0;
    const int ke = half ? kEnd : kh;

    const __nv_bfloat16* Ah = Ph + (size_t)batch * NN * NN + ks;
    const __nv_bfloat16* Al = Pl + (size_t)batch * NN * NN + ks;
    const __nv_bfloat16* Bh = Vh + (size_t)batch * NN + ks;
    const __nv_bfloat16* Bl = Vl + (size_t)batch * NN + ks;
    float* Tp = (half ? Tp1 : Tp0) + (size_t)batch * NN * DD;

    extern __shared__ char sm[];
    float acc[4][8][4] = {};
    gemm_core(Ah, Al, Bh, Bl, m0, n0, NN, BB * NN, (ke - ks) >> 5, sm, acc);
    store_f32(acc, Tp, m0, n0, DD);
}

// ---------------------------------------------------------------------------
// Combine T partials, normalize by row sums, emit bf16 hi/lo.
// ---------------------------------------------------------------------------
__global__ void __launch_bounds__(256)
combine_T(const float* __restrict__ p0, const float* __restrict__ p1,
          const float* __restrict__ rsum,
          __nv_bfloat16* __restrict__ Th, __nv_bfloat16* __restrict__ Tl)
{
    int i = blockIdx.x * 256 + threadIdx.x;          // over (BB*NN*DD)/4
    float4 a = ((const float4*)p0)[i];
    float4 b = ((const float4*)p1)[i];
    const float inv = 1.0f / rsum[i >> 6];           // row = (i*4)/DD
    float v0 = (a.x + b.x) * inv, v1 = (a.y + b.y) * inv;
    float v2 = (a.z + b.z) * inv, v3 = (a.w + b.w) * inv;
    __nv_bfloat16 h0 = __float2bfloat16(v0), h1 = __float2bfloat16(v1);
    __nv_bfloat16 h2 = __float2bfloat16(v2), h3 = __float2bfloat16(v3);
    __nv_bfloat16 l0 = __float2bfloat16(v0 - __bfloat162float(h0));
    __nv_bfloat16 l1 = __float2bfloat16(v1 - __bfloat162float(h1));
    __nv_bfloat16 l2 = __float2bfloat16(v2 - __bfloat162float(h2));
    __nv_bfloat16 l3 = __float2bfloat16(v3 - __bfloat162float(h3));
    ((__nv_bfloat162*)Th)[i * 2 + 0] = __nv_bfloat162(h0, h1);
    ((__nv_bfloat162*)Th)[i * 2 + 1] = __nv_bfloat162(h2, h3);
    ((__nv_bfloat162*)Tl)[i * 2 + 0] = __nv_bfloat162(l0, l1);
    ((__nv_bfloat162*)Tl)[i * 2 + 1] = __nv_bfloat162(l2, l3);
}

// ---------------------------------------------------------------------------
// out = T @ Wvu, f32 out
// ---------------------------------------------------------------------------
__global__ void __launch_bounds__(128, 2)
mma_gemm_out(const __nv_bfloat16* __restrict__ Ah, const __nv_bfloat16* __restrict__ Al,
             const __nv_bfloat16* __restrict__ Bh, const __nv_bfloat16* __restrict__ Bl,
             float* __restrict__ Cf)
{
    const int m0 = blockIdx.y * 128;
    const int n0 = blockIdx.x * 128;
    extern __shared__ char sm[];
    float acc[4][8][4] = {};
    gemm_core(Ah, Al, Bh, Bl, m0, n0, DD, DD, DD >> 5, sm, acc);
    store_f32(acc, Cf, m0, n0, EE);
}

// ---------------------------------------------------------------------------
// Merged prep kernel (one launch):
//   blocks [0, 16384):          X f32 -> bf16 hi/lo split
//   blocks [16384, 16384+1024): 4 weight transpose+splits (256 blocks each)
//   blocks [+1024, +1040):      zero rsum
// ---------------------------------------------------------------------------
__global__ void __launch_bounds__(256)
prep_all(const float* __restrict__ X,
         const float* __restrict__ Wq, const float* __restrict__ Wk,
         const float* __restrict__ Wvd, const float* __restrict__ Wvu,
         __nv_bfloat16* __restrict__ Xh, __nv_bfloat16* __restrict__ Xl,
         __nv_bfloat16* __restrict__ WqTh, __nv_bfloat16* __restrict__ WqTl,
         __nv_bfloat16* __restrict__ WkTh, __nv_bfloat16* __restrict__ WkTl,
         __nv_bfloat16* __restrict__ WvdTh, __nv_bfloat16* __restrict__ WvdTl,
         __nv_bfloat16* __restrict__ WvuTh, __nv_bfloat16* __restrict__ WvuTl,
         float* __restrict__ rsum)
{
    const int b = blockIdx.x;
    const int tid = threadIdx.x;

    if (b < 16384) {                       // ---- X split (exact: 16384*256 = n4)
        int i = b * 256 + tid;
        float4 v = ((const float4*)X)[i];
        __nv_bfloat16 h0 = __float2bfloat16(v.x), h1 = __float2bfloat16(v.y);
        __nv_bfloat16 h2 = __float2bfloat16(v.z), h3 = __float2bfloat16(v.w);
        __nv_bfloat16 l0 = __float2bfloat16(v.x - __bfloat162float(h0));
        __nv_bfloat16 l1 = __float2bfloat16(v.y - __bfloat162float(h1));
        __nv_bfloat16 l2 = __float2bfloat16(v.z - __bfloat162float(h2));
        __nv_bfloat16 l3 = __float2bfloat16(v.w - __bfloat162float(h3));
        ((__nv_bfloat162*)Xh)[i * 2 + 0] = __nv_bfloat162(h0, h1);
        ((__nv_bfloat162*)Xh)[i * 2 + 1] = __nv_bfloat162(h2, h3);
        ((__nv_bfloat162*)Xl)[i * 2 + 0] = __nv_bfloat162(l0, l1);
        ((__nv_bfloat162*)Xl)[i * 2 + 1] = __nv_bfloat162(l2, l3);
        return;
    }
    if (b < 16384 + 1024) {                // ---- weight transpose+split
        const int t = b - 16384;
        const int w = t >> 8;              // 0=Wq 1=Wk 2=Wvd 3=Wvu
        const int s = t & 255;
        const float* src; __nv_bfloat16 *dh, *dl;
        int M, N, gx, gy;
        if (w < 3) {                       // [EE, DD] -> [DD, EE]
            M = EE; N = DD; gx = s & 7; gy = s >> 3;
            src = (w == 0) ? Wq : (w == 1) ? Wk : Wvd;
            dh = (w == 0) ? WqTh : (w == 1) ? WkTh : WvdTh;
            dl = (w == 0) ? WqTl : (w == 1) ? WkTl : WvdTl;
        } else {                           // [DD, EE] -> [EE, DD]
            M = DD; N = EE; gx = s & 31; gy = s >> 5;
            src = Wvu; dh = WvuTh; dl = WvuTl;
        }
        __shared__ float tb[32][33];
        const int bx = gx * 32, by = gy * 32;
        const int x = tid & 31, y = tid >> 5;     // 32x8
#pragma unroll
        for (int i = 0; i < 32; i += 8)
            tb[y + i][x] = src[(size_t)(by + y + i) * N + bx + x];
        __syncthreads();
#pragma unroll
        for (int i = 0; i < 32; i += 8) {
            float v = tb[x][y + i];
            __nv_bfloat16 h = __float2bfloat16(v);
            dh[(size_t)(bx + y + i) * M + by + x] = h;
            dl[(size_t)(bx + y + i) * M + by + x] =
                __float2bfloat16(v - __bfloat162float(h));
        }
        return;
    }
    {                                      // ---- zero rsum (16 blocks x 256 float4)
        const int t = b - (16384 + 1024);
        int i = t * 256 + tid;             // over BB*NN/4 = 4096 float4
        ((float4*)rsum)[i] = make_float4(0.f, 0.f, 0.f, 0.f);
    }
}

// ---------------------------------------------------------------------------
extern "C" void kernel_launch(void* const* d_in, const int* in_sizes, int n_in,
                              void* d_out, int out_size)
{
    (void)in_sizes; (void)n_in; (void)out_size;
    const float* X   = (const float*)d_in[0];
    const float* Wq  = (const float*)d_in[1];
    const float* Wk  = (const float*)d_in[2];
    const float* Wvd = (const float*)d_in[3];
    const float* Wvu = (const float*)d_in[4];
    float* out = (float*)d_out;

    __nv_bfloat16 *pXh, *pXl, *pQh, *pQl, *pKh, *pKl, *pVdTh, *pVdTl, *pTh, *pTl;
    __nv_bfloat16 *pWqTh, *pWqTl, *pWkTh, *pWkTl, *pWvdTh, *pWvdTl, *pWvuTh, *pWvuTl;
    __nv_bfloat16 *pPh, *pPl;
    float *pTp0, *pTp1, *pRs;
    cudaGetSymbolAddress((void**)&pXh, g_Xh);     cudaGetSymbolAddress((void**)&pXl, g_Xl);
    cudaGetSymbolAddress((void**)&pQh, g_Qh);     cudaGetSymbolAddress((void**)&pQl, g_Ql);
    cudaGetSymbolAddress((void**)&pKh, g_Kh);     cudaGetSymbolAddress((void**)&pKl, g_Kl);
    cudaGetSymbolAddress((void**)&pVdTh, g_VdTh); cudaGetSymbolAddress((void**)&pVdTl, g_VdTl);
    cudaGetSymbolAddress((void**)&pTh, g_Th);     cudaGetSymbolAddress((void**)&pTl, g_Tl);
    cudaGetSymbolAddress((void**)&pTp0, g_Tp0);   cudaGetSymbolAddress((void**)&pTp1, g_Tp1);
    cudaGetSymbolAddress((void**)&pRs, g_rsum);
    cudaGetSymbolAddress((void**)&pWqTh, g_WqTh); cudaGetSymbolAddress((void**)&pWqTl, g_WqTl);
    cudaGetSymbolAddress((void**)&pWkTh, g_WkTh); cudaGetSymbolAddress((void**)&pWkTl, g_WkTl);
    cudaGetSymbolAddress((void**)&pWvdTh, g_WvdTh); cudaGetSymbolAddress((void**)&pWvdTl, g_WvdTl);
    cudaGetSymbolAddress((void**)&pWvuTh, g_WvuTh); cudaGetSymbolAddress((void**)&pWvuTl, g_WvuTl);
    cudaGetSymbolAddress((void**)&pPh, g_Ph);     cudaGetSymbolAddress((void**)&pPl, g_Pl);

    cudaFuncSetAttribute(mma_gemm_qkv,
                         cudaFuncAttributeMaxDynamicSharedMemorySize, SMEM_B);
    cudaFuncSetAttribute(mma_gemm_sexp,
                         cudaFuncAttributeMaxDynamicSharedMemorySize, SMEM_B);
    cudaFuncSetAttribute(mma_gemm_tsplit,
                         cudaFuncAttributeMaxDynamicSharedMemorySize, SMEM_B);
    cudaFuncSetAttribute(mma_gemm_out,
                         cudaFuncAttributeMaxDynamicSharedMemorySize, SMEM_B);

    const dim3 blk(128);
    const dim3 pblk(256);

    // 0) merged prep: X split + 4 weight transposes + rsum zero, one launch
    prep_all<<<16384 + 1024 + 16, pblk>>>(
        X, Wq, Wk, Wvd, Wvu, pXh, pXl,
        pWqTh, pWqTl, pWkTh, pWkTl, pWvdTh, pWvdTl, pWvuTh, pWvuTl, pRs);

    // 1) merged Q/K/VdT projection
    mma_gemm_qkv<<<dim3(2, 128, 3), blk, SMEM_B>>>(
        pXh, pXl, pWqTh, pWqTl, pWkTh, pWkTl, pWvdTh, pWvdTl,
        pQh, pQl, pKh, pKl, pVdTh, pVdTl);

    // 2) S = Q@K^T/16 with fused quirk+exp+rowsum epilogue
    mma_gemm_sexp<<<dim3(32, 32, BB), blk, SMEM_B>>>(
        pQh, pQl, pKh, pKl, pPh, pPl, pRs);

    // 3) T partials = exp(S) @ Vd, split-K halves, big-K CTAs first
    mma_gemm_tsplit<<<dim3(2, 32, BB * 2), blk, SMEM_B>>>(
        pPh, pPl, pVdTh, pVdTl, pTp0, pTp1);

    // 4) combine + normalize -> Th/Tl
    combine_T<<<(BB * NN * DD / 4) / 256, pblk>>>(pTp0, pTp1, pRs, pTh, pTl);

    // 5) out = T @ Wvu
    mma_gemm_out<<<dim3(8, 128, 1), blk, SMEM_B>>>(
        pTh, pTl, pWvuTh, pWvuTl, out);
}

// round 12
// speedup vs baseline: 6.6871x; 1.0434x over previous
#include <cuda_runtime.h>
#include <cuda_bf16.h>
#include <cuda_fp16.h>
#include <math.h>
#include <stdint.h>

// Problem shape (fixed)
#define BB 4
#define NN 4096
#define EE 1024
#define DD 256
#define NEG_FILL (-3.402823466385288598e+38f)

// ---------------- scratch (static device globals; no allocs) ----------------
__device__ __half         g_Xh  [(size_t)BB * NN * EE];
__device__ __half         g_Xl  [(size_t)BB * NN * EE];
__device__ __half         g_Qh  [(size_t)BB * NN * DD];
__device__ __half         g_Ql  [(size_t)BB * NN * DD];
__device__ __half         g_Kh  [(size_t)BB * NN * DD];
__device__ __half         g_Kl  [(size_t)BB * NN * DD];
__device__ __nv_bfloat16  g_VdTh[(size_t)DD * BB * NN];  // (X@Wvd)^T bf16 (tsplit B)
__device__ __nv_bfloat16  g_VdTl[(size_t)DD * BB * NN];
__device__ __half         g_Th  [(size_t)BB * NN * DD];  // T = softmax(S)@Vd (f16)
__device__ __half         g_Tl  [(size_t)BB * NN * DD];
__device__ float          g_Tp0 [(size_t)BB * NN * DD];  // T split-K partials (f32)
__device__ float          g_Tp1 [(size_t)BB * NN * DD];
__device__ float          g_rsum[(size_t)BB * NN];       // unnormalized row sums
__device__ __half         g_WqTh[(size_t)DD * EE];
__device__ __half         g_WqTl[(size_t)DD * EE];
__device__ __half         g_WkTh[(size_t)DD * EE];
__device__ __half         g_WkTl[(size_t)DD * EE];
__device__ __half         g_WvdTh[(size_t)DD * EE];
__device__ __half         g_WvdTl[(size_t)DD * EE];
__device__ __half         g_WvuTh[(size_t)EE * DD];
__device__ __half         g_WvuTl[(size_t)EE * DD];
__device__ __nv_bfloat16  g_Ph  [(size_t)BB * NN * NN];  // unnormalized exp(S) hi
__device__ __nv_bfloat16  g_Pl  [(size_t)BB * NN * NN];  // unnormalized exp(S) lo

// ---------------- helpers ----------------
__device__ __forceinline__ uint32_t smem_u32(const void* p) {
    uint32_t a;
    asm("{ .reg .u64 t; cvta.to.shared.u64 t, %1; cvt.u32.u64 %0, t; }"
        : "=r"(a) : "l"(p));
    return a;
}
__device__ __forceinline__ void ldsm4(uint32_t* r, uint32_t a) {
    asm volatile("ldmatrix.sync.aligned.m8n8.x4.shared.b16 {%0,%1,%2,%3}, [%4];"
                 : "=r"(r[0]), "=r"(r[1]), "=r"(r[2]), "=r"(r[3]) : "r"(a));
}
// bf16 MMA (tsplit path)
__device__ __forceinline__ void mma_bf16(float* d, const uint32_t* a, const uint32_t* b) {
    asm volatile(
        "mma.sync.aligned.m16n8k16.row.col.f32.bf16.bf16.f32 "
        "{%0,%1,%2,%3}, {%4,%5,%6,%7}, {%8,%9}, {%0,%1,%2,%3};"
        : "+f"(d[0]), "+f"(d[1]), "+f"(d[2]), "+f"(d[3])
        : "r"(a[0]), "r"(a[1]), "r"(a[2]), "r"(a[3]), "r"(b[0]), "r"(b[1]));
}
// f16 x f16 -> f32 accum (main term)
__device__ __forceinline__ void mma_f16f32(float* d, const uint32_t* a, const uint32_t* b) {
    asm volatile(
        "mma.sync.aligned.m16n8k16.row.col.f32.f16.f16.f32 "
        "{%0,%1,%2,%3}, {%4,%5,%6,%7}, {%8,%9}, {%0,%1,%2,%3};"
        : "+f"(d[0]), "+f"(d[1]), "+f"(d[2]), "+f"(d[3])
        : "r"(a[0]), "r"(a[1]), "r"(a[2]), "r"(a[3]), "r"(b[0]), "r"(b[1]));
}
// f16 x f16 -> f16 accum (correction terms, full-rate hypothesis)
__device__ __forceinline__ void mma_f16f16(uint32_t* d, const uint32_t* a, const uint32_t* b) {
    asm volatile(
        "mma.sync.aligned.m16n8k16.row.col.f16.f16.f16.f16 "
        "{%0,%1}, {%2,%3,%4,%5}, {%6,%7}, {%0,%1};"
        : "+r"(d[0]), "+r"(d[1])
        : "r"(a[0]), "r"(a[1]), "r"(a[2]), "r"(a[3]), "r"(b[0]), "r"(b[1]));
}
__device__ __forceinline__ void cp16(uint32_t saddr, const void* gaddr) {
    asm volatile("cp.async.cg.shared.global [%0], [%1], 16;"
                 :: "r"(saddr), "l"(gaddr) : "memory");
}
#define CP_COMMIT() asm volatile("cp.async.commit_group;" ::: "memory")
#define CP_WAIT1()  asm volatile("cp.async.wait_group 1;" ::: "memory")

// swizzled offset within a Nx32-elem 16-bit tile (rows of 64B, 4x16B chunks)
__device__ __forceinline__ uint32_t tswz(int row, int chunk) {
    return (uint32_t)(row * 64 + ((chunk ^ ((row >> 1) & 3)) << 4));
}

// ===========================================================================
// f16 GEMM core: CTA tile 128x64, 4 warps (2x2) of 64x32, K-slab 32.
// Main term -> f32 accum; corrections (hi*lo + lo*hi) -> shared f16 accum.
// 3-stage cp.async ring. ~164 regs -> occupancy 3 (12 warps/SM).
// ===========================================================================
#define F16_AT   8192                 // A tile 128x64B
#define F16_BT   4096                 // B tile 64x64B
#define F16_STAGE (2 * F16_AT + 2 * F16_BT)   // 24576
#define F16_SMEM (3 * F16_STAGE)              // 73728

__device__ __forceinline__ void gemm_core_f16(
    const __half* __restrict__ Ah, const __half* __restrict__ Al,
    const __half* __restrict__ Bh, const __half* __restrict__ Bl,
    int m0, int n0, int ldA, int ldB, int numIt, char* sm,
    float accF[4][4][4], uint32_t accC[4][4][2])
{
    const int tid = threadIdx.x;
    const int lane = tid & 31;
    const int wid = tid >> 5;
    const int wm = wid >> 1;        // 0..1
    const int wn = wid & 1;         // 0..1

    auto issue = [&](int stage, int it) {
        char* st = sm + stage * F16_STAGE;
        const int k0 = it << 5;
#pragma unroll
        for (int j = 0; j < 6; j++) {
            int idx = tid + j * 128;            // 0..767
            int row = idx >> 2, c = idx & 3;
            if (row < 128) {                    // A rows (j = 0..3 exactly)
                uint32_t off = tswz(row, c);
                uint32_t s0 = smem_u32(st) + off;
                cp16(s0,           Ah + (size_t)(m0 + row) * ldA + k0 + c * 8);
                cp16(s0 + F16_AT,  Al + (size_t)(m0 + row) * ldA + k0 + c * 8);
            } else {                            // B rows (j = 4..5)
                int r2 = row - 128;
                uint32_t off = tswz(r2, c);
                uint32_t s0 = smem_u32(st) + 2 * F16_AT + off;
                cp16(s0,           Bh + (size_t)(n0 + r2) * ldB + k0 + c * 8);
                cp16(s0 + F16_BT,  Bl + (size_t)(n0 + r2) * ldB + k0 + c * 8);
            }
        }
    };

    issue(0, 0); CP_COMMIT();
    if (numIt > 1) issue(1, 1);
    CP_COMMIT();

    for (int it = 0; it < numIt; ++it) {
        CP_WAIT1();
        __syncthreads();
        if (it + 2 < numIt) issue((it + 2) % 3, it + 2);
        CP_COMMIT();

        char* st = sm + (it % 3) * F16_STAGE;
        const uint32_t bAh = smem_u32(st);
        const uint32_t bAl = bAh + F16_AT;
        const uint32_t bBh = bAh + 2 * F16_AT;
        const uint32_t bBl = bBh + F16_BT;

#pragma unroll
        for (int ks = 0; ks < 2; ks++) {
            uint32_t ah[4][4], al[4][4], bh[4][2], bl[4][2];
            const int arow = wm * 64 + (lane & 15);
            const int ac = ks * 2 + (lane >> 4);
#pragma unroll
            for (int mf = 0; mf < 4; mf++) {
                uint32_t o = tswz(arow + mf * 16, ac);
                ldsm4(ah[mf], bAh + o);
                ldsm4(al[mf], bAl + o);
            }
            // paired B ldsm4: covers nf even/odd per instruction
            const int brow = wn * 32 + ((lane >> 4) & 1) * 8 + (lane & 7);
            const int bc = ks * 2 + ((lane >> 3) & 1);
#pragma unroll
            for (int nfp = 0; nfp < 2; nfp++) {
                uint32_t o = tswz(brow + nfp * 16, bc);
                uint32_t t4[4];
                ldsm4(t4, bBh + o);
                bh[2 * nfp][0] = t4[0]; bh[2 * nfp][1] = t4[1];
                bh[2 * nfp + 1][0] = t4[2]; bh[2 * nfp + 1][1] = t4[3];
                ldsm4(t4, bBl + o);
                bl[2 * nfp][0] = t4[0]; bl[2 * nfp][1] = t4[1];
                bl[2 * nfp + 1][0] = t4[2]; bl[2 * nfp + 1][1] = t4[3];
            }
#pragma unroll
            for (int mf = 0; mf < 4; mf++)
#pragma unroll
                for (int nf = 0; nf < 4; nf++) {
                    mma_f16f32(accF[mf][nf], ah[mf], bh[nf]);   // main, f32 acc
                    mma_f16f16(accC[mf][nf], ah[mf], bl[nf]);   // corr, f16 acc
                    mma_f16f16(accC[mf][nf], al[mf], bh[nf]);   // corr, f16 acc
                }
        }
    }
}

// final value of fragment element k (0..3) for (mf,nf)
__device__ __forceinline__ float f16v(const float* aF, const uint32_t* aC, int k) {
    __half2 c = *(const __half2*)&aC[k >> 1];
    float corr = (k & 1) ? __high2float(c) : __low2float(c);
    return aF[k] + corr;
}

// ===========================================================================
// bf16 GEMM core (tsplit only): CTA 128x128, 4 warps of 64x64 (R10 layout)
// ===========================================================================
#define BF_TILE  8192
#define BF_STAGE (4 * BF_TILE)
#define BF_SMEM  (3 * BF_STAGE)

__device__ __forceinline__ void gemm_core_bf(
    const __nv_bfloat16* __restrict__ Ah, const __nv_bfloat16* __restrict__ Al,
    const __nv_bfloat16* __restrict__ Bh, const __nv_bfloat16* __restrict__ Bl,
    int m0, int n0, int ldA, int ldB, int numIt, char* sm,
    float acc[4][8][4])
{
    const int tid = threadIdx.x;
    const int lane = tid & 31;
    const int wid = tid >> 5;
    const int wm = wid >> 1;
    const int wn = wid & 1;

    auto issue = [&](int stage, int it) {
        char* st = sm + stage * BF_STAGE;
        const int k0 = it << 5;
#pragma unroll
        for (int j = 0; j < 4; j++) {
            int idx = tid + j * 128;
            int row = idx >> 2, c = idx & 3;
            uint32_t off = tswz(row, c);
            uint32_t s0 = smem_u32(st) + off;
            cp16(s0,               Ah + (size_t)(m0 + row) * ldA + k0 + c * 8);
            cp16(s0 + BF_TILE,     Al + (size_t)(m0 + row) * ldA + k0 + c * 8);
            cp16(s0 + 2 * BF_TILE, Bh + (size_t)(n0 + row) * ldB + k0 + c * 8);
            cp16(s0 + 3 * BF_TILE, Bl + (size_t)(n0 + row) * ldB + k0 + c * 8);
        }
    };

    issue(0, 0); CP_COMMIT();
    if (numIt > 1) issue(1, 1);
    CP_COMMIT();

    for (int it = 0; it < numIt; ++it) {
        CP_WAIT1();
        __syncthreads();
        if (it + 2 < numIt) issue((it + 2) % 3, it + 2);
        CP_COMMIT();

        char* st = sm + (it % 3) * BF_STAGE;
        const uint32_t bAh = smem_u32(st);
        const uint32_t bAl = bAh + BF_TILE;
        const uint32_t bBh = bAh + 2 * BF_TILE;
        const uint32_t bBl = bAh + 3 * BF_TILE;

#pragma unroll
        for (int ks = 0; ks < 2; ks++) {
            uint32_t ah[4][4], al[4][4], bh[8][2], bl[8][2];
            const int arow = wm * 64 + (lane & 15);
            const int ac = ks * 2 + (lane >> 4);
#pragma unroll
            for (int mf = 0; mf < 4; mf++) {
                uint32_t o = tswz(arow + mf * 16, ac);
                ldsm4(ah[mf], bAh + o);
                ldsm4(al[mf], bAl + o);
            }
            const int brow = wn * 64 + ((lane >> 4) & 1) * 8 + (lane & 7);
            const int bc = ks * 2 + ((lane >> 3) & 1);
#pragma unroll
            for (int nfp = 0; nfp < 4; nfp++) {
                uint32_t o = tswz(brow + nfp * 16, bc);
                uint32_t t4[4];
                ldsm4(t4, bBh + o);
                bh[2 * nfp][0] = t4[0]; bh[2 * nfp][1] = t4[1];
                bh[2 * nfp + 1][0] = t4[2]; bh[2 * nfp + 1][1] = t4[3];
                ldsm4(t4, bBl + o);
                bl[2 * nfp][0] = t4[0]; bl[2 * nfp][1] = t4[1];
                bl[2 * nfp + 1][0] = t4[2]; bl[2 * nfp + 1][1] = t4[3];
            }
#pragma unroll
            for (int mf = 0; mf < 4; mf++)
#pragma unroll
                for (int nf = 0; nf < 8; nf++) {
                    mma_bf16(acc[mf][nf], ah[mf], bh[nf]);
                    mma_bf16(acc[mf][nf], ah[mf], bl[nf]);
                    mma_bf16(acc[mf][nf], al[mf], bh[nf]);
                }
        }
    }
}

// ===========================================================================
// Kernels
// ===========================================================================

// Merged Q/K/Vd projection (f16 core). z=0:Q(f16) z=1:K(f16) z=2:VdT(bf16, CT)
__global__ void __launch_bounds__(128, 3)
mma_gemm_qkv(const __half* __restrict__ Xh, const __half* __restrict__ Xl,
             const __half* __restrict__ Bqh, const __half* __restrict__ Bql,
             const __half* __restrict__ Bkh, const __half* __restrict__ Bkl,
             const __half* __restrict__ Bvh, const __half* __restrict__ Bvl,
             __half* __restrict__ Qh, __half* __restrict__ Ql,
             __half* __restrict__ Kh, __half* __restrict__ Kl,
             __nv_bfloat16* __restrict__ Vh, __nv_bfloat16* __restrict__ Vl)
{
    const int m0 = blockIdx.y * 128;
    const int n0 = blockIdx.x * 64;
    const int z = blockIdx.z;

    const __half* Bh = (z == 0) ? Bqh : (z == 1) ? Bkh : Bvh;
    const __half* Bl = (z == 0) ? Bql : (z == 1) ? Bkl : Bvl;

    extern __shared__ char sm[];
    float accF[4][4][4] = {};
    uint32_t accC[4][4][2] = {};
    gemm_core_f16(Xh, Xl, Bh, Bl, m0, n0, EE, EE, EE >> 5, sm, accF, accC);

    const int lane = threadIdx.x & 31;
    const int wid = threadIdx.x >> 5;
    const int wm = wid >> 1, wn = wid & 1;
    const int g = lane >> 2, t2 = (lane & 3) * 2;
#pragma unroll
    for (int mf = 0; mf < 4; mf++)
#pragma unroll
        for (int nf = 0; nf < 4; nf++) {
            const int r0 = m0 + wm * 64 + mf * 16 + g;
            const int c0 = n0 + wn * 32 + nf * 8 + t2;
#pragma unroll
            for (int h = 0; h < 2; h++) {
                const int r = r0 + h * 8;
                float v0 = f16v(accF[mf][nf], accC[mf][nf], h * 2 + 0);
                float v1 = f16v(accF[mf][nf], accC[mf][nf], h * 2 + 1);
                if (z < 2) {
                    __half* Ch = (z == 0) ? Qh : Kh;
                    __half* Cl = (z == 0) ? Ql : Kl;
                    __half h0 = __float2half_rn(v0);
                    __half h1 = __float2half_rn(v1);
                    __half l0 = __float2half_rn(v0 - __half2float(h0));
                    __half l1 = __float2half_rn(v1 - __half2float(h1));
                    *(__half2*)(Ch + (size_t)r * DD + c0) = __half2(h0, h1);
                    *(__half2*)(Cl + (size_t)r * DD + c0) = __half2(l0, l1);
                } else {
                    __nv_bfloat16 h0 = __float2bfloat16(v0);
                    __nv_bfloat16 h1 = __float2bfloat16(v1);
                    __nv_bfloat16 l0 = __float2bfloat16(v0 - __bfloat162float(h0));
                    __nv_bfloat16 l1 = __float2bfloat16(v1 - __bfloat162float(h1));
                    Vh[(size_t)c0 * (BB * NN) + r] = h0;
                    Vh[(size_t)(c0 + 1) * (BB * NN) + r] = h1;
                    Vl[(size_t)c0 * (BB * NN) + r] = l0;
                    Vl[(size_t)(c0 + 1) * (BB * NN) + r] = l1;
                }
            }
        }
}

// S GEMM (f16 core) with fused quirk + exp + row-sum epilogue; P out in bf16.
__global__ void __launch_bounds__(128, 3)
mma_gemm_sexp(const __half* __restrict__ Qh, const __half* __restrict__ Ql,
              const __half* __restrict__ Kh, const __half* __restrict__ Kl,
              __nv_bfloat16* __restrict__ Ph, __nv_bfloat16* __restrict__ Pl,
              float* __restrict__ rsum)
{
    const int m0 = blockIdx.y * 128;
    const int n0 = blockIdx.x * 64;
    if (n0 > m0 + 127) return;          // fully masked tile
    const int z = blockIdx.z;

    const __half* Ah = Qh + (size_t)z * NN * DD;
    const __half* Al = Ql + (size_t)z * NN * DD;
    const __half* Bh = Kh + (size_t)z * NN * DD;
    const __half* Bl = Kl + (size_t)z * NN * DD;
    Ph += (size_t)z * NN * NN;
    Pl += (size_t)z * NN * NN;
    rsum += (size_t)z * NN;

    extern __shared__ char sm[];
    float accF[4][4][4] = {};
    uint32_t accC[4][4][2] = {};
    gemm_core_f16(Ah, Al, Bh, Bl, m0, n0, DD, DD, DD >> 5, sm, accF, accC);

    const int lane = threadIdx.x & 31;
    const int wid = threadIdx.x >> 5;
    const int wm = wid >> 1, wn = wid & 1;
    const int g = lane >> 2, t2 = (lane & 3) * 2;
    const float alpha = 1.0f / 16.0f;

#pragma unroll
    for (int mf = 0; mf < 4; mf++) {
#pragma unroll
        for (int h = 0; h < 2; h++) {
            const int row = m0 + wm * 64 + mf * 16 + g + h * 8;
            float rs = 0.0f;
#pragma unroll
            for (int nf = 0; nf < 4; nf++) {
                const int col = n0 + wn * 32 + nf * 8 + t2;
                float s0 = f16v(accF[mf][nf], accC[mf][nf], h * 2 + 0) * alpha;
                float s1 = f16v(accF[mf][nf], accC[mf][nf], h * 2 + 1) * alpha;
                float e0 = (col > row) ? 0.0f
                           : expf((s0 != 0.0f) ? s0 : NEG_FILL);
                float e1 = (col + 1 > row) ? 0.0f
                           : expf((s1 != 0.0f) ? s1 : NEG_FILL);
                rs += e0 + e1;
                __nv_bfloat16 h0 = __float2bfloat16(e0);
                __nv_bfloat16 h1 = __float2bfloat16(e1);
                __nv_bfloat16 l0 = __float2bfloat16(e0 - __bfloat162float(h0));
                __nv_bfloat16 l1 = __float2bfloat16(e1 - __bfloat162float(h1));
                *(__nv_bfloat162*)(Ph + (size_t)row * NN + col) = __nv_bfloat162(h0, h1);
                *(__nv_bfloat162*)(Pl + (size_t)row * NN + col) = __nv_bfloat162(l0, l1);
            }
            rs += __shfl_xor_sync(0xffffffff, rs, 1);
            rs += __shfl_xor_sync(0xffffffff, rs, 2);
            if ((lane & 3) == 0) atomicAdd(&rsum[row], rs);
        }
    }
}

// T GEMM (bf16 core, unchanged R10 config), split-K halves, big-K first.
__global__ void __launch_bounds__(128, 2)
mma_gemm_tsplit(const __nv_bfloat16* __restrict__ Ph, const __nv_bfloat16* __restrict__ Pl,
                const __nv_bfloat16* __restrict__ Vh, const __nv_bfloat16* __restrict__ Vl,
                float* __restrict__ Tp0, float* __restrict__ Tp1)
{
    const int by = gridDim.y - 1 - blockIdx.y;
    const int m0 = by * 128;
    const int n0 = blockIdx.x * 128;
    const int batch = blockIdx.z >> 1;
    const int half = blockIdx.z & 1;

    const int kEnd = m0 + 128;
    const int kh = kEnd >> 1;
    const int ks = half ? kh : 0;
    const int ke = half ? kEnd : kh;

    const __nv_bfloat16* Ah = Ph + (size_t)batch * NN * NN + ks;
    const __nv_bfloat16* Al = Pl + (size_t)batch * NN * NN + ks;
    const __nv_bfloat16* Bh = Vh + (size_t)batch * NN + ks;
    const __nv_bfloat16* Bl = Vl + (size_t)batch * NN + ks;
    float* Tp = (half ? Tp1 : Tp0) + (size_t)batch * NN * DD;

    extern __shared__ char sm[];
    float acc[4][8][4] = {};
    gemm_core_bf(Ah, Al, Bh, Bl, m0, n0, NN, BB * NN, (ke - ks) >> 5, sm, acc);

    const int lane = threadIdx.x & 31;
    const int wid = threadIdx.x >> 5;
    const int wm = wid >> 1, wn = wid & 1;
    const int g = lane >> 2, t2 = (lane & 3) * 2;
#pragma unroll
    for (int mf = 0; mf < 4; mf++)
#pragma unroll
        for (int nf = 0; nf < 8; nf++) {
            const float* a = acc[mf][nf];
            const int r0 = m0 + wm * 64 + mf * 16 + g;
            const int c0 = n0 + wn * 64 + nf * 8 + t2;
#pragma unroll
            for (int h = 0; h < 2; h++) {
                const int r = r0 + h * 8;
                *(float2*)(Tp + (size_t)r * DD + c0) =
                    make_float2(a[h * 2], a[h * 2 + 1]);
            }
        }
}

// Combine T partials, normalize, emit f16 hi/lo.
__global__ void __launch_bounds__(256)
combine_T(const float* __restrict__ p0, const float* __restrict__ p1,
          const float* __restrict__ rsum,
          __half* __restrict__ Th, __half* __restrict__ Tl)
{
    int i = blockIdx.x * 256 + threadIdx.x;          // over (BB*NN*DD)/4
    float4 a = ((const float4*)p0)[i];
    float4 b = ((const float4*)p1)[i];
    const float inv = 1.0f / rsum[i >> 6];           // row = (i*4)/DD
    float v0 = (a.x + b.x) * inv, v1 = (a.y + b.y) * inv;
    float v2 = (a.z + b.z) * inv, v3 = (a.w + b.w) * inv;
    __half h0 = __float2half_rn(v0), h1 = __float2half_rn(v1);
    __half h2 = __float2half_rn(v2), h3 = __float2half_rn(v3);
    __half l0 = __float2half_rn(v0 - __half2float(h0));
    __half l1 = __float2half_rn(v1 - __half2float(h1));
    __half l2 = __float2half_rn(v2 - __half2float(h2));
    __half l3 = __float2half_rn(v3 - __half2float(h3));
    ((__half2*)Th)[i * 2 + 0] = __half2(h0, h1);
    ((__half2*)Th)[i * 2 + 1] = __half2(h2, h3);
    ((__half2*)Tl)[i * 2 + 0] = __half2(l0, l1);
    ((__half2*)Tl)[i * 2 + 1] = __half2(l2, l3);
}

// out = T @ Wvu (f16 core), f32 out
__global__ void __launch_bounds__(128, 3)
mma_gemm_out(const __half* __restrict__ Ah, const __half* __restrict__ Al,
             const __half* __restrict__ Bh, const __half* __restrict__ Bl,
             float* __restrict__ Cf)
{
    const int m0 = blockIdx.y * 128;
    const int n0 = blockIdx.x * 64;
    extern __shared__ char sm[];
    float accF[4][4][4] = {};
    uint32_t accC[4][4][2] = {};
    gemm_core_f16(Ah, Al, Bh, Bl, m0, n0, DD, DD, DD >> 5, sm, accF, accC);

    const int lane = threadIdx.x & 31;
    const int wid = threadIdx.x >> 5;
    const int wm = wid >> 1, wn = wid & 1;
    const int g = lane >> 2, t2 = (lane & 3) * 2;
#pragma unroll
    for (int mf = 0; mf < 4; mf++)
#pragma unroll
        for (int nf = 0; nf < 4; nf++) {
            const int r0 = m0 + wm * 64 + mf * 16 + g;
            const int c0 = n0 + wn * 32 + nf * 8 + t2;
#pragma unroll
            for (int h = 0; h < 2; h++) {
                const int r = r0 + h * 8;
                *(float2*)(Cf + (size_t)r * EE + c0) = make_float2(
                    f16v(accF[mf][nf], accC[mf][nf], h * 2 + 0),
                    f16v(accF[mf][nf], accC[mf][nf], h * 2 + 1));
            }
        }
}

// Merged prep kernel: X f16 split + 4 weight transpose/f16-splits + rsum zero.
__global__ void __launch_bounds__(256)
prep_all(const float* __restrict__ X,
         const float* __restrict__ Wq, const float* __restrict__ Wk,
         const float* __restrict__ Wvd, const float* __restrict__ Wvu,
         __half* __restrict__ Xh, __half* __restrict__ Xl,
         __half* __restrict__ WqTh, __half* __restrict__ WqTl,
         __half* __restrict__ WkTh, __half* __restrict__ WkTl,
         __half* __restrict__ WvdTh, __half* __restrict__ WvdTl,
         __half* __restrict__ WvuTh, __half* __restrict__ WvuTl,
         float* __restrict__ rsum)
{
    const int b = blockIdx.x;
    const int tid = threadIdx.x;

    if (b < 16384) {                       // ---- X split
        int i = b * 256 + tid;
        float4 v = ((const float4*)X)[i];
        __half h0 = __float2half_rn(v.x), h1 = __float2half_rn(v.y);
        __half h2 = __float2half_rn(v.z), h3 = __float2half_rn(v.w);
        __half l0 = __float2half_rn(v.x - __half2float(h0));
        __half l1 = __float2half_rn(v.y - __half2float(h1));
        __half l2 = __float2half_rn(v.z - __half2float(h2));
        __half l3 = __float2half_rn(v.w - __half2float(h3));
        ((__half2*)Xh)[i * 2 + 0] = __half2(h0, h1);
        ((__half2*)Xh)[i * 2 + 1] = __half2(h2, h3);
        ((__half2*)Xl)[i * 2 + 0] = __half2(l0, l1);
        ((__half2*)Xl)[i * 2 + 1] = __half2(l2, l3);
        return;
    }
    if (b < 16384 + 1024) {                // ---- weight transpose + f16 split
        const int t = b - 16384;
        const int w = t >> 8;
        const int s = t & 255;
        const float* src; __half *dh, *dl;
        int M, N, gx, gy;
        if (w < 3) {                       // [EE, DD] -> [DD, EE]
            M = EE; N = DD; gx = s & 7; gy = s >> 3;
            src = (w == 0) ? Wq : (w == 1) ? Wk : Wvd;
            dh = (w == 0) ? WqTh : (w == 1) ? WkTh : WvdTh;
            dl = (w == 0) ? WqTl : (w == 1) ? WkTl : WvdTl;
        } else {                           // [DD, EE] -> [EE, DD]
            M = DD; N = EE; gx = s & 31; gy = s >> 5;
            src = Wvu; dh = WvuTh; dl = WvuTl;
        }
        __shared__ float tb[32][33];
        const int bx = gx * 32, by = gy * 32;
        const int x = tid & 31, y = tid >> 5;
#pragma unroll
        for (int i = 0; i < 32; i += 8)
            tb[y + i][x] = src[(size_t)(by + y + i) * N + bx + x];
        __syncthreads();
#pragma unroll
        for (int i = 0; i < 32; i += 8) {
            float v = tb[x][y + i];
            __half h = __float2half_rn(v);
            dh[(size_t)(bx + y + i) * M + by + x] = h;
            dl[(size_t)(bx + y + i) * M + by + x] =
                __float2half_rn(v - __half2float(h));
        }
        return;
    }
    {                                      // ---- zero rsum
        const int t = b - (16384 + 1024);
        int i = t * 256 + tid;
        ((float4*)rsum)[i] = make_float4(0.f, 0.f, 0.f, 0.f);
    }
}

// ---------------------------------------------------------------------------
extern "C" void kernel_launch(void* const* d_in, const int* in_sizes, int n_in,
                              void* d_out, int out_size)
{
    (void)in_sizes; (void)n_in; (void)out_size;
    const float* X   = (const float*)d_in[0];
    const float* Wq  = (const float*)d_in[1];
    const float* Wk  = (const float*)d_in[2];
    const float* Wvd = (const float*)d_in[3];
    const float* Wvu = (const float*)d_in[4];
    float* out = (float*)d_out;

    __half *pXh, *pXl, *pQh, *pQl, *pKh, *pKl, *pTh, *pTl;
    __half *pWqTh, *pWqTl, *pWkTh, *pWkTl, *pWvdTh, *pWvdTl, *pWvuTh, *pWvuTl;
    __nv_bfloat16 *pVdTh, *pVdTl, *pPh, *pPl;
    float *pTp0, *pTp1, *pRs;
    cudaGetSymbolAddress((void**)&pXh, g_Xh);     cudaGetSymbolAddress((void**)&pXl, g_Xl);
    cudaGetSymbolAddress((void**)&pQh, g_Qh);     cudaGetSymbolAddress((void**)&pQl, g_Ql);
    cudaGetSymbolAddress((void**)&pKh, g_Kh);     cudaGetSymbolAddress((void**)&pKl, g_Kl);
    cudaGetSymbolAddress((void**)&pVdTh, g_VdTh); cudaGetSymbolAddress((void**)&pVdTl, g_VdTl);
    cudaGetSymbolAddress((void**)&pTh, g_Th);     cudaGetSymbolAddress((void**)&pTl, g_Tl);
    cudaGetSymbolAddress((void**)&pTp0, g_Tp0);   cudaGetSymbolAddress((void**)&pTp1, g_Tp1);
    cudaGetSymbolAddress((void**)&pRs, g_rsum);
    cudaGetSymbolAddress((void**)&pWqTh, g_WqTh); cudaGetSymbolAddress((void**)&pWqTl, g_WqTl);
    cudaGetSymbolAddress((void**)&pWkTh, g_WkTh); cudaGetSymbolAddress((void**)&pWkTl, g_WkTl);
    cudaGetSymbolAddress((void**)&pWvdTh, g_WvdTh); cudaGetSymbolAddress((void**)&pWvdTl, g_WvdTl);
    cudaGetSymbolAddress((void**)&pWvuTh, g_WvuTh); cudaGetSymbolAddress((void**)&pWvuTl, g_WvuTl);
    cudaGetSymbolAddress((void**)&pPh, g_Ph);     cudaGetSymbolAddress((void**)&pPl, g_Pl);

    cudaFuncSetAttribute(mma_gemm_qkv,
                         cudaFuncAttributeMaxDynamicSharedMemorySize, F16_SMEM);
    cudaFuncSetAttribute(mma_gemm_sexp,
                         cudaFuncAttributeMaxDynamicSharedMemorySize, F16_SMEM);
    cudaFuncSetAttribute(mma_gemm_out,
                         cudaFuncAttributeMaxDynamicSharedMemorySize, F16_SMEM);
    cudaFuncSetAttribute(mma_gemm_tsplit,
                         cudaFuncAttributeMaxDynamicSharedMemorySize, BF_SMEM);

    const dim3 blk(128);
    const dim3 pblk(256);

    // 0) merged prep
    prep_all<<<16384 + 1024 + 16, pblk>>>(
        X, Wq, Wk, Wvd, Wvu, pXh, pXl,
        pWqTh, pWqTl, pWkTh, pWkTl, pWvdTh, pWvdTl, pWvuTh, pWvuTl, pRs);

    // 1) merged Q/K/VdT projection (f16 core, 128x64 tiles)
    mma_gemm_qkv<<<dim3(4, 128, 3), blk, F16_SMEM>>>(
        pXh, pXl, pWqTh, pWqTl, pWkTh, pWkTl, pWvdTh, pWvdTl,
        pQh, pQl, pKh, pKl, pVdTh, pVdTl);

    // 2) S = Q@K^T/16 with fused quirk+exp+rowsum epilogue (f16 core)
    mma_gemm_sexp<<<dim3(64, 32, BB), blk, F16_SMEM>>>(
        pQh, pQl, pKh, pKl, pPh, pPl, pRs);

    // 3) T partials = exp(S) @ Vd (bf16 core), split-K halves, big-K first
    mma_gemm_tsplit<<<dim3(2, 32, BB * 2), blk, BF_SMEM>>>(
        pPh, pPl, pVdTh, pVdTl, pTp0, pTp1);

    // 4) combine + normalize -> Th/Tl (f16)
    combine_T<<<(BB * NN * DD / 4) / 256, pblk>>>(pTp0, pTp1, pRs, pTh, pTl);

    // 5) out = T @ Wvu (f16 core)
    mma_gemm_out<<<dim3(16, 128, 1), blk, F16_SMEM>>>(
        pTh, pTl, pWvuTh, pWvuTl, out);
}

// round 14
// speedup vs baseline: 6.8008x; 1.0170x over previous
#include <cuda_runtime.h>
#include <cuda_bf16.h>
#include <cuda_fp16.h>
#include <math.h>
#include <stdint.h>

// Problem shape (fixed)
#define BB 4
#define NN 4096
#define EE 1024
#define DD 256
#define NEG_FILL (-3.402823466385288598e+38f)
#define PSCALE     0.0009765625f     // 2^-10: P stored scaled so f16 holds exp(S)
#define PSCALE_INV 1024.0f

// ---------------- scratch (static device globals; no allocs) ----------------
__device__ __half g_Xh  [(size_t)BB * NN * EE];
__device__ __half g_Xl  [(size_t)BB * NN * EE];
__device__ __half g_Qh  [(size_t)BB * NN * DD];
__device__ __half g_Ql  [(size_t)BB * NN * DD];
__device__ __half g_Kh  [(size_t)BB * NN * DD];
__device__ __half g_Kl  [(size_t)BB * NN * DD];
__device__ __half g_VdTh[(size_t)DD * BB * NN];  // (X@Wvd)^T  [256, B*N]
__device__ __half g_VdTl[(size_t)DD * BB * NN];
__device__ __half g_Th  [(size_t)BB * NN * DD];  // T = softmax(S)@Vd
__device__ __half g_Tl  [(size_t)BB * NN * DD];
__device__ float  g_Tp0 [(size_t)BB * NN * DD];  // T split-K partials (f32)
__device__ float  g_Tp1 [(size_t)BB * NN * DD];
__device__ float  g_rsum[(size_t)BB * NN];       // unnormalized row sums
__device__ __half g_WqTh[(size_t)DD * EE];
__device__ __half g_WqTl[(size_t)DD * EE];
__device__ __half g_WkTh[(size_t)DD * EE];
__device__ __half g_WkTl[(size_t)DD * EE];
__device__ __half g_WvdTh[(size_t)DD * EE];
__device__ __half g_WvdTl[(size_t)DD * EE];
__device__ __half g_WvuTh[(size_t)EE * DD];
__device__ __half g_WvuTl[(size_t)EE * DD];
__device__ __half g_Ph  [(size_t)BB * NN * NN];  // exp(S) * PSCALE, hi
__device__ __half g_Pl  [(size_t)BB * NN * NN];  // exp(S) * PSCALE, lo

// ---------------- helpers ----------------
__device__ __forceinline__ uint32_t smem_u32(const void* p) {
    uint32_t a;
    asm("{ .reg .u64 t; cvta.to.shared.u64 t, %1; cvt.u32.u64 %0, t; }"
        : "=r"(a) : "l"(p));
    return a;
}
__device__ __forceinline__ void ldsm4(uint32_t* r, uint32_t a) {
    asm volatile("ldmatrix.sync.aligned.m8n8.x4.shared.b16 {%0,%1,%2,%3}, [%4];"
                 : "=r"(r[0]), "=r"(r[1]), "=r"(r[2]), "=r"(r[3]) : "r"(a));
}
// f16 x f16 -> f32 accum (main term)
__device__ __forceinline__ void mma_f16f32(float* d, const uint32_t* a, const uint32_t* b) {
    asm volatile(
        "mma.sync.aligned.m16n8k16.row.col.f32.f16.f16.f32 "
        "{%0,%1,%2,%3}, {%4,%5,%6,%7}, {%8,%9}, {%0,%1,%2,%3};"
        : "+f"(d[0]), "+f"(d[1]), "+f"(d[2]), "+f"(d[3])
        : "r"(a[0]), "r"(a[1]), "r"(a[2]), "r"(a[3]), "r"(b[0]), "r"(b[1]));
}
// f16 x f16 -> f16 accum (correction terms)
__device__ __forceinline__ void mma_f16f16(uint32_t* d, const uint32_t* a, const uint32_t* b) {
    asm volatile(
        "mma.sync.aligned.m16n8k16.row.col.f16.f16.f16.f16 "
        "{%0,%1}, {%2,%3,%4,%5}, {%6,%7}, {%0,%1};"
        : "+r"(d[0]), "+r"(d[1])
        : "r"(a[0]), "r"(a[1]), "r"(a[2]), "r"(a[3]), "r"(b[0]), "r"(b[1]));
}
__device__ __forceinline__ void cp16(uint32_t saddr, const void* gaddr) {
    asm volatile("cp.async.cg.shared.global [%0], [%1], 16;"
                 :: "r"(saddr), "l"(gaddr) : "memory");
}
#define CP_COMMIT() asm volatile("cp.async.commit_group;" ::: "memory")
#define CP_WAIT1()  asm volatile("cp.async.wait_group 1;" ::: "memory")

// swizzled offset within a Nx32-elem 16-bit tile (rows of 64B, 4x16B chunks)
__device__ __forceinline__ uint32_t tswz(int row, int chunk) {
    return (uint32_t)(row * 64 + ((chunk ^ ((row >> 1) & 3)) << 4));
}

// ===========================================================================
// f16 GEMM core: CTA tile 128x64, 4 warps (2x2) of 64x32, K-slab 32.
// Main term -> f32 accum; corrections (hi*lo + lo*hi) -> shared f16 accum.
// 3-stage cp.async ring.
// ===========================================================================
#define F16_AT   8192                 // A tile 128x64B
#define F16_BT   4096                 // B tile 64x64B
#define F16_STAGE (2 * F16_AT + 2 * F16_BT)   // 24576
#define F16_SMEM (3 * F16_STAGE)              // 73728

__device__ __forceinline__ void gemm_core_f16(
    const __half* __restrict__ Ah, const __half* __restrict__ Al,
    const __half* __restrict__ Bh, const __half* __restrict__ Bl,
    int m0, int n0, int ldA, int ldB, int numIt, char* sm,
    float accF[4][4][4], uint32_t accC[4][4][2])
{
    const int tid = threadIdx.x;
    const int lane = tid & 31;
    const int wid = tid >> 5;
    const int wm = wid >> 1;        // 0..1
    const int wn = wid & 1;         // 0..1

    auto issue = [&](int stage, int it) {
        char* st = sm + stage * F16_STAGE;
        const int k0 = it << 5;
#pragma unroll
        for (int j = 0; j < 6; j++) {
            int idx = tid + j * 128;            // 0..767
            int row = idx >> 2, c = idx & 3;
            if (row < 128) {                    // A rows (j = 0..3 exactly)
                uint32_t off = tswz(row, c);
                uint32_t s0 = smem_u32(st) + off;
                cp16(s0,           Ah + (size_t)(m0 + row) * ldA + k0 + c * 8);
                cp16(s0 + F16_AT,  Al + (size_t)(m0 + row) * ldA + k0 + c * 8);
            } else {                            // B rows (j = 4..5)
                int r2 = row - 128;
                uint32_t off = tswz(r2, c);
                uint32_t s0 = smem_u32(st) + 2 * F16_AT + off;
                cp16(s0,           Bh + (size_t)(n0 + r2) * ldB + k0 + c * 8);
                cp16(s0 + F16_BT,  Bl + (size_t)(n0 + r2) * ldB + k0 + c * 8);
            }
        }
    };

    issue(0, 0); CP_COMMIT();
    if (numIt > 1) issue(1, 1);
    CP_COMMIT();

    for (int it = 0; it < numIt; ++it) {
        CP_WAIT1();
        __syncthreads();
        if (it + 2 < numIt) issue((it + 2) % 3, it + 2);
        CP_COMMIT();

        char* st = sm + (it % 3) * F16_STAGE;
        const uint32_t bAh = smem_u32(st);
        const uint32_t bAl = bAh + F16_AT;
        const uint32_t bBh = bAh + 2 * F16_AT;
        const uint32_t bBl = bBh + F16_BT;

#pragma unroll
        for (int ks = 0; ks < 2; ks++) {
            uint32_t ah[4][4], al[4][4], bh[4][2], bl[4][2];
            const int arow = wm * 64 + (lane & 15);
            const int ac = ks * 2 + (lane >> 4);
#pragma unroll
            for (int mf = 0; mf < 4; mf++) {
                uint32_t o = tswz(arow + mf * 16, ac);
                ldsm4(ah[mf], bAh + o);
                ldsm4(al[mf], bAl + o);
            }
            // paired B ldsm4: covers nf even/odd per instruction
            const int brow = wn * 32 + ((lane >> 4) & 1) * 8 + (lane & 7);
            const int bc = ks * 2 + ((lane >> 3) & 1);
#pragma unroll
            for (int nfp = 0; nfp < 2; nfp++) {
                uint32_t o = tswz(brow + nfp * 16, bc);
                uint32_t t4[4];
                ldsm4(t4, bBh + o);
                bh[2 * nfp][0] = t4[0]; bh[2 * nfp][1] = t4[1];
                bh[2 * nfp + 1][0] = t4[2]; bh[2 * nfp + 1][1] = t4[3];
                ldsm4(t4, bBl + o);
                bl[2 * nfp][0] = t4[0]; bl[2 * nfp][1] = t4[1];
                bl[2 * nfp + 1][0] = t4[2]; bl[2 * nfp + 1][1] = t4[3];
            }
#pragma unroll
            for (int mf = 0; mf < 4; mf++)
#pragma unroll
                for (int nf = 0; nf < 4; nf++) {
                    mma_f16f32(accF[mf][nf], ah[mf], bh[nf]);   // main, f32 acc
                    mma_f16f16(accC[mf][nf], ah[mf], bl[nf]);   // corr, f16 acc
                    mma_f16f16(accC[mf][nf], al[mf], bh[nf]);   // corr, f16 acc
                }
        }
    }
}

// final value of fragment element k (0..3) for (mf,nf)
__device__ __forceinline__ float f16v(const float* aF, const uint32_t* aC, int k) {
    __half2 c = *(const __half2*)&aC[k >> 1];
    float corr = (k & 1) ? __high2float(c) : __low2float(c);
    return aF[k] + corr;
}

// ===========================================================================
// Kernels
// ===========================================================================

// Merged Q/K/Vd projection (f16 core). z=0:Q z=1:K z=2:VdT (CT, f16)
__global__ void __launch_bounds__(128, 3)
mma_gemm_qkv(const __half* __restrict__ Xh, const __half* __restrict__ Xl,
             const __half* __restrict__ Bqh, const __half* __restrict__ Bql,
             const __half* __restrict__ Bkh, const __half* __restrict__ Bkl,
             const __half* __restrict__ Bvh, const __half* __restrict__ Bvl,
             __half* __restrict__ Qh, __half* __restrict__ Ql,
             __half* __restrict__ Kh, __half* __restrict__ Kl,
             __half* __restrict__ Vh, __half* __restrict__ Vl)
{
    const int m0 = blockIdx.y * 128;
    const int n0 = blockIdx.x * 64;
    const int z = blockIdx.z;

    const __half* Bh = (z == 0) ? Bqh : (z == 1) ? Bkh : Bvh;
    const __half* Bl = (z == 0) ? Bql : (z == 1) ? Bkl : Bvl;

    extern __shared__ char sm[];
    float accF[4][4][4] = {};
    uint32_t accC[4][4][2] = {};
    gemm_core_f16(Xh, Xl, Bh, Bl, m0, n0, EE, EE, EE >> 5, sm, accF, accC);

    const int lane = threadIdx.x & 31;
    const int wid = threadIdx.x >> 5;
    const int wm = wid >> 1, wn = wid & 1;
    const int g = lane >> 2, t2 = (lane & 3) * 2;
#pragma unroll
    for (int mf = 0; mf < 4; mf++)
#pragma unroll
        for (int nf = 0; nf < 4; nf++) {
            const int r0 = m0 + wm * 64 + mf * 16 + g;
            const int c0 = n0 + wn * 32 + nf * 8 + t2;
#pragma unroll
            for (int h = 0; h < 2; h++) {
                const int r = r0 + h * 8;
                float v0 = f16v(accF[mf][nf], accC[mf][nf], h * 2 + 0);
                float v1 = f16v(accF[mf][nf], accC[mf][nf], h * 2 + 1);
                __half h0 = __float2half_rn(v0);
                __half h1 = __float2half_rn(v1);
                __half l0 = __float2half_rn(v0 - __half2float(h0));
                __half l1 = __float2half_rn(v1 - __half2float(h1));
                if (z < 2) {
                    __half* Ch = (z == 0) ? Qh : Kh;
                    __half* Cl = (z == 0) ? Ql : Kl;
                    *(__half2*)(Ch + (size_t)r * DD + c0) = __half2(h0, h1);
                    *(__half2*)(Cl + (size_t)r * DD + c0) = __half2(l0, l1);
                } else {
                    Vh[(size_t)c0 * (BB * NN) + r] = h0;
                    Vh[(size_t)(c0 + 1) * (BB * NN) + r] = h1;
                    Vl[(size_t)c0 * (BB * NN) + r] = l0;
                    Vl[(size_t)(c0 + 1) * (BB * NN) + r] = l1;
                }
            }
        }
}

// S GEMM (f16 core) with fused quirk + exp + row-sum epilogue.
// P written as f16 hi/lo of e*PSCALE (so f16 range holds exp(S)); rowsum unscaled.
__global__ void __launch_bounds__(128, 3)
mma_gemm_sexp(const __half* __restrict__ Qh, const __half* __restrict__ Ql,
              const __half* __restrict__ Kh, const __half* __restrict__ Kl,
              __half* __restrict__ Ph, __half* __restrict__ Pl,
              float* __restrict__ rsum)
{
    const int m0 = blockIdx.y * 128;
    const int n0 = blockIdx.x * 64;
    if (n0 > m0 + 127) return;          // fully masked tile
    const int z = blockIdx.z;

    const __half* Ah = Qh + (size_t)z * NN * DD;
    const __half* Al = Ql + (size_t)z * NN * DD;
    const __half* Bh = Kh + (size_t)z * NN * DD;
    const __half* Bl = Kl + (size_t)z * NN * DD;
    Ph += (size_t)z * NN * NN;
    Pl += (size_t)z * NN * NN;
    rsum += (size_t)z * NN;

    extern __shared__ char sm[];
    float accF[4][4][4] = {};
    uint32_t accC[4][4][2] = {};
    gemm_core_f16(Ah, Al, Bh, Bl, m0, n0, DD, DD, DD >> 5, sm, accF, accC);

    const int lane = threadIdx.x & 31;
    const int wid = threadIdx.x >> 5;
    const int wm = wid >> 1, wn = wid & 1;
    const int g = lane >> 2, t2 = (lane & 3) * 2;
    const float alpha = 1.0f / 16.0f;

#pragma unroll
    for (int mf = 0; mf < 4; mf++) {
#pragma unroll
        for (int h = 0; h < 2; h++) {
            const int row = m0 + wm * 64 + mf * 16 + g + h * 8;
            float rs = 0.0f;
#pragma unroll
            for (int nf = 0; nf < 4; nf++) {
                const int col = n0 + wn * 32 + nf * 8 + t2;
                float s0 = f16v(accF[mf][nf], accC[mf][nf], h * 2 + 0) * alpha;
                float s1 = f16v(accF[mf][nf], accC[mf][nf], h * 2 + 1) * alpha;
                float e0 = (col > row) ? 0.0f
                           : expf((s0 != 0.0f) ? s0 : NEG_FILL);
                float e1 = (col + 1 > row) ? 0.0f
                           : expf((s1 != 0.0f) ? s1 : NEG_FILL);
                rs += e0 + e1;
                float es0 = e0 * PSCALE, es1 = e1 * PSCALE;
                __half h0 = __float2half_rn(es0);
                __half h1 = __float2half_rn(es1);
                __half l0 = __float2half_rn(es0 - __half2float(h0));
                __half l1 = __float2half_rn(es1 - __half2float(h1));
                *(__half2*)(Ph + (size_t)row * NN + col) = __half2(h0, h1);
                *(__half2*)(Pl + (size_t)row * NN + col) = __half2(l0, l1);
            }
            rs += __shfl_xor_sync(0xffffffff, rs, 1);
            rs += __shfl_xor_sync(0xffffffff, rs, 2);
            if ((lane & 3) == 0) atomicAdd(&rsum[row], rs);
        }
    }
}

// T GEMM (f16 core), split-K halves, big-K first. Output f32 partials
// (scaled by PSCALE; combine multiplies back).
__global__ void __launch_bounds__(128, 3)
mma_gemm_tsplit(const __half* __restrict__ Ph, const __half* __restrict__ Pl,
                const __half* __restrict__ Vh, const __half* __restrict__ Vl,
                float* __restrict__ Tp0, float* __restrict__ Tp1)
{
    const int by = gridDim.y - 1 - blockIdx.y;
    const int m0 = by * 128;
    const int n0 = blockIdx.x * 64;
    const int batch = blockIdx.z >> 1;
    const int half = blockIdx.z & 1;

    const int kEnd = m0 + 128;          // causal K limit (multiple of 128)
    const int kh = kEnd >> 1;
    const int ks = half ? kh : 0;
    const int ke = half ? kEnd : kh;

    const __half* Ah = Ph + (size_t)batch * NN * NN + ks;
    const __half* Al = Pl + (size_t)batch * NN * NN + ks;
    const __half* Bh = Vh + (size_t)batch * NN + ks;
    const __half* Bl = Vl + (size_t)batch * NN + ks;
    float* Tp = (half ? Tp1 : Tp0) + (size_t)batch * NN * DD;

    extern __shared__ char sm[];
    float accF[4][4][4] = {};
    uint32_t accC[4][4][2] = {};
    gemm_core_f16(Ah, Al, Bh, Bl, m0, n0, NN, BB * NN, (ke - ks) >> 5, sm, accF, accC);

    const int lane = threadIdx.x & 31;
    const int wid = threadIdx.x >> 5;
    const int wm = wid >> 1, wn = wid & 1;
    const int g = lane >> 2, t2 = (lane & 3) * 2;
#pragma unroll
    for (int mf = 0; mf < 4; mf++)
#pragma unroll
        for (int nf = 0; nf < 4; nf++) {
            const int r0 = m0 + wm * 64 + mf * 16 + g;
            const int c0 = n0 + wn * 32 + nf * 8 + t2;
#pragma unroll
            for (int h = 0; h < 2; h++) {
                const int r = r0 + h * 8;
                *(float2*)(Tp + (size_t)r * DD + c0) = make_float2(
                    f16v(accF[mf][nf], accC[mf][nf], h * 2 + 0),
                    f16v(accF[mf][nf], accC[mf][nf], h * 2 + 1));
            }
        }
}

// Combine T partials, undo PSCALE, normalize, emit f16 hi/lo.
__global__ void __launch_bounds__(256)
combine_T(const float* __restrict__ p0, const float* __restrict__ p1,
          const float* __restrict__ rsum,
          __half* __restrict__ Th, __half* __restrict__ Tl)
{
    int i = blockIdx.x * 256 + threadIdx.x;          // over (BB*NN*DD)/4
    float4 a = ((const float4*)p0)[i];
    float4 b = ((const float4*)p1)[i];
    const float inv = PSCALE_INV / rsum[i >> 6];     // row = (i*4)/DD
    float v0 = (a.x + b.x) * inv, v1 = (a.y + b.y) * inv;
    float v2 = (a.z + b.z) * inv, v3 = (a.w + b.w) * inv;
    __half h0 = __float2half_rn(v0), h1 = __float2half_rn(v1);
    __half h2 = __float2half_rn(v2), h3 = __float2half_rn(v3);
    __half l0 = __float2half_rn(v0 - __half2float(h0));
    __half l1 = __float2half_rn(v1 - __half2float(h1));
    __half l2 = __float2half_rn(v2 - __half2float(h2));
    __half l3 = __float2half_rn(v3 - __half2float(h3));
    ((__half2*)Th)[i * 2 + 0] = __half2(h0, h1);
    ((__half2*)Th)[i * 2 + 1] = __half2(h2, h3);
    ((__half2*)Tl)[i * 2 + 0] = __half2(l0, l1);
    ((__half2*)Tl)[i * 2 + 1] = __half2(l2, l3);
}

// out = T @ Wvu (f16 core), f32 out
__global__ void __launch_bounds__(128, 3)
mma_gemm_out(const __half* __restrict__ Ah, const __half* __restrict__ Al,
             const __half* __restrict__ Bh, const __half* __restrict__ Bl,
             float* __restrict__ Cf)
{
    const int m0 = blockIdx.y * 128;
    const int n0 = blockIdx.x * 64;
    extern __shared__ char sm[];
    float accF[4][4][4] = {};
    uint32_t accC[4][4][2] = {};
    gemm_core_f16(Ah, Al, Bh, Bl, m0, n0, DD, DD, DD >> 5, sm, accF, accC);

    const int lane = threadIdx.x & 31;
    const int wid = threadIdx.x >> 5;
    const int wm = wid >> 1, wn = wid & 1;
    const int g = lane >> 2, t2 = (lane & 3) * 2;
#pragma unroll
    for (int mf = 0; mf < 4; mf++)
#pragma unroll
        for (int nf = 0; nf < 4; nf++) {
            const int r0 = m0 + wm * 64 + mf * 16 + g;
            const int c0 = n0 + wn * 32 + nf * 8 + t2;
#pragma unroll
            for (int h = 0; h < 2; h++) {
                const int r = r0 + h * 8;
                *(float2*)(Cf + (size_t)r * EE + c0) = make_float2(
                    f16v(accF[mf][nf], accC[mf][nf], h * 2 + 0),
                    f16v(accF[mf][nf], accC[mf][nf], h * 2 + 1));
            }
        }
}

// Merged prep kernel: X f16 split + 4 weight transpose/f16-splits + rsum zero.
__global__ void __launch_bounds__(256)
prep_all(const float* __restrict__ X,
         const float* __restrict__ Wq, const float* __restrict__ Wk,
         const float* __restrict__ Wvd, const float* __restrict__ Wvu,
         __half* __restrict__ Xh, __half* __restrict__ Xl,
         __half* __restrict__ WqTh, __half* __restrict__ WqTl,
         __half* __restrict__ WkTh, __half* __restrict__ WkTl,
         __half* __restrict__ WvdTh, __half* __restrict__ WvdTl,
         __half* __restrict__ WvuTh, __half* __restrict__ WvuTl,
         float* __restrict__ rsum)
{
    const int b = blockIdx.x;
    const int tid = threadIdx.x;

    if (b < 16384) {                       // ---- X split
        int i = b * 256 + tid;
        float4 v = ((const float4*)X)[i];
        __half h0 = __float2half_rn(v.x), h1 = __float2half_rn(v.y);
        __half h2 = __float2half_rn(v.z), h3 = __float2half_rn(v.w);
        __half l0 = __float2half_rn(v.x - __half2float(h0));
        __half l1 = __float2half_rn(v.y - __half2float(h1));
        __half l2 = __float2half_rn(v.z - __half2float(h2));
        __half l3 = __float2half_rn(v.w - __half2float(h3));
        ((__half2*)Xh)[i * 2 + 0] = __half2(h0, h1);
        ((__half2*)Xh)[i * 2 + 1] = __half2(h2, h3);
        ((__half2*)Xl)[i * 2 + 0] = __half2(l0, l1);
        ((__half2*)Xl)[i * 2 + 1] = __half2(l2, l3);
        return;
    }
    if (b < 16384 + 1024) {                // ---- weight transpose + f16 split
        const int t = b - 16384;
        const int w = t >> 8;
        const int s = t & 255;
        const float* src; __half *dh, *dl;
        int M, N, gx, gy;
        if (w < 3) {                       // [EE, DD] -> [DD, EE]
            M = EE; N = DD; gx = s & 7; gy = s >> 3;
            src = (w == 0) ? Wq : (w == 1) ? Wk : Wvd;
            dh = (w == 0) ? WqTh : (w == 1) ? WkTh : WvdTh;
            dl = (w == 0) ? WqTl : (w == 1) ? WkTl : WvdTl;
        } else {                           // [DD, EE] -> [EE, DD]
            M = DD; N = EE; gx = s & 31; gy = s >> 5;
            src = Wvu; dh = WvuTh; dl = WvuTl;
        }
        __shared__ float tb[32][33];
        const int bx = gx * 32, by = gy * 32;
        const int x = tid & 31, y = tid >> 5;
#pragma unroll
        for (int i = 0; i < 32; i += 8)
            tb[y + i][x] = src[(size_t)(by + y + i) * N + bx + x];
        __syncthreads();
#pragma unroll
        for (int i = 0; i < 32; i += 8) {
            float v = tb[x][y + i];
            __half h = __float2half_rn(v);
            dh[(size_t)(bx + y + i) * M + by + x] = h;
            dl[(size_t)(bx + y + i) * M + by + x] =
                __float2half_rn(v - __half2float(h));
        }
        return;
    }
    {                                      // ---- zero rsum
        const int t = b - (16384 + 1024);
        int i = t * 256 + tid;
        ((float4*)rsum)[i] = make_float4(0.f, 0.f, 0.f, 0.f);
    }
}

// ---------------------------------------------------------------------------
extern "C" void kernel_launch(void* const* d_in, const int* in_sizes, int n_in,
                              void* d_out, int out_size)
{
    (void)in_sizes; (void)n_in; (void)out_size;
    const float* X   = (const float*)d_in[0];
    const float* Wq  = (const float*)d_in[1];
    const float* Wk  = (const float*)d_in[2];
    const float* Wvd = (const float*)d_in[3];
    const float* Wvu = (const float*)d_in[4];
    float* out = (float*)d_out;

    __half *pXh, *pXl, *pQh, *pQl, *pKh, *pKl, *pTh, *pTl, *pVdTh, *pVdTl, *pPh, *pPl;
    __half *pWqTh, *pWqTl, *pWkTh, *pWkTl, *pWvdTh, *pWvdTl, *pWvuTh, *pWvuTl;
    float *pTp0, *pTp1, *pRs;
    cudaGetSymbolAddress((void**)&pXh, g_Xh);     cudaGetSymbolAddress((void**)&pXl, g_Xl);
    cudaGetSymbolAddress((void**)&pQh, g_Qh);     cudaGetSymbolAddress((void**)&pQl, g_Ql);
    cudaGetSymbolAddress((void**)&pKh, g_Kh);     cudaGetSymbolAddress((void**)&pKl, g_Kl);
    cudaGetSymbolAddress((void**)&pVdTh, g_VdTh); cudaGetSymbolAddress((void**)&pVdTl, g_VdTl);
    cudaGetSymbolAddress((void**)&pTh, g_Th);     cudaGetSymbolAddress((void**)&pTl, g_Tl);
    cudaGetSymbolAddress((void**)&pTp0, g_Tp0);   cudaGetSymbolAddress((void**)&pTp1, g_Tp1);
    cudaGetSymbolAddress((void**)&pRs, g_rsum);
    cudaGetSymbolAddress((void**)&pWqTh, g_WqTh); cudaGetSymbolAddress((void**)&pWqTl, g_WqTl);
    cudaGetSymbolAddress((void**)&pWkTh, g_WkTh); cudaGetSymbolAddress((void**)&pWkTl, g_WkTl);
    cudaGetSymbolAddress((void**)&pWvdTh, g_WvdTh); cudaGetSymbolAddress((void**)&pWvdTl, g_WvdTl);
    cudaGetSymbolAddress((void**)&pWvuTh, g_WvuTh); cudaGetSymbolAddress((void**)&pWvuTl, g_WvuTl);
    cudaGetSymbolAddress((void**)&pPh, g_Ph);     cudaGetSymbolAddress((void**)&pPl, g_Pl);

    cudaFuncSetAttribute(mma_gemm_qkv,
                         cudaFuncAttributeMaxDynamicSharedMemorySize, F16_SMEM);
    cudaFuncSetAttribute(mma_gemm_sexp,
                         cudaFuncAttributeMaxDynamicSharedMemorySize, F16_SMEM);
    cudaFuncSetAttribute(mma_gemm_tsplit,
                         cudaFuncAttributeMaxDynamicSharedMemorySize, F16_SMEM);
    cudaFuncSetAttribute(mma_gemm_out,
                         cudaFuncAttributeMaxDynamicSharedMemorySize, F16_SMEM);

    const dim3 blk(128);
    const dim3 pblk(256);

    // 0) merged prep
    prep_all<<<16384 + 1024 + 16, pblk>>>(
        X, Wq, Wk, Wvd, Wvu, pXh, pXl,
        pWqTh, pWqTl, pWkTh, pWkTl, pWvdTh, pWvdTl, pWvuTh, pWvuTl, pRs);

    // 1) merged Q/K/VdT projection (f16 core, 128x64 tiles)
    mma_gemm_qkv<<<dim3(4, 128, 3), blk, F16_SMEM>>>(
        pXh, pXl, pWqTh, pWqTl, pWkTh, pWkTl, pWvdTh, pWvdTl,
        pQh, pQl, pKh, pKl, pVdTh, pVdTl);

    // 2) S = Q@K^T/16 with fused quirk+exp+rowsum epilogue (f16 core)
    mma_gemm_sexp<<<dim3(64, 32, BB), blk, F16_SMEM>>>(
        pQh, pQl, pKh, pKl, pPh, pPl, pRs);

    // 3) T partials = P' @ Vd (f16 core), split-K halves, big-K first
    mma_gemm_tsplit<<<dim3(4, 32, BB * 2), blk, F16_SMEM>>>(
        pPh, pPl, pVdTh, pVdTl, pTp0, pTp1);

    // 4) combine + undo PSCALE + normalize -> Th/Tl (f16)
    combine_T<<<(BB * NN * DD / 4) / 256, pblk>>>(pTp0, pTp1, pRs, pTh, pTl);

    // 5) out = T @ Wvu (f16 core)
    mma_gemm_out<<<dim3(16, 128, 1), blk, F16_SMEM>>>(
        pTh, pTl, pWvuTh, pWvuTl, out);
}

// round 15
// speedup vs baseline: 8.2667x; 1.2156x over previous
#include <cuda_runtime.h>
#include <cuda_bf16.h>
#include <cuda_fp16.h>
#include <math.h>
#include <stdint.h>

// Problem shape (fixed)
#define BB 4
#define NN 4096
#define EE 1024
#define DD 256
#define NEG_FILL (-3.402823466385288598e+38f)
#define PSCALE     0.0009765625f     // 2^-10: P stored scaled so f16 holds exp(S)
#define PSCALE_INV 1024.0f

// ---------------- scratch (static device globals; no allocs) ----------------
__device__ __half g_Xh  [(size_t)BB * NN * EE];
__device__ __half g_Xl  [(size_t)BB * NN * EE];
__device__ __half g_Qh  [(size_t)BB * NN * DD];
__device__ __half g_Ql  [(size_t)BB * NN * DD];
__device__ __half g_Kh  [(size_t)BB * NN * DD];
__device__ __half g_Kl  [(size_t)BB * NN * DD];
__device__ __half g_VdTh[(size_t)DD * BB * NN];  // (X@Wvd)^T  [256, B*N]
__device__ __half g_Th  [(size_t)BB * NN * DD];  // T = softmax(S)@Vd
__device__ __half g_Tl  [(size_t)BB * NN * DD];
__device__ float  g_Tp0 [(size_t)BB * NN * DD];  // T split-K partials (f32)
__device__ float  g_Tp1 [(size_t)BB * NN * DD];
__device__ float  g_rsum[(size_t)BB * NN];       // unnormalized row sums
__device__ __half g_WqTh[(size_t)DD * EE];
__device__ __half g_WqTl[(size_t)DD * EE];
__device__ __half g_WkTh[(size_t)DD * EE];
__device__ __half g_WkTl[(size_t)DD * EE];
__device__ __half g_WvdTh[(size_t)DD * EE];
__device__ __half g_WvdTl[(size_t)DD * EE];
__device__ __half g_WvuTh[(size_t)EE * DD];
__device__ __half g_WvuTl[(size_t)EE * DD];
__device__ __half g_Ph  [(size_t)BB * NN * NN];  // exp(S) * PSCALE (f16, hi only)

// ---------------- helpers ----------------
__device__ __forceinline__ uint32_t smem_u32(const void* p) {
    uint32_t a;
    asm("{ .reg .u64 t; cvta.to.shared.u64 t, %1; cvt.u32.u64 %0, t; }"
        : "=r"(a) : "l"(p));
    return a;
}
__device__ __forceinline__ void ldsm4(uint32_t* r, uint32_t a) {
    asm volatile("ldmatrix.sync.aligned.m8n8.x4.shared.b16 {%0,%1,%2,%3}, [%4];"
                 : "=r"(r[0]), "=r"(r[1]), "=r"(r[2]), "=r"(r[3]) : "r"(a));
}
// f16 x f16 -> f32 accum (main term)
__device__ __forceinline__ void mma_f16f32(float* d, const uint32_t* a, const uint32_t* b) {
    asm volatile(
        "mma.sync.aligned.m16n8k16.row.col.f32.f16.f16.f32 "
        "{%0,%1,%2,%3}, {%4,%5,%6,%7}, {%8,%9}, {%0,%1,%2,%3};"
        : "+f"(d[0]), "+f"(d[1]), "+f"(d[2]), "+f"(d[3])
        : "r"(a[0]), "r"(a[1]), "r"(a[2]), "r"(a[3]), "r"(b[0]), "r"(b[1]));
}
// f16 x f16 -> f16 accum (correction terms)
__device__ __forceinline__ void mma_f16f16(uint32_t* d, const uint32_t* a, const uint32_t* b) {
    asm volatile(
        "mma.sync.aligned.m16n8k16.row.col.f16.f16.f16.f16 "
        "{%0,%1}, {%2,%3,%4,%5}, {%6,%7}, {%0,%1};"
        : "+r"(d[0]), "+r"(d[1])
        : "r"(a[0]), "r"(a[1]), "r"(a[2]), "r"(a[3]), "r"(b[0]), "r"(b[1]));
}
__device__ __forceinline__ void cp16(uint32_t saddr, const void* gaddr) {
    asm volatile("cp.async.cg.shared.global [%0], [%1], 16;"
                 :: "r"(saddr), "l"(gaddr) : "memory");
}
#define CP_COMMIT() asm volatile("cp.async.commit_group;" ::: "memory")
#define CP_WAIT1()  asm volatile("cp.async.wait_group 1;" ::: "memory")

// swizzled offset within a Nx32-elem 16-bit tile (rows of 64B, 4x16B chunks)
__device__ __forceinline__ uint32_t tswz(int row, int chunk) {
    return (uint32_t)(row * 64 + ((chunk ^ ((row >> 1) & 3)) << 4));
}

// ===========================================================================
// f16 split-3 GEMM core: CTA tile 128x64, 4 warps (2x2) of 64x32, K-slab 32.
// Main term -> f32 accum; corrections (hi*lo + lo*hi) -> shared f16 accum.
// ===========================================================================
#define F16_AT   8192                 // A tile 128x64B
#define F16_BT   4096                 // B tile 64x64B
#define F16_STAGE (2 * F16_AT + 2 * F16_BT)   // 24576
#define F16_SMEM (3 * F16_STAGE)              // 73728

__device__ __forceinline__ void gemm_core_f16(
    const __half* __restrict__ Ah, const __half* __restrict__ Al,
    const __half* __restrict__ Bh, const __half* __restrict__ Bl,
    int m0, int n0, int ldA, int ldB, int numIt, char* sm,
    float accF[4][4][4], uint32_t accC[4][4][2])
{
    const int tid = threadIdx.x;
    const int lane = tid & 31;
    const int wid = tid >> 5;
    const int wm = wid >> 1;        // 0..1
    const int wn = wid & 1;         // 0..1

    auto issue = [&](int stage, int it) {
        char* st = sm + stage * F16_STAGE;
        const int k0 = it << 5;
#pragma unroll
        for (int j = 0; j < 6; j++) {
            int idx = tid + j * 128;            // 0..767
            int row = idx >> 2, c = idx & 3;
            if (row < 128) {                    // A rows
                uint32_t off = tswz(row, c);
                uint32_t s0 = smem_u32(st) + off;
                cp16(s0,           Ah + (size_t)(m0 + row) * ldA + k0 + c * 8);
                cp16(s0 + F16_AT,  Al + (size_t)(m0 + row) * ldA + k0 + c * 8);
            } else {                            // B rows
                int r2 = row - 128;
                uint32_t off = tswz(r2, c);
                uint32_t s0 = smem_u32(st) + 2 * F16_AT + off;
                cp16(s0,           Bh + (size_t)(n0 + r2) * ldB + k0 + c * 8);
                cp16(s0 + F16_BT,  Bl + (size_t)(n0 + r2) * ldB + k0 + c * 8);
            }
        }
    };

    issue(0, 0); CP_COMMIT();
    if (numIt > 1) issue(1, 1);
    CP_COMMIT();

    for (int it = 0; it < numIt; ++it) {
        CP_WAIT1();
        __syncthreads();
        if (it + 2 < numIt) issue((it + 2) % 3, it + 2);
        CP_COMMIT();

        char* st = sm + (it % 3) * F16_STAGE;
        const uint32_t bAh = smem_u32(st);
        const uint32_t bAl = bAh + F16_AT;
        const uint32_t bBh = bAh + 2 * F16_AT;
        const uint32_t bBl = bBh + F16_BT;

#pragma unroll
        for (int ks = 0; ks < 2; ks++) {
            uint32_t ah[4][4], al[4][4], bh[4][2], bl[4][2];
            const int arow = wm * 64 + (lane & 15);
            const int ac = ks * 2 + (lane >> 4);
#pragma unroll
            for (int mf = 0; mf < 4; mf++) {
                uint32_t o = tswz(arow + mf * 16, ac);
                ldsm4(ah[mf], bAh + o);
                ldsm4(al[mf], bAl + o);
            }
            const int brow = wn * 32 + ((lane >> 4) & 1) * 8 + (lane & 7);
            const int bc = ks * 2 + ((lane >> 3) & 1);
#pragma unroll
            for (int nfp = 0; nfp < 2; nfp++) {
                uint32_t o = tswz(brow + nfp * 16, bc);
                uint32_t t4[4];
                ldsm4(t4, bBh + o);
                bh[2 * nfp][0] = t4[0]; bh[2 * nfp][1] = t4[1];
                bh[2 * nfp + 1][0] = t4[2]; bh[2 * nfp + 1][1] = t4[3];
                ldsm4(t4, bBl + o);
                bl[2 * nfp][0] = t4[0]; bl[2 * nfp][1] = t4[1];
                bl[2 * nfp + 1][0] = t4[2]; bl[2 * nfp + 1][1] = t4[3];
            }
#pragma unroll
            for (int mf = 0; mf < 4; mf++)
#pragma unroll
                for (int nf = 0; nf < 4; nf++) {
                    mma_f16f32(accF[mf][nf], ah[mf], bh[nf]);   // main, f32 acc
                    mma_f16f16(accC[mf][nf], ah[mf], bl[nf]);   // corr, f16 acc
                    mma_f16f16(accC[mf][nf], al[mf], bh[nf]);   // corr, f16 acc
                }
        }
    }
}

// final value of fragment element k (0..3) for (mf,nf)
__device__ __forceinline__ float f16v(const float* aF, const uint32_t* aC, int k) {
    __half2 c = *(const __half2*)&aC[k >> 1];
    float corr = (k & 1) ? __high2float(c) : __low2float(c);
    return aF[k] + corr;
}

// ===========================================================================
// f16 single-term GEMM core (value path): CTA 128x64, 4 warps, 1 MMA/fragment.
// Half the smem/loads of split-3; regs ~110 -> occupancy 4.
// ===========================================================================
#define T1_AT    8192
#define T1_BT    4096
#define T1_STAGE (T1_AT + T1_BT)     // 12288
#define T1_SMEM  (3 * T1_STAGE)      // 36864

__device__ __forceinline__ void gemm_core_f16_1(
    const __half* __restrict__ Ah, const __half* __restrict__ Bh,
    int m0, int n0, int ldA, int ldB, int numIt, char* sm,
    float accF[4][4][4])
{
    const int tid = threadIdx.x;
    const int lane = tid & 31;
    const int wid = tid >> 5;
    const int wm = wid >> 1;
    const int wn = wid & 1;

    auto issue = [&](int stage, int it) {
        char* st = sm + stage * T1_STAGE;
        const int k0 = it << 5;
#pragma unroll
        for (int j = 0; j < 6; j++) {
            int idx = tid + j * 128;            // 0..767
            int row = idx >> 2, c = idx & 3;
            if (row < 128) {                    // A rows
                uint32_t off = tswz(row, c);
                cp16(smem_u32(st) + off,
                     Ah + (size_t)(m0 + row) * ldA + k0 + c * 8);
            } else {                            // B rows
                int r2 = row - 128;
                uint32_t off = tswz(r2, c);
                cp16(smem_u32(st) + T1_AT + off,
                     Bh + (size_t)(n0 + r2) * ldB + k0 + c * 8);
            }
        }
    };

    issue(0, 0); CP_COMMIT();
    if (numIt > 1) issue(1, 1);
    CP_COMMIT();

    for (int it = 0; it < numIt; ++it) {
        CP_WAIT1();
        __syncthreads();
        if (it + 2 < numIt) issue((it + 2) % 3, it + 2);
        CP_COMMIT();

        char* st = sm + (it % 3) * T1_STAGE;
        const uint32_t bAh = smem_u32(st);
        const uint32_t bBh = bAh + T1_AT;

#pragma unroll
        for (int ks = 0; ks < 2; ks++) {
            uint32_t ah[4][4], bh[4][2];
            const int arow = wm * 64 + (lane & 15);
            const int ac = ks * 2 + (lane >> 4);
#pragma unroll
            for (int mf = 0; mf < 4; mf++)
                ldsm4(ah[mf], bAh + tswz(arow + mf * 16, ac));
            const int brow = wn * 32 + ((lane >> 4) & 1) * 8 + (lane & 7);
            const int bc = ks * 2 + ((lane >> 3) & 1);
#pragma unroll
            for (int nfp = 0; nfp < 2; nfp++) {
                uint32_t t4[4];
                ldsm4(t4, bBh + tswz(brow + nfp * 16, bc));
                bh[2 * nfp][0] = t4[0]; bh[2 * nfp][1] = t4[1];
                bh[2 * nfp + 1][0] = t4[2]; bh[2 * nfp + 1][1] = t4[3];
            }
#pragma unroll
            for (int mf = 0; mf < 4; mf++)
#pragma unroll
                for (int nf = 0; nf < 4; nf++)
                    mma_f16f32(accF[mf][nf], ah[mf], bh[nf]);
        }
    }
}

// ===========================================================================
// Kernels
// ===========================================================================

// Merged Q/K/Vd projection (split-3 core). z=0:Q z=1:K z=2:VdT (CT, hi only)
__global__ void __launch_bounds__(128, 3)
mma_gemm_qkv(const __half* __restrict__ Xh, const __half* __restrict__ Xl,
             const __half* __restrict__ Bqh, const __half* __restrict__ Bql,
             const __half* __restrict__ Bkh, const __half* __restrict__ Bkl,
             const __half* __restrict__ Bvh, const __half* __restrict__ Bvl,
             __half* __restrict__ Qh, __half* __restrict__ Ql,
             __half* __restrict__ Kh, __half* __restrict__ Kl,
             __half* __restrict__ Vh)
{
    const int m0 = blockIdx.y * 128;
    const int n0 = blockIdx.x * 64;
    const int z = blockIdx.z;

    const __half* Bh = (z == 0) ? Bqh : (z == 1) ? Bkh : Bvh;
    const __half* Bl = (z == 0) ? Bql : (z == 1) ? Bkl : Bvl;

    extern __shared__ char sm[];
    float accF[4][4][4] = {};
    uint32_t accC[4][4][2] = {};
    gemm_core_f16(Xh, Xl, Bh, Bl, m0, n0, EE, EE, EE >> 5, sm, accF, accC);

    const int lane = threadIdx.x & 31;
    const int wid = threadIdx.x >> 5;
    const int wm = wid >> 1, wn = wid & 1;
    const int g = lane >> 2, t2 = (lane & 3) * 2;
#pragma unroll
    for (int mf = 0; mf < 4; mf++)
#pragma unroll
        for (int nf = 0; nf < 4; nf++) {
            const int r0 = m0 + wm * 64 + mf * 16 + g;
            const int c0 = n0 + wn * 32 + nf * 8 + t2;
#pragma unroll
            for (int h = 0; h < 2; h++) {
                const int r = r0 + h * 8;
                float v0 = f16v(accF[mf][nf], accC[mf][nf], h * 2 + 0);
                float v1 = f16v(accF[mf][nf], accC[mf][nf], h * 2 + 1);
                __half h0 = __float2half_rn(v0);
                __half h1 = __float2half_rn(v1);
                if (z < 2) {
                    __half* Ch = (z == 0) ? Qh : Kh;
                    __half* Cl = (z == 0) ? Ql : Kl;
                    __half l0 = __float2half_rn(v0 - __half2float(h0));
                    __half l1 = __float2half_rn(v1 - __half2float(h1));
                    *(__half2*)(Ch + (size_t)r * DD + c0) = __half2(h0, h1);
                    *(__half2*)(Cl + (size_t)r * DD + c0) = __half2(l0, l1);
                } else {
                    Vh[(size_t)c0 * (BB * NN) + r] = h0;
                    Vh[(size_t)(c0 + 1) * (BB * NN) + r] = h1;
                }
            }
        }
}

// S GEMM (split-3 core) with fused quirk + exp + row-sum epilogue.
// P written as f16 of e*PSCALE (hi only); rowsum unscaled f32.
__global__ void __launch_bounds__(128, 3)
mma_gemm_sexp(const __half* __restrict__ Qh, const __half* __restrict__ Ql,
              const __half* __restrict__ Kh, const __half* __restrict__ Kl,
              __half* __restrict__ Ph, float* __restrict__ rsum)
{
    const int m0 = blockIdx.y * 128;
    const int n0 = blockIdx.x * 64;
    if (n0 > m0 + 127) return;          // fully masked tile
    const int z = blockIdx.z;

    const __half* Ah = Qh + (size_t)z * NN * DD;
    const __half* Al = Ql + (size_t)z * NN * DD;
    const __half* Bh = Kh + (size_t)z * NN * DD;
    const __half* Bl = Kl + (size_t)z * NN * DD;
    Ph += (size_t)z * NN * NN;
    rsum += (size_t)z * NN;

    extern __shared__ char sm[];
    float accF[4][4][4] = {};
    uint32_t accC[4][4][2] = {};
    gemm_core_f16(Ah, Al, Bh, Bl, m0, n0, DD, DD, DD >> 5, sm, accF, accC);

    const int lane = threadIdx.x & 31;
    const int wid = threadIdx.x >> 5;
    const int wm = wid >> 1, wn = wid & 1;
    const int g = lane >> 2, t2 = (lane & 3) * 2;
    const float alpha = 1.0f / 16.0f;

#pragma unroll
    for (int mf = 0; mf < 4; mf++) {
#pragma unroll
        for (int h = 0; h < 2; h++) {
            const int row = m0 + wm * 64 + mf * 16 + g + h * 8;
            float rs = 0.0f;
#pragma unroll
            for (int nf = 0; nf < 4; nf++) {
                const int col = n0 + wn * 32 + nf * 8 + t2;
                float s0 = f16v(accF[mf][nf], accC[mf][nf], h * 2 + 0) * alpha;
                float s1 = f16v(accF[mf][nf], accC[mf][nf], h * 2 + 1) * alpha;
                float e0 = (col > row) ? 0.0f
                           : expf((s0 != 0.0f) ? s0 : NEG_FILL);
                float e1 = (col + 1 > row) ? 0.0f
                           : expf((s1 != 0.0f) ? s1 : NEG_FILL);
                rs += e0 + e1;
                __half h0 = __float2half_rn(e0 * PSCALE);
                __half h1 = __float2half_rn(e1 * PSCALE);
                *(__half2*)(Ph + (size_t)row * NN + col) = __half2(h0, h1);
            }
            rs += __shfl_xor_sync(0xffffffff, rs, 1);
            rs += __shfl_xor_sync(0xffffffff, rs, 2);
            if ((lane & 3) == 0) atomicAdd(&rsum[row], rs);
        }
    }
}

// T GEMM (single-term f16 core), split-K halves, big-K first.
// f32 partials (scaled by PSCALE; combine undoes it).
__global__ void __launch_bounds__(128, 4)
mma_gemm_tsplit(const __half* __restrict__ Ph, const __half* __restrict__ Vh,
                float* __restrict__ Tp0, float* __restrict__ Tp1)
{
    const int by = gridDim.y - 1 - blockIdx.y;
    const int m0 = by * 128;
    const int n0 = blockIdx.x * 64;
    const int batch = blockIdx.z >> 1;
    const int half = blockIdx.z & 1;

    const int kEnd = m0 + 128;          // causal K limit (multiple of 128)
    const int kh = kEnd >> 1;
    const int ks = half ? kh : 0;
    const int ke = half ? kEnd : kh;

    const __half* Ah = Ph + (size_t)batch * NN * NN + ks;
    const __half* Bh = Vh + (size_t)batch * NN + ks;
    float* Tp = (half ? Tp1 : Tp0) + (size_t)batch * NN * DD;

    extern __shared__ char sm[];
    float accF[4][4][4] = {};
    gemm_core_f16_1(Ah, Bh, m0, n0, NN, BB * NN, (ke - ks) >> 5, sm, accF);

    const int lane = threadIdx.x & 31;
    const int wid = threadIdx.x >> 5;
    const int wm = wid >> 1, wn = wid & 1;
    const int g = lane >> 2, t2 = (lane & 3) * 2;
#pragma unroll
    for (int mf = 0; mf < 4; mf++)
#pragma unroll
        for (int nf = 0; nf < 4; nf++) {
            const int r0 = m0 + wm * 64 + mf * 16 + g;
            const int c0 = n0 + wn * 32 + nf * 8 + t2;
#pragma unroll
            for (int h = 0; h < 2; h++) {
                const int r = r0 + h * 8;
                *(float2*)(Tp + (size_t)r * DD + c0) =
                    make_float2(accF[mf][nf][h * 2 + 0], accF[mf][nf][h * 2 + 1]);
            }
        }
}

// Combine T partials, undo PSCALE, normalize, emit f16 hi/lo.
__global__ void __launch_bounds__(256)
combine_T(const float* __restrict__ p0, const float* __restrict__ p1,
          const float* __restrict__ rsum,
          __half* __restrict__ Th, __half* __restrict__ Tl)
{
    int i = blockIdx.x * 256 + threadIdx.x;          // over (BB*NN*DD)/4
    float4 a = ((const float4*)p0)[i];
    float4 b = ((const float4*)p1)[i];
    const float inv = PSCALE_INV / rsum[i >> 6];     // row = (i*4)/DD
    float v0 = (a.x + b.x) * inv, v1 = (a.y + b.y) * inv;
    float v2 = (a.z + b.z) * inv, v3 = (a.w + b.w) * inv;
    __half h0 = __float2half_rn(v0), h1 = __float2half_rn(v1);
    __half h2 = __float2half_rn(v2), h3 = __float2half_rn(v3);
    __half l0 = __float2half_rn(v0 - __half2float(h0));
    __half l1 = __float2half_rn(v1 - __half2float(h1));
    __half l2 = __float2half_rn(v2 - __half2float(h2));
    __half l3 = __float2half_rn(v3 - __half2float(h3));
    ((__half2*)Th)[i * 2 + 0] = __half2(h0, h1);
    ((__half2*)Th)[i * 2 + 1] = __half2(h2, h3);
    ((__half2*)Tl)[i * 2 + 0] = __half2(l0, l1);
    ((__half2*)Tl)[i * 2 + 1] = __half2(l2, l3);
}

// out = T @ Wvu (split-3 core), f32 out
__global__ void __launch_bounds__(128, 3)
mma_gemm_out(const __half* __restrict__ Ah, const __half* __restrict__ Al,
             const __half* __restrict__ Bh, const __half* __restrict__ Bl,
             float* __restrict__ Cf)
{
    const int m0 = blockIdx.y * 128;
    const int n0 = blockIdx.x * 64;
    extern __shared__ char sm[];
    float accF[4][4][4] = {};
    uint32_t accC[4][4][2] = {};
    gemm_core_f16(Ah, Al, Bh, Bl, m0, n0, DD, DD, DD >> 5, sm, accF, accC);

    const int lane = threadIdx.x & 31;
    const int wid = threadIdx.x >> 5;
    const int wm = wid >> 1, wn = wid & 1;
    const int g = lane >> 2, t2 = (lane & 3) * 2;
#pragma unroll
    for (int mf = 0; mf < 4; mf++)
#pragma unroll
        for (int nf = 0; nf < 4; nf++) {
            const int r0 = m0 + wm * 64 + mf * 16 + g;
            const int c0 = n0 + wn * 32 + nf * 8 + t2;
#pragma unroll
            for (int h = 0; h < 2; h++) {
                const int r = r0 + h * 8;
                *(float2*)(Cf + (size_t)r * EE + c0) = make_float2(
                    f16v(accF[mf][nf], accC[mf][nf], h * 2 + 0),
                    f16v(accF[mf][nf], accC[mf][nf], h * 2 + 1));
            }
        }
}

// Merged prep kernel: X f16 split + 4 weight transpose/f16-splits + rsum zero.
__global__ void __launch_bounds__(256)
prep_all(const float* __restrict__ X,
         const float* __restrict__ Wq, const float* __restrict__ Wk,
         const float* __restrict__ Wvd, const float* __restrict__ Wvu,
         __half* __restrict__ Xh, __half* __restrict__ Xl,
         __half* __restrict__ WqTh, __half* __restrict__ WqTl,
         __half* __restrict__ WkTh, __half* __restrict__ WkTl,
         __half* __restrict__ WvdTh, __half* __restrict__ WvdTl,
         __half* __restrict__ WvuTh, __half* __restrict__ WvuTl,
         float* __restrict__ rsum)
{
    const int b = blockIdx.x;
    const int tid = threadIdx.x;

    if (b < 16384) {                       // ---- X split
        int i = b * 256 + tid;
        float4 v = ((const float4*)X)[i];
        __half h0 = __float2half_rn(v.x), h1 = __float2half_rn(v.y);
        __half h2 = __float2half_rn(v.z), h3 = __float2half_rn(v.w);
        __half l0 = __float2half_rn(v.x - __half2float(h0));
        __half l1 = __float2half_rn(v.y - __half2float(h1));
        __half l2 = __float2half_rn(v.z - __half2float(h2));
        __half l3 = __float2half_rn(v.w - __half2float(h3));
        ((__half2*)Xh)[i * 2 + 0] = __half2(h0, h1);
        ((__half2*)Xh)[i * 2 + 1] = __half2(h2, h3);
        ((__half2*)Xl)[i * 2 + 0] = __half2(l0, l1);
        ((__half2*)Xl)[i * 2 + 1] = __half2(l2, l3);
        return;
    }
    if (b < 16384 + 1024) {                // ---- weight transpose + f16 split
        const int t = b - 16384;
        const int w = t >> 8;
        const int s = t & 255;
        const float* src; __half *dh, *dl;
        int M, N, gx, gy;
        if (w < 3) {                       // [EE, DD] -> [DD, EE]
            M = EE; N = DD; gx = s & 7; gy = s >> 3;
            src = (w == 0) ? Wq : (w == 1) ? Wk : Wvd;
            dh = (w == 0) ? WqTh : (w == 1) ? WkTh : WvdTh;
            dl = (w == 0) ? WqTl : (w == 1) ? WkTl : WvdTl;
        } else {                           // [DD, EE] -> [EE, DD]
            M = DD; N = EE; gx = s & 31; gy = s >> 5;
            src = Wvu; dh = WvuTh; dl = WvuTl;
        }
        __shared__ float tb[32][33];
        const int bx = gx * 32, by = gy * 32;
        const int x = tid & 31, y = tid >> 5;
#pragma unroll
        for (int i = 0; i < 32; i += 8)
            tb[y + i][x] = src[(size_t)(by + y + i) * N + bx + x];
        __syncthreads();
#pragma unroll
        for (int i = 0; i < 32; i += 8) {
            float v = tb[x][y + i];
            __half h = __float2half_rn(v);
            dh[(size_t)(bx + y + i) * M + by + x] = h;
            dl[(size_t)(bx + y + i) * M + by + x] =
                __float2half_rn(v - __half2float(h));
        }
        return;
    }
    {                                      // ---- zero rsum
        const int t = b - (16384 + 1024);
        int i = t * 256 + tid;
        ((float4*)rsum)[i] = make_float4(0.f, 0.f, 0.f, 0.f);
    }
}

// ---------------------------------------------------------------------------
extern "C" void kernel_launch(void* const* d_in, const int* in_sizes, int n_in,
                              void* d_out, int out_size)
{
    (void)in_sizes; (void)n_in; (void)out_size;
    const float* X   = (const float*)d_in[0];
    const float* Wq  = (const float*)d_in[1];
    const float* Wk  = (const float*)d_in[2];
    const float* Wvd = (const float*)d_in[3];
    const float* Wvu = (const float*)d_in[4];
    float* out = (float*)d_out;

    __half *pXh, *pXl, *pQh, *pQl, *pKh, *pKl, *pTh, *pTl, *pVdTh, *pPh;
    __half *pWqTh, *pWqTl, *pWkTh, *pWkTl, *pWvdTh, *pWvdTl, *pWvuTh, *pWvuTl;
    float *pTp0, *pTp1, *pRs;
    cudaGetSymbolAddress((void**)&pXh, g_Xh);     cudaGetSymbolAddress((void**)&pXl, g_Xl);
    cudaGetSymbolAddress((void**)&pQh, g_Qh);     cudaGetSymbolAddress((void**)&pQl, g_Ql);
    cudaGetSymbolAddress((void**)&pKh, g_Kh);     cudaGetSymbolAddress((void**)&pKl, g_Kl);
    cudaGetSymbolAddress((void**)&pVdTh, g_VdTh);
    cudaGetSymbolAddress((void**)&pTh, g_Th);     cudaGetSymbolAddress((void**)&pTl, g_Tl);
    cudaGetSymbolAddress((void**)&pTp0, g_Tp0);   cudaGetSymbolAddress((void**)&pTp1, g_Tp1);
    cudaGetSymbolAddress((void**)&pRs, g_rsum);
    cudaGetSymbolAddress((void**)&pWqTh, g_WqTh); cudaGetSymbolAddress((void**)&pWqTl, g_WqTl);
    cudaGetSymbolAddress((void**)&pWkTh, g_WkTh); cudaGetSymbolAddress((void**)&pWkTl, g_WkTl);
    cudaGetSymbolAddress((void**)&pWvdTh, g_WvdTh); cudaGetSymbolAddress((void**)&pWvdTl, g_WvdTl);
    cudaGetSymbolAddress((void**)&pWvuTh, g_WvuTh); cudaGetSymbolAddress((void**)&pWvuTl, g_WvuTl);
    cudaGetSymbolAddress((void**)&pPh, g_Ph);

    cudaFuncSetAttribute(mma_gemm_qkv,
                         cudaFuncAttributeMaxDynamicSharedMemorySize, F16_SMEM);
    cudaFuncSetAttribute(mma_gemm_sexp,
                         cudaFuncAttributeMaxDynamicSharedMemorySize, F16_SMEM);
    cudaFuncSetAttribute(mma_gemm_tsplit,
                         cudaFuncAttributeMaxDynamicSharedMemorySize, T1_SMEM);
    cudaFuncSetAttribute(mma_gemm_out,
                         cudaFuncAttributeMaxDynamicSharedMemorySize, F16_SMEM);

    const dim3 blk(128);
    const dim3 pblk(256);

    // 0) merged prep
    prep_all<<<16384 + 1024 + 16, pblk>>>(
        X, Wq, Wk, Wvd, Wvu, pXh, pXl,
        pWqTh, pWqTl, pWkTh, pWkTl, pWvdTh, pWvdTl, pWvuTh, pWvuTl, pRs);

    // 1) merged Q/K/VdT projection (split-3 core, 128x64 tiles)
    mma_gemm_qkv<<<dim3(4, 128, 3), blk, F16_SMEM>>>(
        pXh, pXl, pWqTh, pWqTl, pWkTh, pWkTl, pWvdTh, pWvdTl,
        pQh, pQl, pKh, pKl, pVdTh);

    // 2) S = Q@K^T/16 with fused quirk+exp+rowsum epilogue (split-3 core)
    mma_gemm_sexp<<<dim3(64, 32, BB), blk, F16_SMEM>>>(
        pQh, pQl, pKh, pKl, pPh, pRs);

    // 3) T partials = P' @ Vd (single-term core), split-K halves, big-K first
    mma_gemm_tsplit<<<dim3(4, 32, BB * 2), blk, T1_SMEM>>>(
        pPh, pVdTh, pTp0, pTp1);

    // 4) combine + undo PSCALE + normalize -> Th/Tl (f16)
    combine_T<<<(BB * NN * DD / 4) / 256, pblk>>>(pTp0, pTp1, pRs, pTh, pTl);

    // 5) out = T @ Wvu (split-3 core)
    mma_gemm_out<<<dim3(16, 128, 1), blk, F16_SMEM>>>(
        pTh, pTl, pWvuTh, pWvuTl, out);
}

// round 16
// speedup vs baseline: 8.8041x; 1.0650x over previous
#include <cuda_runtime.h>
#include <cuda_bf16.h>
#include <cuda_fp16.h>
#include <math.h>
#include <stdint.h>

// Problem shape (fixed)
#define BB 4
#define NN 4096
#define EE 1024
#define DD 256
#define NEG_FILL (-3.402823466385288598e+38f)
#define PSCALE     0.0009765625f     // 2^-10: P stored scaled so f16 holds exp(S)
#define PSCALE_INV 1024.0f

// ---------------- scratch (static device globals; no allocs) ----------------
__device__ __half g_Xh  [(size_t)BB * NN * EE];
__device__ __half g_Xl  [(size_t)BB * NN * EE];
__device__ __half g_Qh  [(size_t)BB * NN * DD];
__device__ __half g_Ql  [(size_t)BB * NN * DD];
__device__ __half g_Kh  [(size_t)BB * NN * DD];
__device__ __half g_Kl  [(size_t)BB * NN * DD];
__device__ __half g_VdTh[(size_t)DD * BB * NN];  // (X@Wvd)^T  [256, B*N]
__device__ __half g_Th  [(size_t)BB * NN * DD];  // T = softmax(S)@Vd
__device__ __half g_Tl  [(size_t)BB * NN * DD];
__device__ float  g_Tp0 [(size_t)BB * NN * DD];  // T split-K partials (f32)
__device__ float  g_Tp1 [(size_t)BB * NN * DD];
__device__ float  g_rsum[(size_t)BB * NN];       // unnormalized row sums
__device__ __half g_WqTh[(size_t)DD * EE];
__device__ __half g_WqTl[(size_t)DD * EE];
__device__ __half g_WkTh[(size_t)DD * EE];
__device__ __half g_WkTl[(size_t)DD * EE];
__device__ __half g_WvdTh[(size_t)DD * EE];
__device__ __half g_WvdTl[(size_t)DD * EE];
__device__ __half g_WvuTh[(size_t)EE * DD];
__device__ __half g_WvuTl[(size_t)EE * DD];
__device__ __half g_Ph  [(size_t)BB * NN * NN];  // exp(S) * PSCALE (f16, hi only)

// ---------------- helpers ----------------
__device__ __forceinline__ uint32_t smem_u32(const void* p) {
    uint32_t a;
    asm("{ .reg .u64 t; cvta.to.shared.u64 t, %1; cvt.u32.u64 %0, t; }"
        : "=r"(a) : "l"(p));
    return a;
}
__device__ __forceinline__ void ldsm4(uint32_t* r, uint32_t a) {
    asm volatile("ldmatrix.sync.aligned.m8n8.x4.shared.b16 {%0,%1,%2,%3}, [%4];"
                 : "=r"(r[0]), "=r"(r[1]), "=r"(r[2]), "=r"(r[3]) : "r"(a));
}
// f16 x f16 -> f32 accum (main term)
__device__ __forceinline__ void mma_f16f32(float* d, const uint32_t* a, const uint32_t* b) {
    asm volatile(
        "mma.sync.aligned.m16n8k16.row.col.f32.f16.f16.f32 "
        "{%0,%1,%2,%3}, {%4,%5,%6,%7}, {%8,%9}, {%0,%1,%2,%3};"
        : "+f"(d[0]), "+f"(d[1]), "+f"(d[2]), "+f"(d[3])
        : "r"(a[0]), "r"(a[1]), "r"(a[2]), "r"(a[3]), "r"(b[0]), "r"(b[1]));
}
// f16 x f16 -> f16 accum (correction terms)
__device__ __forceinline__ void mma_f16f16(uint32_t* d, const uint32_t* a, const uint32_t* b) {
    asm volatile(
        "mma.sync.aligned.m16n8k16.row.col.f16.f16.f16.f16 "
        "{%0,%1}, {%2,%3,%4,%5}, {%6,%7}, {%0,%1};"
        : "+r"(d[0]), "+r"(d[1])
        : "r"(a[0]), "r"(a[1]), "r"(a[2]), "r"(a[3]), "r"(b[0]), "r"(b[1]));
}
__device__ __forceinline__ void cp16(uint32_t saddr, const void* gaddr) {
    asm volatile("cp.async.cg.shared.global [%0], [%1], 16;"
                 :: "r"(saddr), "l"(gaddr) : "memory");
}
#define CP_COMMIT() asm volatile("cp.async.commit_group;" ::: "memory")
#define CP_WAIT1()  asm volatile("cp.async.wait_group 1;" ::: "memory")

// swizzled offset within a Nx32-elem 16-bit tile (rows of 64B, 4x16B chunks)
__device__ __forceinline__ uint32_t tswz(int row, int chunk) {
    return (uint32_t)(row * 64 + ((chunk ^ ((row >> 1) & 3)) << 4));
}

// ===========================================================================
// f16 split-3 GEMM core: CTA tile 128x64, 4 warps (2x2) of 64x32, K-slab 32.
// Main term -> f32 accum; corrections (hi*lo + lo*hi) -> shared f16 accum.
// ===========================================================================
#define F16_AT   8192                 // A tile 128x64B
#define F16_BT   4096                 // B tile 64x64B
#define F16_STAGE (2 * F16_AT + 2 * F16_BT)   // 24576
#define F16_SMEM (3 * F16_STAGE)              // 73728

__device__ __forceinline__ void gemm_core_f16(
    const __half* __restrict__ Ah, const __half* __restrict__ Al,
    const __half* __restrict__ Bh, const __half* __restrict__ Bl,
    int m0, int n0, int ldA, int ldB, int numIt, char* sm,
    float accF[4][4][4], uint32_t accC[4][4][2])
{
    const int tid = threadIdx.x;
    const int lane = tid & 31;
    const int wid = tid >> 5;
    const int wm = wid >> 1;        // 0..1
    const int wn = wid & 1;         // 0..1

    auto issue = [&](int stage, int it) {
        char* st = sm + stage * F16_STAGE;
        const int k0 = it << 5;
#pragma unroll
        for (int j = 0; j < 6; j++) {
            int idx = tid + j * 128;            // 0..767
            int row = idx >> 2, c = idx & 3;
            if (row < 128) {                    // A rows
                uint32_t off = tswz(row, c);
                uint32_t s0 = smem_u32(st) + off;
                cp16(s0,           Ah + (size_t)(m0 + row) * ldA + k0 + c * 8);
                cp16(s0 + F16_AT,  Al + (size_t)(m0 + row) * ldA + k0 + c * 8);
            } else {                            // B rows
                int r2 = row - 128;
                uint32_t off = tswz(r2, c);
                uint32_t s0 = smem_u32(st) + 2 * F16_AT + off;
                cp16(s0,           Bh + (size_t)(n0 + r2) * ldB + k0 + c * 8);
                cp16(s0 + F16_BT,  Bl + (size_t)(n0 + r2) * ldB + k0 + c * 8);
            }
        }
    };

    issue(0, 0); CP_COMMIT();
    if (numIt > 1) issue(1, 1);
    CP_COMMIT();

    for (int it = 0; it < numIt; ++it) {
        CP_WAIT1();
        __syncthreads();
        if (it + 2 < numIt) issue((it + 2) % 3, it + 2);
        CP_COMMIT();

        char* st = sm + (it % 3) * F16_STAGE;
        const uint32_t bAh = smem_u32(st);
        const uint32_t bAl = bAh + F16_AT;
        const uint32_t bBh = bAh + 2 * F16_AT;
        const uint32_t bBl = bBh + F16_BT;

#pragma unroll
        for (int ks = 0; ks < 2; ks++) {
            uint32_t ah[4][4], al[4][4], bh[4][2], bl[4][2];
            const int arow = wm * 64 + (lane & 15);
            const int ac = ks * 2 + (lane >> 4);
#pragma unroll
            for (int mf = 0; mf < 4; mf++) {
                uint32_t o = tswz(arow + mf * 16, ac);
                ldsm4(ah[mf], bAh + o);
                ldsm4(al[mf], bAl + o);
            }
            const int brow = wn * 32 + ((lane >> 4) & 1) * 8 + (lane & 7);
            const int bc = ks * 2 + ((lane >> 3) & 1);
#pragma unroll
            for (int nfp = 0; nfp < 2; nfp++) {
                uint32_t o = tswz(brow + nfp * 16, bc);
                uint32_t t4[4];
                ldsm4(t4, bBh + o);
                bh[2 * nfp][0] = t4[0]; bh[2 * nfp][1] = t4[1];
                bh[2 * nfp + 1][0] = t4[2]; bh[2 * nfp + 1][1] = t4[3];
                ldsm4(t4, bBl + o);
                bl[2 * nfp][0] = t4[0]; bl[2 * nfp][1] = t4[1];
                bl[2 * nfp + 1][0] = t4[2]; bl[2 * nfp + 1][1] = t4[3];
            }
#pragma unroll
            for (int mf = 0; mf < 4; mf++)
#pragma unroll
                for (int nf = 0; nf < 4; nf++) {
                    mma_f16f32(accF[mf][nf], ah[mf], bh[nf]);   // main, f32 acc
                    mma_f16f16(accC[mf][nf], ah[mf], bl[nf]);   // corr, f16 acc
                    mma_f16f16(accC[mf][nf], al[mf], bh[nf]);   // corr, f16 acc
                }
        }
    }
}

// final value of fragment element k (0..3) for (mf,nf)
__device__ __forceinline__ float f16v(const float* aF, const uint32_t* aC, int k) {
    __half2 c = *(const __half2*)&aC[k >> 1];
    float corr = (k & 1) ? __high2float(c) : __low2float(c);
    return aF[k] + corr;
}

// ===========================================================================
// f16 single-term GEMM core: CTA 128x64, 4 warps, 1 MMA/fragment, occ 4.
// ===========================================================================
#define T1_AT    8192
#define T1_BT    4096
#define T1_STAGE (T1_AT + T1_BT)     // 12288
#define T1_SMEM  (3 * T1_STAGE)      // 36864

__device__ __forceinline__ void gemm_core_f16_1(
    const __half* __restrict__ Ah, const __half* __restrict__ Bh,
    int m0, int n0, int ldA, int ldB, int numIt, char* sm,
    float accF[4][4][4])
{
    const int tid = threadIdx.x;
    const int lane = tid & 31;
    const int wid = tid >> 5;
    const int wm = wid >> 1;
    const int wn = wid & 1;

    auto issue = [&](int stage, int it) {
        char* st = sm + stage * T1_STAGE;
        const int k0 = it << 5;
#pragma unroll
        for (int j = 0; j < 6; j++) {
            int idx = tid + j * 128;            // 0..767
            int row = idx >> 2, c = idx & 3;
            if (row < 128) {                    // A rows
                uint32_t off = tswz(row, c);
                cp16(smem_u32(st) + off,
                     Ah + (size_t)(m0 + row) * ldA + k0 + c * 8);
            } else {                            // B rows
                int r2 = row - 128;
                uint32_t off = tswz(r2, c);
                cp16(smem_u32(st) + T1_AT + off,
                     Bh + (size_t)(n0 + r2) * ldB + k0 + c * 8);
            }
        }
    };

    issue(0, 0); CP_COMMIT();
    if (numIt > 1) issue(1, 1);
    CP_COMMIT();

    for (int it = 0; it < numIt; ++it) {
        CP_WAIT1();
        __syncthreads();
        if (it + 2 < numIt) issue((it + 2) % 3, it + 2);
        CP_COMMIT();

        char* st = sm + (it % 3) * T1_STAGE;
        const uint32_t bAh = smem_u32(st);
        const uint32_t bBh = bAh + T1_AT;

#pragma unroll
        for (int ks = 0; ks < 2; ks++) {
            uint32_t ah[4][4], bh[4][2];
            const int arow = wm * 64 + (lane & 15);
            const int ac = ks * 2 + (lane >> 4);
#pragma unroll
            for (int mf = 0; mf < 4; mf++)
                ldsm4(ah[mf], bAh + tswz(arow + mf * 16, ac));
            const int brow = wn * 32 + ((lane >> 4) & 1) * 8 + (lane & 7);
            const int bc = ks * 2 + ((lane >> 3) & 1);
#pragma unroll
            for (int nfp = 0; nfp < 2; nfp++) {
                uint32_t t4[4];
                ldsm4(t4, bBh + tswz(brow + nfp * 16, bc));
                bh[2 * nfp][0] = t4[0]; bh[2 * nfp][1] = t4[1];
                bh[2 * nfp + 1][0] = t4[2]; bh[2 * nfp + 1][1] = t4[3];
            }
#pragma unroll
            for (int mf = 0; mf < 4; mf++)
#pragma unroll
                for (int nf = 0; nf < 4; nf++)
                    mma_f16f32(accF[mf][nf], ah[mf], bh[nf]);
        }
    }
}

// ===========================================================================
// Kernels
// ===========================================================================

// Merged Q/K projection (split-3 core). z=0:Q z=1:K (both f16 hi/lo out)
__global__ void __launch_bounds__(128, 3)
mma_gemm_qk(const __half* __restrict__ Xh, const __half* __restrict__ Xl,
            const __half* __restrict__ Bqh, const __half* __restrict__ Bql,
            const __half* __restrict__ Bkh, const __half* __restrict__ Bkl,
            __half* __restrict__ Qh, __half* __restrict__ Ql,
            __half* __restrict__ Kh, __half* __restrict__ Kl)
{
    const int m0 = blockIdx.y * 128;
    const int n0 = blockIdx.x * 64;
    const int z = blockIdx.z;

    const __half* Bh = (z == 0) ? Bqh : Bkh;
    const __half* Bl = (z == 0) ? Bql : Bkl;

    extern __shared__ char sm[];
    float accF[4][4][4] = {};
    uint32_t accC[4][4][2] = {};
    gemm_core_f16(Xh, Xl, Bh, Bl, m0, n0, EE, EE, EE >> 5, sm, accF, accC);

    const int lane = threadIdx.x & 31;
    const int wid = threadIdx.x >> 5;
    const int wm = wid >> 1, wn = wid & 1;
    const int g = lane >> 2, t2 = (lane & 3) * 2;
    __half* Ch = (z == 0) ? Qh : Kh;
    __half* Cl = (z == 0) ? Ql : Kl;
#pragma unroll
    for (int mf = 0; mf < 4; mf++)
#pragma unroll
        for (int nf = 0; nf < 4; nf++) {
            const int r0 = m0 + wm * 64 + mf * 16 + g;
            const int c0 = n0 + wn * 32 + nf * 8 + t2;
#pragma unroll
            for (int h = 0; h < 2; h++) {
                const int r = r0 + h * 8;
                float v0 = f16v(accF[mf][nf], accC[mf][nf], h * 2 + 0);
                float v1 = f16v(accF[mf][nf], accC[mf][nf], h * 2 + 1);
                __half h0 = __float2half_rn(v0);
                __half h1 = __float2half_rn(v1);
                __half l0 = __float2half_rn(v0 - __half2float(h0));
                __half l1 = __float2half_rn(v1 - __half2float(h1));
                *(__half2*)(Ch + (size_t)r * DD + c0) = __half2(h0, h1);
                *(__half2*)(Cl + (size_t)r * DD + c0) = __half2(l0, l1);
            }
        }
}

// Vd projection (single-term core): VdT = (Xh @ Wvdh)^T, f16 hi-only out.
// Corrections are pointless here: the output is rounded to a single f16
// anyway, so GEMM error (2^-11 incoh.) is masked by output quantization.
__global__ void __launch_bounds__(128, 4)
mma_gemm_vd(const __half* __restrict__ Xh, const __half* __restrict__ Bvh,
            __half* __restrict__ Vh)
{
    const int m0 = blockIdx.y * 128;
    const int n0 = blockIdx.x * 64;

    extern __shared__ char sm[];
    float accF[4][4][4] = {};
    gemm_core_f16_1(Xh, Bvh, m0, n0, EE, EE, EE >> 5, sm, accF);

    const int lane = threadIdx.x & 31;
    const int wid = threadIdx.x >> 5;
    const int wm = wid >> 1, wn = wid & 1;
    const int g = lane >> 2, t2 = (lane & 3) * 2;
#pragma unroll
    for (int mf = 0; mf < 4; mf++)
#pragma unroll
        for (int nf = 0; nf < 4; nf++) {
            const int r0 = m0 + wm * 64 + mf * 16 + g;
            const int c0 = n0 + wn * 32 + nf * 8 + t2;
#pragma unroll
            for (int h = 0; h < 2; h++) {
                const int r = r0 + h * 8;
                Vh[(size_t)c0 * (BB * NN) + r] =
                    __float2half_rn(accF[mf][nf][h * 2 + 0]);
                Vh[(size_t)(c0 + 1) * (BB * NN) + r] =
                    __float2half_rn(accF[mf][nf][h * 2 + 1]);
            }
        }
}

// S GEMM (split-3 core) with fused quirk + exp + row-sum epilogue.
// P written as f16 of e*PSCALE (hi only); rowsum unscaled f32.
__global__ void __launch_bounds__(128, 3)
mma_gemm_sexp(const __half* __restrict__ Qh, const __half* __restrict__ Ql,
              const __half* __restrict__ Kh, const __half* __restrict__ Kl,
              __half* __restrict__ Ph, float* __restrict__ rsum)
{
    const int m0 = blockIdx.y * 128;
    const int n0 = blockIdx.x * 64;
    if (n0 > m0 + 127) return;          // fully masked tile
    const int z = blockIdx.z;

    const __half* Ah = Qh + (size_t)z * NN * DD;
    const __half* Al = Ql + (size_t)z * NN * DD;
    const __half* Bh = Kh + (size_t)z * NN * DD;
    const __half* Bl = Kl + (size_t)z * NN * DD;
    Ph += (size_t)z * NN * NN;
    rsum += (size_t)z * NN;

    extern __shared__ char sm[];
    float accF[4][4][4] = {};
    uint32_t accC[4][4][2] = {};
    gemm_core_f16(Ah, Al, Bh, Bl, m0, n0, DD, DD, DD >> 5, sm, accF, accC);

    const int lane = threadIdx.x & 31;
    const int wid = threadIdx.x >> 5;
    const int wm = wid >> 1, wn = wid & 1;
    const int g = lane >> 2, t2 = (lane & 3) * 2;
    const float alpha = 1.0f / 16.0f;

#pragma unroll
    for (int mf = 0; mf < 4; mf++) {
#pragma unroll
        for (int h = 0; h < 2; h++) {
            const int row = m0 + wm * 64 + mf * 16 + g + h * 8;
            float rs = 0.0f;
#pragma unroll
            for (int nf = 0; nf < 4; nf++) {
                const int col = n0 + wn * 32 + nf * 8 + t2;
                float s0 = f16v(accF[mf][nf], accC[mf][nf], h * 2 + 0) * alpha;
                float s1 = f16v(accF[mf][nf], accC[mf][nf], h * 2 + 1) * alpha;
                float e0 = (col > row) ? 0.0f
                           : expf((s0 != 0.0f) ? s0 : NEG_FILL);
                float e1 = (col + 1 > row) ? 0.0f
                           : expf((s1 != 0.0f) ? s1 : NEG_FILL);
                rs += e0 + e1;
                __half h0 = __float2half_rn(e0 * PSCALE);
                __half h1 = __float2half_rn(e1 * PSCALE);
                *(__half2*)(Ph + (size_t)row * NN + col) = __half2(h0, h1);
            }
            rs += __shfl_xor_sync(0xffffffff, rs, 1);
            rs += __shfl_xor_sync(0xffffffff, rs, 2);
            if ((lane & 3) == 0) atomicAdd(&rsum[row], rs);
        }
    }
}

// T GEMM (single-term core), split-K halves, big-K first.
// f32 partials (scaled by PSCALE; combine undoes it).
__global__ void __launch_bounds__(128, 4)
mma_gemm_tsplit(const __half* __restrict__ Ph, const __half* __restrict__ Vh,
                float* __restrict__ Tp0, float* __restrict__ Tp1)
{
    const int by = gridDim.y - 1 - blockIdx.y;
    const int m0 = by * 128;
    const int n0 = blockIdx.x * 64;
    const int batch = blockIdx.z >> 1;
    const int half = blockIdx.z & 1;

    const int kEnd = m0 + 128;          // causal K limit (multiple of 128)
    const int kh = kEnd >> 1;
    const int ks = half ? kh : 0;
    const int ke = half ? kEnd : kh;

    const __half* Ah = Ph + (size_t)batch * NN * NN + ks;
    const __half* Bh = Vh + (size_t)batch * NN + ks;
    float* Tp = (half ? Tp1 : Tp0) + (size_t)batch * NN * DD;

    extern __shared__ char sm[];
    float accF[4][4][4] = {};
    gemm_core_f16_1(Ah, Bh, m0, n0, NN, BB * NN, (ke - ks) >> 5, sm, accF);

    const int lane = threadIdx.x & 31;
    const int wid = threadIdx.x >> 5;
    const int wm = wid >> 1, wn = wid & 1;
    const int g = lane >> 2, t2 = (lane & 3) * 2;
#pragma unroll
    for (int mf = 0; mf < 4; mf++)
#pragma unroll
        for (int nf = 0; nf < 4; nf++) {
            const int r0 = m0 + wm * 64 + mf * 16 + g;
            const int c0 = n0 + wn * 32 + nf * 8 + t2;
#pragma unroll
            for (int h = 0; h < 2; h++) {
                const int r = r0 + h * 8;
                *(float2*)(Tp + (size_t)r * DD + c0) =
                    make_float2(accF[mf][nf][h * 2 + 0], accF[mf][nf][h * 2 + 1]);
            }
        }
}

// Combine T partials, undo PSCALE, normalize, emit f16 hi/lo.
__global__ void __launch_bounds__(256)
combine_T(const float* __restrict__ p0, const float* __restrict__ p1,
          const float* __restrict__ rsum,
          __half* __restrict__ Th, __half* __restrict__ Tl)
{
    int i = blockIdx.x * 256 + threadIdx.x;          // over (BB*NN*DD)/4
    float4 a = ((const float4*)p0)[i];
    float4 b = ((const float4*)p1)[i];
    const float inv = PSCALE_INV / rsum[i >> 6];     // row = (i*4)/DD
    float v0 = (a.x + b.x) * inv, v1 = (a.y + b.y) * inv;
    float v2 = (a.z + b.z) * inv, v3 = (a.w + b.w) * inv;
    __half h0 = __float2half_rn(v0), h1 = __float2half_rn(v1);
    __half h2 = __float2half_rn(v2), h3 = __float2half_rn(v3);
    __half l0 = __float2half_rn(v0 - __half2float(h0));
    __half l1 = __float2half_rn(v1 - __half2float(h1));
    __half l2 = __float2half_rn(v2 - __half2float(h2));
    __half l3 = __float2half_rn(v3 - __half2float(h3));
    ((__half2*)Th)[i * 2 + 0] = __half2(h0, h1);
    ((__half2*)Th)[i * 2 + 1] = __half2(h2, h3);
    ((__half2*)Tl)[i * 2 + 0] = __half2(l0, l1);
    ((__half2*)Tl)[i * 2 + 1] = __half2(l2, l3);
}

// out = T @ Wvu (split-3 core), f32 out
__global__ void __launch_bounds__(128, 3)
mma_gemm_out(const __half* __restrict__ Ah, const __half* __restrict__ Al,
             const __half* __restrict__ Bh, const __half* __restrict__ Bl,
             float* __restrict__ Cf)
{
    const int m0 = blockIdx.y * 128;
    const int n0 = blockIdx.x * 64;
    extern __shared__ char sm[];
    float accF[4][4][4] = {};
    uint32_t accC[4][4][2] = {};
    gemm_core_f16(Ah, Al, Bh, Bl, m0, n0, DD, DD, DD >> 5, sm, accF, accC);

    const int lane = threadIdx.x & 31;
    const int wid = threadIdx.x >> 5;
    const int wm = wid >> 1, wn = wid & 1;
    const int g = lane >> 2, t2 = (lane & 3) * 2;
#pragma unroll
    for (int mf = 0; mf < 4; mf++)
#pragma unroll
        for (int nf = 0; nf < 4; nf++) {
            const int r0 = m0 + wm * 64 + mf * 16 + g;
            const int c0 = n0 + wn * 32 + nf * 8 + t2;
#pragma unroll
            for (int h = 0; h < 2; h++) {
                const int r = r0 + h * 8;
                *(float2*)(Cf + (size_t)r * EE + c0) = make_float2(
                    f16v(accF[mf][nf], accC[mf][nf], h * 2 + 0),
                    f16v(accF[mf][nf], accC[mf][nf], h * 2 + 1));
            }
        }
}

// Merged prep kernel: X f16 split + 4 weight transpose/f16-splits + rsum zero.
__global__ void __launch_bounds__(256)
prep_all(const float* __restrict__ X,
         const float* __restrict__ Wq, const float* __restrict__ Wk,
         const float* __restrict__ Wvd, const float* __restrict__ Wvu,
         __half* __restrict__ Xh, __half* __restrict__ Xl,
         __half* __restrict__ WqTh, __half* __restrict__ WqTl,
         __half* __restrict__ WkTh, __half* __restrict__ WkTl,
         __half* __restrict__ WvdTh, __half* __restrict__ WvdTl,
         __half* __restrict__ WvuTh, __half* __restrict__ WvuTl,
         float* __restrict__ rsum)
{
    const int b = blockIdx.x;
    const int tid = threadIdx.x;

    if (b < 16384) {                       // ---- X split
        int i = b * 256 + tid;
        float4 v = ((const float4*)X)[i];
        __half h0 = __float2half_rn(v.x), h1 = __float2half_rn(v.y);
        __half h2 = __float2half_rn(v.z), h3 = __float2half_rn(v.w);
        __half l0 = __float2half_rn(v.x - __half2float(h0));
        __half l1 = __float2half_rn(v.y - __half2float(h1));
        __half l2 = __float2half_rn(v.z - __half2float(h2));
        __half l3 = __float2half_rn(v.w - __half2float(h3));
        ((__half2*)Xh)[i * 2 + 0] = __half2(h0, h1);
        ((__half2*)Xh)[i * 2 + 1] = __half2(h2, h3);
        ((__half2*)Xl)[i * 2 + 0] = __half2(l0, l1);
        ((__half2*)Xl)[i * 2 + 1] = __half2(l2, l3);
        return;
    }
    if (b < 16384 + 1024) {                // ---- weight transpose + f16 split
        const int t = b - 16384;
        const int w = t >> 8;
        const int s = t & 255;
        const float* src; __half *dh, *dl;
        int M, N, gx, gy;
        if (w < 3) {                       // [EE, DD] -> [DD, EE]
            M = EE; N = DD; gx = s & 7; gy = s >> 3;
            src = (w == 0) ? Wq : (w == 1) ? Wk : Wvd;
            dh = (w == 0) ? WqTh : (w == 1) ? WkTh : WvdTh;
            dl = (w == 0) ? WqTl : (w == 1) ? WkTl : WvdTl;
        } else {                           // [DD, EE] -> [EE, DD]
            M = DD; N = EE; gx = s & 31; gy = s >> 5;
            src = Wvu; dh = WvuTh; dl = WvuTl;
        }
        __shared__ float tb[32][33];
        const int bx = gx * 32, by = gy * 32;
        const int x = tid & 31, y = tid >> 5;
#pragma unroll
        for (int i = 0; i < 32; i += 8)
            tb[y + i][x] = src[(size_t)(by + y + i) * N + bx + x];
        __syncthreads();
#pragma unroll
        for (int i = 0; i < 32; i += 8) {
            float v = tb[x][y + i];
            __half h = __float2half_rn(v);
            dh[(size_t)(bx + y + i) * M + by + x] = h;
            dl[(size_t)(bx + y + i) * M + by + x] =
                __float2half_rn(v - __half2float(h));
        }
        return;
    }
    {                                      // ---- zero rsum
        const int t = b - (16384 + 1024);
        int i = t * 256 + tid;
        ((float4*)rsum)[i] = make_float4(0.f, 0.f, 0.f, 0.f);
    }
}

// ---------------------------------------------------------------------------
extern "C" void kernel_launch(void* const* d_in, const int* in_sizes, int n_in,
                              void* d_out, int out_size)
{
    (void)in_sizes; (void)n_in; (void)out_size;
    const float* X   = (const float*)d_in[0];
    const float* Wq  = (const float*)d_in[1];
    const float* Wk  = (const float*)d_in[2];
    const float* Wvd = (const float*)d_in[3];
    const float* Wvu = (const float*)d_in[4];
    float* out = (float*)d_out;

    __half *pXh, *pXl, *pQh, *pQl, *pKh, *pKl, *pTh, *pTl, *pVdTh, *pPh;
    __half *pWqTh, *pWqTl, *pWkTh, *pWkTl, *pWvdTh, *pWvdTl, *pWvuTh, *pWvuTl;
    float *pTp0, *pTp1, *pRs;
    cudaGetSymbolAddress((void**)&pXh, g_Xh);     cudaGetSymbolAddress((void**)&pXl, g_Xl);
    cudaGetSymbolAddress((void**)&pQh, g_Qh);     cudaGetSymbolAddress((void**)&pQl, g_Ql);
    cudaGetSymbolAddress((void**)&pKh, g_Kh);     cudaGetSymbolAddress((void**)&pKl, g_Kl);
    cudaGetSymbolAddress((void**)&pVdTh, g_VdTh);
    cudaGetSymbolAddress((void**)&pTh, g_Th);     cudaGetSymbolAddress((void**)&pTl, g_Tl);
    cudaGetSymbolAddress((void**)&pTp0, g_Tp0);   cudaGetSymbolAddress((void**)&pTp1, g_Tp1);
    cudaGetSymbolAddress((void**)&pRs, g_rsum);
    cudaGetSymbolAddress((void**)&pWqTh, g_WqTh); cudaGetSymbolAddress((void**)&pWqTl, g_WqTl);
    cudaGetSymbolAddress((void**)&pWkTh, g_WkTh); cudaGetSymbolAddress((void**)&pWkTl, g_WkTl);
    cudaGetSymbolAddress((void**)&pWvdTh, g_WvdTh); cudaGetSymbolAddress((void**)&pWvdTl, g_WvdTl);
    cudaGetSymbolAddress((void**)&pWvuTh, g_WvuTh); cudaGetSymbolAddress((void**)&pWvuTl, g_WvuTl);
    cudaGetSymbolAddress((void**)&pPh, g_Ph);

    cudaFuncSetAttribute(mma_gemm_qk,
                         cudaFuncAttributeMaxDynamicSharedMemorySize, F16_SMEM);
    cudaFuncSetAttribute(mma_gemm_vd,
                         cudaFuncAttributeMaxDynamicSharedMemorySize, T1_SMEM);
    cudaFuncSetAttribute(mma_gemm_sexp,
                         cudaFuncAttributeMaxDynamicSharedMemorySize, F16_SMEM);
    cudaFuncSetAttribute(mma_gemm_tsplit,
                         cudaFuncAttributeMaxDynamicSharedMemorySize, T1_SMEM);
    cudaFuncSetAttribute(mma_gemm_out,
                         cudaFuncAttributeMaxDynamicSharedMemorySize, F16_SMEM);

    const dim3 blk(128);
    const dim3 pblk(256);

    // 0) merged prep
    prep_all<<<16384 + 1024 + 16, pblk>>>(
        X, Wq, Wk, Wvd, Wvu, pXh, pXl,
        pWqTh, pWqTl, pWkTh, pWkTl, pWvdTh, pWvdTl, pWvuTh, pWvuTl, pRs);

    // 1a) Q/K projection (split-3 core)
    mma_gemm_qk<<<dim3(4, 128, 2), blk, F16_SMEM>>>(
        pXh, pXl, pWqTh, pWqTl, pWkTh, pWkTl, pQh, pQl, pKh, pKl);

    // 1b) VdT projection (single-term core; output rounded to f16 anyway)
    mma_gemm_vd<<<dim3(4, 128), blk, T1_SMEM>>>(pXh, pWvdTh, pVdTh);

    // 2) S = Q@K^T/16 with fused quirk+exp+rowsum epilogue (split-3 core)
    mma_gemm_sexp<<<dim3(64, 32, BB), blk, F16_SMEM>>>(
        pQh, pQl, pKh, pKl, pPh, pRs);

    // 3) T partials = P' @ Vd (single-term core), split-K halves, big-K first
    mma_gemm_tsplit<<<dim3(4, 32, BB * 2), blk, T1_SMEM>>>(
        pPh, pVdTh, pTp0, pTp1);

    // 4) combine + undo PSCALE + normalize -> Th/Tl (f16)
    combine_T<<<(BB * NN * DD / 4) / 256, pblk>>>(pTp0, pTp1, pRs, pTh, pTl);

    // 5) out = T @ Wvu (split-3 core)
    mma_gemm_out<<<dim3(16, 128, 1), blk, F16_SMEM>>>(
        pTh, pTl, pWvuTh, pWvuTl, out);
}